// round 8
// baseline (speedup 1.0000x reference)
#include <cuda_runtime.h>

#define NN 50000
#define NE 800000

typedef unsigned int u32;
typedef unsigned long long u64;

// ---------------------------------------------------------------------------
// Device scratch (no cudaMalloc allowed)
// ---------------------------------------------------------------------------
__device__ float g_agg[(size_t)NN * 128];
// Pre-split bf16 weights, transposed to [n][k], row stride 272B,
// per 128-K chunk: [hi 34816 B][lo 34816 B] = 69632 B.
#define WCHUNK 69632
__device__ __align__(16) unsigned char g_we[5 * WCHUNK]; // edge: L1 x3, L2, L3
__device__ __align__(16) unsigned char g_wn[4 * WCHUNK]; // node: L1 x2, L2, L3

// ---------------------------------------------------------------------------
// SMEM: A_hi, A_lo (128 rows each), B double buffer (2 x (hi+lo)).
// ---------------------------------------------------------------------------
#define ROWB 272
#define BTILE 34816              // 128 * 272
#define SM_AHI 0
#define SM_ALO BTILE             // 34816
#define SM_B0  (2 * BTILE)       // 69632
#define SM_B1  (4 * BTILE)       // 139264
#define SM_BYTES (6 * BTILE)     // 208896

#define MROWS 128
#define NTHREADS 512

// ---------------------------------------------------------------------------
// Helpers
// ---------------------------------------------------------------------------
__device__ __forceinline__ u32 smem_u32(const void* p) {
    u32 a;
    asm("{ .reg .u64 t; cvta.to.shared.u64 t, %1; cvt.u32.u64 %0, t; }"
        : "=r"(a) : "l"(p));
    return a;
}
__device__ __forceinline__ u32 pack_bf16x2(float e0, float e1) {
    u32 r;
    asm("cvt.rn.bf16x2.f32 %0, %1, %2;" : "=r"(r) : "f"(e1), "f"(e0));
    return r;
}
__device__ __forceinline__ float bf_lo_f(u32 p) { return __uint_as_float(p << 16); }
__device__ __forceinline__ float bf_hi_f(u32 p) { return __uint_as_float(p & 0xffff0000u); }
__device__ __forceinline__ float silu_f(float v) { return __fdividef(v, 1.0f + __expf(-v)); }

__device__ __forceinline__ void ldsm4(u32& r0, u32& r1, u32& r2, u32& r3, u32 addr) {
    asm volatile("ldmatrix.sync.aligned.m8n8.x4.shared.b16 {%0,%1,%2,%3}, [%4];"
                 : "=r"(r0), "=r"(r1), "=r"(r2), "=r"(r3) : "r"(addr));
}
__device__ __forceinline__ void mma16816(float* c, const u32* a, u32 b0, u32 b1) {
    asm volatile(
        "mma.sync.aligned.m16n8k16.row.col.f32.bf16.bf16.f32 "
        "{%0,%1,%2,%3}, {%4,%5,%6,%7}, {%8,%9}, {%0,%1,%2,%3};"
        : "+f"(c[0]), "+f"(c[1]), "+f"(c[2]), "+f"(c[3])
        : "r"(a[0]), "r"(a[1]), "r"(a[2]), "r"(a[3]), "r"(b0), "r"(b1));
}
__device__ __forceinline__ void split4(float v0, float v1, float v2, float v3,
                                       u64& hi, u64& lo) {
    u32 h0 = pack_bf16x2(v0, v1), h1 = pack_bf16x2(v2, v3);
    u32 l0 = pack_bf16x2(v0 - bf_lo_f(h0), v1 - bf_hi_f(h0));
    u32 l1 = pack_bf16x2(v2 - bf_lo_f(h1), v3 - bf_hi_f(h1));
    hi = (u64)h0 | ((u64)h1 << 32);
    lo = (u64)l0 | ((u64)l1 << 32);
}

// ---- cp.async ----
__device__ __forceinline__ void cp16(u32 dst, const void* src) {
    asm volatile("cp.async.cg.shared.global [%0], [%1], 16;" :: "r"(dst), "l"(src));
}
#define CP_COMMIT() asm volatile("cp.async.commit_group;" ::: "memory")
#define CP_WAIT(n)  asm volatile("cp.async.wait_group %0;" :: "n"(n) : "memory")

// Async prefetch of one weight chunk (hi+lo, 69632 B = 4352 x 16B). 512 thr.
__device__ __forceinline__ void fill_B_async(u32 dst, const unsigned char* w, int tid) {
#pragma unroll
    for (int i = 0; i < 9; ++i) {
        int t = tid + i * NTHREADS;
        if (t < WCHUNK / 16) cp16(dst + t * 16, w + t * 16);
    }
}

// ---------------------------------------------------------------------------
// Per-warp GEMM over one 128-K chunk, 3-term bf16 split. Warp tile 16x64.
// acc[8][4]: 8 n8-groups x 4 regs (one m16 group).
// ---------------------------------------------------------------------------
__device__ __forceinline__ void chunk_mma(u32 smb, u32 bbase, float acc[8][4],
                                          int mbase, int nbase, int lane) {
    const u32 a_off = (u32)(mbase + (lane & 15)) * ROWB + (u32)(lane >> 4) * 16;
    const u32 b_off = (u32)(nbase + (lane & 7) + ((lane >> 4) & 1) * 8) * ROWB
                    + (u32)((lane >> 3) & 1) * 16;
    const u32 bhi = smb + bbase, blo = smb + bbase + BTILE;
#pragma unroll
    for (int ks = 0; ks < 8; ++ks) {
        const u32 kb = (u32)ks * 32;
        u32 ah[4], al[4], b[4][4];
        ldsm4(ah[0], ah[1], ah[2], ah[3], smb + SM_AHI + a_off + kb);
#pragma unroll
        for (int g = 0; g < 4; ++g)
            ldsm4(b[g][0], b[g][1], b[g][2], b[g][3],
                  bhi + b_off + (u32)g * (16 * ROWB) + kb);
        // hh
#pragma unroll
        for (int ng = 0; ng < 8; ++ng)
            mma16816(acc[ng], ah, b[ng >> 1][(ng & 1) * 2], b[ng >> 1][(ng & 1) * 2 + 1]);
        // lh
        ldsm4(al[0], al[1], al[2], al[3], smb + SM_ALO + a_off + kb);
#pragma unroll
        for (int ng = 0; ng < 8; ++ng)
            mma16816(acc[ng], al, b[ng >> 1][(ng & 1) * 2], b[ng >> 1][(ng & 1) * 2 + 1]);
        // hl
#pragma unroll
        for (int g = 0; g < 4; ++g)
            ldsm4(b[g][0], b[g][1], b[g][2], b[g][3],
                  blo + b_off + (u32)g * (16 * ROWB) + kb);
#pragma unroll
        for (int ng = 0; ng < 8; ++ng)
            mma16816(acc[ng], ah, b[ng >> 1][(ng & 1) * 2], b[ng >> 1][(ng & 1) * 2 + 1]);
    }
}

// bias + SiLU from acc -> A smem (hi/lo), zero acc
__device__ __forceinline__ void mid_epi(char* sm, float acc[8][4],
                                        const float* __restrict__ bias,
                                        int mbase, int nbase, int lane) {
    const int q = lane & 3, r = lane >> 2;
#pragma unroll
    for (int ng = 0; ng < 8; ++ng) {
        const int col = nbase + ng * 8 + q * 2;
        const float bx = __ldg(bias + col), by = __ldg(bias + col + 1);
        const int r0 = mbase + r, r1 = r0 + 8;
        float v0 = silu_f(acc[ng][0] + bx);
        float v1 = silu_f(acc[ng][1] + by);
        float v2 = silu_f(acc[ng][2] + bx);
        float v3 = silu_f(acc[ng][3] + by);
        u32 h0 = pack_bf16x2(v0, v1);
        u32 l0 = pack_bf16x2(v0 - bf_lo_f(h0), v1 - bf_hi_f(h0));
        u32 h1 = pack_bf16x2(v2, v3);
        u32 l1 = pack_bf16x2(v2 - bf_lo_f(h1), v3 - bf_hi_f(h1));
        *(u32*)(sm + SM_AHI + r0 * ROWB + col * 2) = h0;
        *(u32*)(sm + SM_ALO + r0 * ROWB + col * 2) = l0;
        *(u32*)(sm + SM_AHI + r1 * ROWB + col * 2) = h1;
        *(u32*)(sm + SM_ALO + r1 * ROWB + col * 2) = l1;
        acc[ng][0] = 0.f; acc[ng][1] = 0.f;
        acc[ng][2] = 0.f; acc[ng][3] = 0.f;
    }
}

#define SVS 130  // float scratch stride; 128*130*4 = 66560 <= 2*BTILE

__device__ __forceinline__ void final_dump(char* sm, float acc[8][4],
                                           const float* __restrict__ b3,
                                           int mbase, int nbase, int lane) {
    float* sv = (float*)sm;
    const int q = lane & 3, r = lane >> 2;
#pragma unroll
    for (int ng = 0; ng < 8; ++ng) {
        const int col = nbase + ng * 8 + q * 2;
        const float bx = __ldg(b3 + col), by = __ldg(b3 + col + 1);
        const int r0 = mbase + r, r1 = r0 + 8;
        *(float2*)(sv + r0 * SVS + col) = make_float2(acc[ng][0] + bx, acc[ng][1] + by);
        *(float2*)(sv + r1 * SVS + col) = make_float2(acc[ng][2] + bx, acc[ng][3] + by);
    }
}

// per-row mean/rstd stored in B0 region (dead by then)
__device__ __forceinline__ void ln_stats(char* sm, int tid) {
    if (tid < MROWS) {
        const float* sv = (float*)sm;
        float s1 = 0.f, s2 = 0.f;
#pragma unroll 16
        for (int c = 0; c < 128; c += 2) {
            float2 v = *(const float2*)(sv + tid * SVS + c);
            s1 += v.x + v.y;
            s2 += v.x * v.x + v.y * v.y;
        }
        float mean = s1 * (1.0f / 128.0f);
        float var = s2 * (1.0f / 128.0f) - mean * mean;
        ((float*)(sm + SM_B0))[tid] = mean;
        ((float*)(sm + SM_B0 + 512))[tid] = rsqrtf(var + 1e-5f);
    }
}

// ---------------------------------------------------------------------------
// Edge kernel: 128 edges/block, 512 threads (16 warps), warp tile 16x64
// ---------------------------------------------------------------------------
__global__ __launch_bounds__(NTHREADS, 1)
void edge_kernel(const float* __restrict__ x, const int* __restrict__ eidx,
                 const float* __restrict__ ea,
                 const float* __restrict__ b1, const float* __restrict__ b2,
                 const float* __restrict__ b3,
                 const float* __restrict__ gw, const float* __restrict__ bw,
                 float* __restrict__ out_e) {
    extern __shared__ char sm[];
    const u32 smb = smem_u32(sm);
    const int tid = threadIdx.x, wid = tid >> 5, lane = tid & 31;
    const int mbase = (wid >> 1) * 16, nbase = (wid & 1) * 64;
    const int e0 = blockIdx.x * MROWS;

    float acc[8][4];
#pragma unroll
    for (int ng = 0; ng < 8; ++ng)
#pragma unroll
        for (int k = 0; k < 4; ++k) acc[ng][k] = 0.f;

    // prefetch first two weight chunks
    fill_B_async(smb + SM_B0, g_we, tid);              CP_COMMIT();
    fill_B_async(smb + SM_B1, g_we + WCHUNK, tid);     CP_COMMIT();

    // ---- layer 1: 3 accumulated K=128 chunks (x[i], x[j], edge_attr) ----
    for (int s = 0; s < 3; ++s) {
        const int row = tid >> 2, qb = (tid & 3) * 8;
        const int g = (s == 0) ? __ldg(eidx + e0 + row)
                    : (s == 1) ? __ldg(eidx + NE + e0 + row)
                               : (e0 + row);
        const float4* src = (s == 2) ? (const float4*)ea : (const float4*)x;
#pragma unroll 4
        for (int i = 0; i < 8; ++i) {
            float4 v = __ldg(src + (size_t)g * 32 + qb + i);
            u64 hi, lo;
            split4(v.x, v.y, v.z, v.w, hi, lo);
            *(u64*)(sm + SM_AHI + row * ROWB + (qb + i) * 8) = hi;
            *(u64*)(sm + SM_ALO + row * ROWB + (qb + i) * 8) = lo;
        }
        CP_WAIT(1);
        __syncthreads();
        chunk_mma(smb, (s & 1) ? SM_B1 : SM_B0, acc, mbase, nbase, lane);
        __syncthreads();
        if (s + 2 < 5) {
            fill_B_async(smb + ((s & 1) ? SM_B1 : SM_B0), g_we + (size_t)(s + 2) * WCHUNK, tid);
            CP_COMMIT();
        }
    }

    // ---- layer 2 (chunk 3 -> buffer 1) ----
    mid_epi(sm, acc, b1, mbase, nbase, lane);
    CP_WAIT(1);
    __syncthreads();
    chunk_mma(smb, SM_B1, acc, mbase, nbase, lane);
    __syncthreads();

    // ---- layer 3 (chunk 4 -> buffer 0) ----
    mid_epi(sm, acc, b2, mbase, nbase, lane);
    CP_WAIT(0);
    __syncthreads();
    chunk_mma(smb, SM_B0, acc, mbase, nbase, lane);
    __syncthreads();

    // ---- final: bias3 -> LN -> residual -> store + scatter ----
    final_dump(sm, acc, b3, mbase, nbase, lane);
    __syncthreads();
    ln_stats(sm, tid);
    __syncthreads();

    {
        const int tc = tid & 15, tr = tid >> 4;   // tr 0..31
        const float* sv = (const float*)sm;
        const float* smean = (const float*)(sm + SM_B0);
        const float* srstd = (const float*)(sm + SM_B0 + 512);
        float gv[8], bv[8];
#pragma unroll
        for (int j = 0; j < 8; ++j) {
            gv[j] = __ldg(gw + tc * 8 + j);
            bv[j] = __ldg(bw + tc * 8 + j);
        }
        // 512 threads x 4 iters: rows 0..127, 16 col-groups
        for (int r4 = 0; r4 < 4; ++r4) {
            const int row = r4 * 32 + tr;
            const long long gr = e0 + row;
            const float mean = smean[row], rstd = srstd[row];
            float4 ra = __ldg((const float4*)ea + gr * 32 + tc * 2);
            float4 rb = __ldg((const float4*)ea + gr * 32 + tc * 2 + 1);
            float o[8];
#pragma unroll
            for (int j = 0; j < 8; ++j)
                o[j] = (sv[row * SVS + tc * 8 + j] - mean) * rstd * gv[j] + bv[j];
            o[0] += ra.x; o[1] += ra.y; o[2] += ra.z; o[3] += ra.w;
            o[4] += rb.x; o[5] += rb.y; o[6] += rb.z; o[7] += rb.w;
            ((float4*)out_e)[gr * 32 + tc * 2]     = make_float4(o[0], o[1], o[2], o[3]);
            ((float4*)out_e)[gr * 32 + tc * 2 + 1] = make_float4(o[4], o[5], o[6], o[7]);
            const int dj = __ldg(eidx + NE + gr);
            float* ap = g_agg + (size_t)dj * 128 + tc * 8;
#pragma unroll
            for (int j = 0; j < 8; ++j) atomicAdd(ap + j, o[j]);
        }
    }
}

// ---------------------------------------------------------------------------
// Node kernel: 128 nodes/block, 512 threads
// ---------------------------------------------------------------------------
__global__ __launch_bounds__(NTHREADS, 1)
void node_kernel(const float* __restrict__ x,
                 const float* __restrict__ b1, const float* __restrict__ b2,
                 const float* __restrict__ b3,
                 const float* __restrict__ gw, const float* __restrict__ bw,
                 float* __restrict__ out_x) {
    extern __shared__ char sm[];
    const u32 smb = smem_u32(sm);
    const int tid = threadIdx.x, wid = tid >> 5, lane = tid & 31;
    const int mbase = (wid >> 1) * 16, nbase = (wid & 1) * 64;
    const int n0 = blockIdx.x * MROWS;

    float acc[8][4];
#pragma unroll
    for (int ng = 0; ng < 8; ++ng)
#pragma unroll
        for (int k = 0; k < 4; ++k) acc[ng][k] = 0.f;

    fill_B_async(smb + SM_B0, g_wn, tid);              CP_COMMIT();
    fill_B_async(smb + SM_B1, g_wn + WCHUNK, tid);     CP_COMMIT();

    // ---- layer 1: 2 accumulated K=128 chunks (x, agg) ----
    for (int s = 0; s < 2; ++s) {
        const float4* src = (s == 0) ? (const float4*)x : (const float4*)g_agg;
        const int row = tid >> 2, qb = (tid & 3) * 8;
        const int g = n0 + row;
#pragma unroll 4
        for (int i = 0; i < 8; ++i) {
            float4 v = make_float4(0.f, 0.f, 0.f, 0.f);
            if (g < NN) v = __ldg(src + (size_t)g * 32 + qb + i);
            u64 hi, lo;
            split4(v.x, v.y, v.z, v.w, hi, lo);
            *(u64*)(sm + SM_AHI + row * ROWB + (qb + i) * 8) = hi;
            *(u64*)(sm + SM_ALO + row * ROWB + (qb + i) * 8) = lo;
        }
        CP_WAIT(1);
        __syncthreads();
        chunk_mma(smb, (s & 1) ? SM_B1 : SM_B0, acc, mbase, nbase, lane);
        __syncthreads();
        if (s + 2 < 4) {
            fill_B_async(smb + ((s & 1) ? SM_B1 : SM_B0), g_wn + (size_t)(s + 2) * WCHUNK, tid);
            CP_COMMIT();
        }
    }

    // ---- layer 2 (chunk 2 -> buffer 0) ----
    mid_epi(sm, acc, b1, mbase, nbase, lane);
    CP_WAIT(1);
    __syncthreads();
    chunk_mma(smb, SM_B0, acc, mbase, nbase, lane);
    __syncthreads();

    // ---- layer 3 (chunk 3 -> buffer 1) ----
    mid_epi(sm, acc, b2, mbase, nbase, lane);
    CP_WAIT(0);
    __syncthreads();
    chunk_mma(smb, SM_B1, acc, mbase, nbase, lane);
    __syncthreads();

    final_dump(sm, acc, b3, mbase, nbase, lane);
    __syncthreads();
    ln_stats(sm, tid);
    __syncthreads();

    {
        const int tc = tid & 15, tr = tid >> 4;
        const float* sv = (const float*)sm;
        const float* smean = (const float*)(sm + SM_B0);
        const float* srstd = (const float*)(sm + SM_B0 + 512);
        float gv[8], bv[8];
#pragma unroll
        for (int j = 0; j < 8; ++j) {
            gv[j] = __ldg(gw + tc * 8 + j);
            bv[j] = __ldg(bw + tc * 8 + j);
        }
        for (int r4 = 0; r4 < 4; ++r4) {
            const int row = r4 * 32 + tr;
            const long long gr = n0 + row;
            if (gr < NN) {
                const float mean = smean[row], rstd = srstd[row];
                float4 ra = __ldg((const float4*)x + gr * 32 + tc * 2);
                float4 rb = __ldg((const float4*)x + gr * 32 + tc * 2 + 1);
                float o[8];
#pragma unroll
                for (int j = 0; j < 8; ++j)
                    o[j] = (sv[row * SVS + tc * 8 + j] - mean) * rstd * gv[j] + bv[j];
                o[0] += ra.x; o[1] += ra.y; o[2] += ra.z; o[3] += ra.w;
                o[4] += rb.x; o[5] += rb.y; o[6] += rb.z; o[7] += rb.w;
                ((float4*)out_x)[gr * 32 + tc * 2]     = make_float4(o[0], o[1], o[2], o[3]);
                ((float4*)out_x)[gr * 32 + tc * 2 + 1] = make_float4(o[4], o[5], o[6], o[7]);
            }
        }
    }
}

// ---------------------------------------------------------------------------
// Weight prep: split into bf16 hi/lo, transpose to [n][k], row stride 272B.
// ---------------------------------------------------------------------------
__global__ void prep_w(const float* __restrict__ ew1, const float* __restrict__ ew2,
                       const float* __restrict__ ew3, const float* __restrict__ nw1,
                       const float* __restrict__ nw2, const float* __restrict__ nw3) {
    int i = blockIdx.x * blockDim.x + threadIdx.x;
    if (i >= 9 * 16384) return;
    unsigned char* dst;
    float val;
    int cs = i >> 14, r = i & 16383;
    int kl = r >> 7, n = r & 127;
    if (cs < 5) {
        if (cs < 3)       val = ew1[(cs * 128 + kl) * 128 + n];
        else if (cs == 3) val = ew2[kl * 128 + n];
        else              val = ew3[kl * 128 + n];
        dst = g_we + (size_t)cs * WCHUNK;
    } else {
        int ns = cs - 5;
        if (ns < 2)       val = nw1[(ns * 128 + kl) * 128 + n];
        else if (ns == 2) val = nw2[kl * 128 + n];
        else              val = nw3[kl * 128 + n];
        dst = g_wn + (size_t)ns * WCHUNK;
    }
    u32 h = pack_bf16x2(val, 0.f);
    u32 l = pack_bf16x2(val - bf_lo_f(h), 0.f);
    *(unsigned short*)(dst + n * ROWB + kl * 2)         = (unsigned short)(h & 0xffff);
    *(unsigned short*)(dst + BTILE + n * ROWB + kl * 2) = (unsigned short)(l & 0xffff);
}

__global__ void zero_agg_kernel() {
    int i = blockIdx.x * blockDim.x + threadIdx.x;
    if (i < NN * 32)
        ((float4*)g_agg)[i] = make_float4(0.f, 0.f, 0.f, 0.f);
}

// ---------------------------------------------------------------------------
extern "C" void kernel_launch(void* const* d_in, const int* in_sizes, int n_in,
                              void* d_out, int out_size) {
    const float* x    = (const float*)d_in[0];
    const int*   eidx = (const int*)d_in[1];
    const float* ea   = (const float*)d_in[2];
    const float* ew1  = (const float*)d_in[3];
    const float* eb1  = (const float*)d_in[4];
    const float* ew2  = (const float*)d_in[5];
    const float* eb2  = (const float*)d_in[6];
    const float* ew3  = (const float*)d_in[7];
    const float* eb3  = (const float*)d_in[8];
    const float* eg   = (const float*)d_in[9];
    const float* ebt  = (const float*)d_in[10];
    const float* nw1  = (const float*)d_in[11];
    const float* nb1  = (const float*)d_in[12];
    const float* nw2  = (const float*)d_in[13];
    const float* nb2  = (const float*)d_in[14];
    const float* nw3  = (const float*)d_in[15];
    const float* nb3  = (const float*)d_in[16];
    const float* ng   = (const float*)d_in[17];
    const float* nbt  = (const float*)d_in[18];

    float* out_x = (float*)d_out;                       // [50000, 128]
    float* out_e = (float*)d_out + (size_t)NN * 128;    // [800000, 128]

    cudaFuncSetAttribute(edge_kernel, cudaFuncAttributeMaxDynamicSharedMemorySize, SM_BYTES);
    cudaFuncSetAttribute(node_kernel, cudaFuncAttributeMaxDynamicSharedMemorySize, SM_BYTES);

    zero_agg_kernel<<<(NN * 32 + 255) / 256, 256>>>();
    prep_w<<<(9 * 16384 + 255) / 256, 256>>>(ew1, ew2, ew3, nw1, nw2, nw3);
    edge_kernel<<<NE / MROWS, NTHREADS, SM_BYTES>>>(x, eidx, ea, eb1, eb2, eb3, eg, ebt, out_e);
    node_kernel<<<(NN + MROWS - 1) / MROWS, NTHREADS, SM_BYTES>>>(x, nb1, nb2, nb3, ng, nbt, out_x);
}

// round 9
// speedup vs baseline: 1.0371x; 1.0371x over previous
#include <cuda_runtime.h>

#define NN 50000
#define NE 800000

typedef unsigned int u32;
typedef unsigned long long u64;

// ---------------------------------------------------------------------------
// Device scratch (no cudaMalloc allowed)
// ---------------------------------------------------------------------------
__device__ float g_agg[(size_t)NN * 128];
// Pre-split bf16 weights, transposed to [n][k], row stride 272B.
// Chunk = [hi 34816][lo 34816]; halves are consecutive 34816-byte blocks.
#define HB 34816
#define WCHUNK (2 * HB)
__device__ __align__(16) unsigned char g_we[5 * WCHUNK]; // edge: L1 x3, L2, L3
__device__ __align__(16) unsigned char g_wn[4 * WCHUNK]; // node: L1 x2, L2, L3

// ---------------------------------------------------------------------------
// SMEM: A_hi, A_lo (64 rows), two B half-buffers (128 rows each).
// ---------------------------------------------------------------------------
#define ROWB 272
#define SM_AHI 0
#define SM_ALO 17408             // 64*272
#define SM_BB0 34816
#define SM_BB1 (34816 + HB)      // 69632
#define SM_BYTES (34816 + 2 * HB) // 104448  -> 2 blocks/SM

#define MROWS 64
#define NTHREADS 128

// ---------------------------------------------------------------------------
// Helpers
// ---------------------------------------------------------------------------
__device__ __forceinline__ u32 smem_u32(const void* p) {
    u32 a;
    asm("{ .reg .u64 t; cvta.to.shared.u64 t, %1; cvt.u32.u64 %0, t; }"
        : "=r"(a) : "l"(p));
    return a;
}
__device__ __forceinline__ u32 pack_bf16x2(float e0, float e1) {
    u32 r;
    asm("cvt.rn.bf16x2.f32 %0, %1, %2;" : "=r"(r) : "f"(e1), "f"(e0));
    return r;
}
__device__ __forceinline__ float bf_lo_f(u32 p) { return __uint_as_float(p << 16); }
__device__ __forceinline__ float bf_hi_f(u32 p) { return __uint_as_float(p & 0xffff0000u); }
__device__ __forceinline__ float silu_f(float v) { return __fdividef(v, 1.0f + __expf(-v)); }

__device__ __forceinline__ void ldsm4(u32& r0, u32& r1, u32& r2, u32& r3, u32 addr) {
    asm volatile("ldmatrix.sync.aligned.m8n8.x4.shared.b16 {%0,%1,%2,%3}, [%4];"
                 : "=r"(r0), "=r"(r1), "=r"(r2), "=r"(r3) : "r"(addr));
}
__device__ __forceinline__ void mma16816(float* c, const u32* a, u32 b0, u32 b1) {
    asm volatile(
        "mma.sync.aligned.m16n8k16.row.col.f32.bf16.bf16.f32 "
        "{%0,%1,%2,%3}, {%4,%5,%6,%7}, {%8,%9}, {%0,%1,%2,%3};"
        : "+f"(c[0]), "+f"(c[1]), "+f"(c[2]), "+f"(c[3])
        : "r"(a[0]), "r"(a[1]), "r"(a[2]), "r"(a[3]), "r"(b0), "r"(b1));
}
__device__ __forceinline__ void split4(float v0, float v1, float v2, float v3,
                                       u64& hi, u64& lo) {
    u32 h0 = pack_bf16x2(v0, v1), h1 = pack_bf16x2(v2, v3);
    u32 l0 = pack_bf16x2(v0 - bf_lo_f(h0), v1 - bf_hi_f(h0));
    u32 l1 = pack_bf16x2(v2 - bf_lo_f(h1), v3 - bf_hi_f(h1));
    hi = (u64)h0 | ((u64)h1 << 32);
    lo = (u64)l0 | ((u64)l1 << 32);
}

// ---- cp.async ----
__device__ __forceinline__ void cp16(u32 dst, const void* src) {
    asm volatile("cp.async.cg.shared.global [%0], [%1], 16;" :: "r"(dst), "l"(src));
}
#define CP_COMMIT() asm volatile("cp.async.commit_group;" ::: "memory")
#define CP_WAIT(n)  asm volatile("cp.async.wait_group %0;" :: "n"(n) : "memory")

// Prefetch one 34816-B weight half (2176 x 16B, 128 threads -> 17 each).
__device__ __forceinline__ void fill_half(u32 dst, const unsigned char* w, int tid) {
#pragma unroll
    for (int i = 0; i < 17; ++i) {
        int t = tid + i * NTHREADS;
        cp16(dst + t * 16, w + t * 16);
    }
}

// ---------------------------------------------------------------------------
// MMA halves over one 128-K chunk. Warp tile 32x64. acc[2][8][4].
// even: hh + lh on B-hi half. odd: hl on B-lo half.
// ---------------------------------------------------------------------------
__device__ __forceinline__ void mma_even(u32 smb, u32 bbuf, float acc[2][8][4],
                                         int mbase, int nbase, int lane) {
    const u32 a_off = (u32)(mbase + (lane & 15)) * ROWB + (u32)(lane >> 4) * 16;
    const u32 b_off = (u32)(nbase + (lane & 7) + ((lane >> 4) & 1) * 8) * ROWB
                    + (u32)((lane >> 3) & 1) * 16;
#pragma unroll
    for (int ks = 0; ks < 8; ++ks) {
        const u32 kb = (u32)ks * 32;
        u32 ah[2][4], al[2][4], b[4][4];
#pragma unroll
        for (int mg = 0; mg < 2; ++mg)
            ldsm4(ah[mg][0], ah[mg][1], ah[mg][2], ah[mg][3],
                  smb + SM_AHI + a_off + (u32)mg * (16 * ROWB) + kb);
#pragma unroll
        for (int g = 0; g < 4; ++g)
            ldsm4(b[g][0], b[g][1], b[g][2], b[g][3],
                  bbuf + b_off + (u32)g * (16 * ROWB) + kb);
#pragma unroll
        for (int mg = 0; mg < 2; ++mg)
#pragma unroll
            for (int ng = 0; ng < 8; ++ng)
                mma16816(acc[mg][ng], ah[mg], b[ng >> 1][(ng & 1) * 2], b[ng >> 1][(ng & 1) * 2 + 1]);
#pragma unroll
        for (int mg = 0; mg < 2; ++mg)
            ldsm4(al[mg][0], al[mg][1], al[mg][2], al[mg][3],
                  smb + SM_ALO + a_off + (u32)mg * (16 * ROWB) + kb);
#pragma unroll
        for (int mg = 0; mg < 2; ++mg)
#pragma unroll
            for (int ng = 0; ng < 8; ++ng)
                mma16816(acc[mg][ng], al[mg], b[ng >> 1][(ng & 1) * 2], b[ng >> 1][(ng & 1) * 2 + 1]);
    }
}

__device__ __forceinline__ void mma_odd(u32 smb, u32 bbuf, float acc[2][8][4],
                                        int mbase, int nbase, int lane) {
    const u32 a_off = (u32)(mbase + (lane & 15)) * ROWB + (u32)(lane >> 4) * 16;
    const u32 b_off = (u32)(nbase + (lane & 7) + ((lane >> 4) & 1) * 8) * ROWB
                    + (u32)((lane >> 3) & 1) * 16;
#pragma unroll
    for (int ks = 0; ks < 8; ++ks) {
        const u32 kb = (u32)ks * 32;
        u32 ah[2][4], b[4][4];
#pragma unroll
        for (int mg = 0; mg < 2; ++mg)
            ldsm4(ah[mg][0], ah[mg][1], ah[mg][2], ah[mg][3],
                  smb + SM_AHI + a_off + (u32)mg * (16 * ROWB) + kb);
#pragma unroll
        for (int g = 0; g < 4; ++g)
            ldsm4(b[g][0], b[g][1], b[g][2], b[g][3],
                  bbuf + b_off + (u32)g * (16 * ROWB) + kb);
#pragma unroll
        for (int mg = 0; mg < 2; ++mg)
#pragma unroll
            for (int ng = 0; ng < 8; ++ng)
                mma16816(acc[mg][ng], ah[mg], b[ng >> 1][(ng & 1) * 2], b[ng >> 1][(ng & 1) * 2 + 1]);
    }
}

// bias + SiLU from acc -> A smem (hi/lo), zero acc
__device__ __forceinline__ void mid_epi(char* sm, float acc[2][8][4],
                                        const float* __restrict__ bias,
                                        int mbase, int nbase, int lane) {
    const int q = lane & 3, r = lane >> 2;
#pragma unroll
    for (int mg = 0; mg < 2; ++mg) {
#pragma unroll
        for (int ng = 0; ng < 8; ++ng) {
            const int col = nbase + ng * 8 + q * 2;
            const float bx = __ldg(bias + col), by = __ldg(bias + col + 1);
            const int r0 = mbase + mg * 16 + r, r1 = r0 + 8;
            float v0 = silu_f(acc[mg][ng][0] + bx);
            float v1 = silu_f(acc[mg][ng][1] + by);
            float v2 = silu_f(acc[mg][ng][2] + bx);
            float v3 = silu_f(acc[mg][ng][3] + by);
            u32 h0 = pack_bf16x2(v0, v1);
            u32 l0 = pack_bf16x2(v0 - bf_lo_f(h0), v1 - bf_hi_f(h0));
            u32 h1 = pack_bf16x2(v2, v3);
            u32 l1 = pack_bf16x2(v2 - bf_lo_f(h1), v3 - bf_hi_f(h1));
            *(u32*)(sm + SM_AHI + r0 * ROWB + col * 2) = h0;
            *(u32*)(sm + SM_ALO + r0 * ROWB + col * 2) = l0;
            *(u32*)(sm + SM_AHI + r1 * ROWB + col * 2) = h1;
            *(u32*)(sm + SM_ALO + r1 * ROWB + col * 2) = l1;
            acc[mg][ng][0] = 0.f; acc[mg][ng][1] = 0.f;
            acc[mg][ng][2] = 0.f; acc[mg][ng][3] = 0.f;
        }
    }
}

#define SVS 130  // float scratch stride; 64*130*4 = 33280 <= A region

__device__ __forceinline__ void final_dump(char* sm, float acc[2][8][4],
                                           const float* __restrict__ b3,
                                           int mbase, int nbase, int lane) {
    float* sv = (float*)sm;
    const int q = lane & 3, r = lane >> 2;
#pragma unroll
    for (int mg = 0; mg < 2; ++mg) {
#pragma unroll
        for (int ng = 0; ng < 8; ++ng) {
            const int col = nbase + ng * 8 + q * 2;
            const float bx = __ldg(b3 + col), by = __ldg(b3 + col + 1);
            const int r0 = mbase + mg * 16 + r, r1 = r0 + 8;
            *(float2*)(sv + r0 * SVS + col) = make_float2(acc[mg][ng][0] + bx, acc[mg][ng][1] + by);
            *(float2*)(sv + r1 * SVS + col) = make_float2(acc[mg][ng][2] + bx, acc[mg][ng][3] + by);
        }
    }
}

// per-row mean/rstd; stats in B0 region (dead by then)
__device__ __forceinline__ void ln_stats(char* sm, int tid) {
    if (tid < MROWS) {
        const float* sv = (float*)sm;
        float s1 = 0.f, s2 = 0.f;
#pragma unroll 16
        for (int c = 0; c < 128; c += 2) {
            float2 v = *(const float2*)(sv + tid * SVS + c);
            s1 += v.x + v.y;
            s2 += v.x * v.x + v.y * v.y;
        }
        float mean = s1 * (1.0f / 128.0f);
        float var = s2 * (1.0f / 128.0f) - mean * mean;
        ((float*)(sm + SM_BB0))[tid] = mean;
        ((float*)(sm + SM_BB0 + 256))[tid] = rsqrtf(var + 1e-5f);
    }
}

// ---------------------------------------------------------------------------
// Edge kernel: 64 edges/block, 128 threads (4 warps), 2 blocks/SM
// ---------------------------------------------------------------------------
__global__ __launch_bounds__(NTHREADS)
void edge_kernel(const float* __restrict__ x, const int* __restrict__ eidx,
                 const float* __restrict__ ea,
                 const float* __restrict__ b1, const float* __restrict__ b2,
                 const float* __restrict__ b3,
                 const float* __restrict__ gw, const float* __restrict__ bw,
                 float* __restrict__ out_e) {
    extern __shared__ char sm[];
    const u32 smb = smem_u32(sm);
    const int tid = threadIdx.x, wid = tid >> 5, lane = tid & 31;
    const int mbase = (wid >> 1) * 32, nbase = (wid & 1) * 64;
    const int e0 = blockIdx.x * MROWS;

    float acc[2][8][4];
#pragma unroll
    for (int mg = 0; mg < 2; ++mg)
#pragma unroll
        for (int ng = 0; ng < 8; ++ng)
#pragma unroll
            for (int k = 0; k < 4; ++k) acc[mg][ng][k] = 0.f;

    // prologue: prefetch first two weight halves
    fill_half(smb + SM_BB0, g_we, tid);       CP_COMMIT();
    fill_half(smb + SM_BB1, g_we + HB, tid);  CP_COMMIT();

    // gather A(0) = x[i]
    {
        const int row = tid >> 1, qb = (tid & 1) * 16;
        const int g = __ldg(eidx + e0 + row);
#pragma unroll 4
        for (int i = 0; i < 16; ++i) {
            float4 v = __ldg((const float4*)x + (size_t)g * 32 + qb + i);
            u64 hi, lo;
            split4(v.x, v.y, v.z, v.w, hi, lo);
            *(u64*)(sm + SM_AHI + row * ROWB + (qb + i) * 8) = hi;
            *(u64*)(sm + SM_ALO + row * ROWB + (qb + i) * 8) = lo;
        }
    }

    // 5 chunks = 10 half-steps
#pragma unroll 1
    for (int t = 0; t < 10; ++t) {
        const u32 bbuf = smb + SM_BB0 + (u32)(t & 1) * HB;
        CP_WAIT(1);
        __syncthreads();
        if (t & 1) mma_odd(smb, bbuf, acc, mbase, nbase, lane);
        else       mma_even(smb, bbuf, acc, mbase, nbase, lane);
        __syncthreads();
        if (t + 2 < 10) {
            fill_half(bbuf, g_we + (size_t)(t + 2) * HB, tid);
            CP_COMMIT();
        }
        if (t & 1) {
            const int s = t >> 1;
            if (s < 2) {
                // gather A(s+1): s+1==1 -> x[j], s+1==2 -> edge_attr
                const int row = tid >> 1, qb = (tid & 1) * 16;
                const int g = (s == 0) ? __ldg(eidx + NE + e0 + row) : (e0 + row);
                const float4* src = (s == 0) ? (const float4*)x : (const float4*)ea;
#pragma unroll 4
                for (int i = 0; i < 16; ++i) {
                    float4 v = __ldg(src + (size_t)g * 32 + qb + i);
                    u64 hi, lo;
                    split4(v.x, v.y, v.z, v.w, hi, lo);
                    *(u64*)(sm + SM_AHI + row * ROWB + (qb + i) * 8) = hi;
                    *(u64*)(sm + SM_ALO + row * ROWB + (qb + i) * 8) = lo;
                }
            } else if (s == 2) {
                mid_epi(sm, acc, b1, mbase, nbase, lane);
            } else if (s == 3) {
                mid_epi(sm, acc, b2, mbase, nbase, lane);
            }
        }
    }

    // ---- final: bias3 -> LN -> residual -> store + scatter ----
    final_dump(sm, acc, b3, mbase, nbase, lane);
    __syncthreads();
    ln_stats(sm, tid);
    __syncthreads();

    {
        const int tc = tid & 15, tr = tid >> 4;   // tr 0..7
        const float* sv = (const float*)sm;
        const float* smean = (const float*)(sm + SM_BB0);
        const float* srstd = (const float*)(sm + SM_BB0 + 256);
        float gv[8], bv[8];
#pragma unroll
        for (int j = 0; j < 8; ++j) {
            gv[j] = __ldg(gw + tc * 8 + j);
            bv[j] = __ldg(bw + tc * 8 + j);
        }
        // 128 threads x 8 iters: rows 0..63, 16 col-groups
        for (int r8 = 0; r8 < 8; ++r8) {
            const int row = r8 * 8 + tr;
            const long long gr = e0 + row;
            const float mean = smean[row], rstd = srstd[row];
            float4 ra = __ldg((const float4*)ea + gr * 32 + tc * 2);
            float4 rb = __ldg((const float4*)ea + gr * 32 + tc * 2 + 1);
            float o[8];
#pragma unroll
            for (int j = 0; j < 8; ++j)
                o[j] = (sv[row * SVS + tc * 8 + j] - mean) * rstd * gv[j] + bv[j];
            o[0] += ra.x; o[1] += ra.y; o[2] += ra.z; o[3] += ra.w;
            o[4] += rb.x; o[5] += rb.y; o[6] += rb.z; o[7] += rb.w;
            ((float4*)out_e)[gr * 32 + tc * 2]     = make_float4(o[0], o[1], o[2], o[3]);
            ((float4*)out_e)[gr * 32 + tc * 2 + 1] = make_float4(o[4], o[5], o[6], o[7]);
            const int dj = __ldg(eidx + NE + gr);
            float* ap = g_agg + (size_t)dj * 128 + tc * 8;
#pragma unroll
            for (int j = 0; j < 8; ++j) atomicAdd(ap + j, o[j]);
        }
    }
}

// ---------------------------------------------------------------------------
// Node kernel: 64 nodes/block, 128 threads, 2 blocks/SM
// ---------------------------------------------------------------------------
__global__ __launch_bounds__(NTHREADS)
void node_kernel(const float* __restrict__ x,
                 const float* __restrict__ b1, const float* __restrict__ b2,
                 const float* __restrict__ b3,
                 const float* __restrict__ gw, const float* __restrict__ bw,
                 float* __restrict__ out_x) {
    extern __shared__ char sm[];
    const u32 smb = smem_u32(sm);
    const int tid = threadIdx.x, wid = tid >> 5, lane = tid & 31;
    const int mbase = (wid >> 1) * 32, nbase = (wid & 1) * 64;
    const int n0 = blockIdx.x * MROWS;

    float acc[2][8][4];
#pragma unroll
    for (int mg = 0; mg < 2; ++mg)
#pragma unroll
        for (int ng = 0; ng < 8; ++ng)
#pragma unroll
            for (int k = 0; k < 4; ++k) acc[mg][ng][k] = 0.f;

    fill_half(smb + SM_BB0, g_wn, tid);       CP_COMMIT();
    fill_half(smb + SM_BB1, g_wn + HB, tid);  CP_COMMIT();

    // gather A(0) = x
    {
        const int row = tid >> 1, qb = (tid & 1) * 16;
        const int g = n0 + row;
#pragma unroll 4
        for (int i = 0; i < 16; ++i) {
            float4 v = make_float4(0.f, 0.f, 0.f, 0.f);
            if (g < NN) v = __ldg((const float4*)x + (size_t)g * 32 + qb + i);
            u64 hi, lo;
            split4(v.x, v.y, v.z, v.w, hi, lo);
            *(u64*)(sm + SM_AHI + row * ROWB + (qb + i) * 8) = hi;
            *(u64*)(sm + SM_ALO + row * ROWB + (qb + i) * 8) = lo;
        }
    }

    // 4 chunks = 8 half-steps
#pragma unroll 1
    for (int t = 0; t < 8; ++t) {
        const u32 bbuf = smb + SM_BB0 + (u32)(t & 1) * HB;
        CP_WAIT(1);
        __syncthreads();
        if (t & 1) mma_odd(smb, bbuf, acc, mbase, nbase, lane);
        else       mma_even(smb, bbuf, acc, mbase, nbase, lane);
        __syncthreads();
        if (t + 2 < 8) {
            fill_half(bbuf, g_wn + (size_t)(t + 2) * HB, tid);
            CP_COMMIT();
        }
        if (t & 1) {
            const int s = t >> 1;
            if (s == 0) {
                // gather A(1) = agg
                const int row = tid >> 1, qb = (tid & 1) * 16;
                const int g = n0 + row;
#pragma unroll 4
                for (int i = 0; i < 16; ++i) {
                    float4 v = make_float4(0.f, 0.f, 0.f, 0.f);
                    if (g < NN) v = __ldg((const float4*)g_agg + (size_t)g * 32 + qb + i);
                    u64 hi, lo;
                    split4(v.x, v.y, v.z, v.w, hi, lo);
                    *(u64*)(sm + SM_AHI + row * ROWB + (qb + i) * 8) = hi;
                    *(u64*)(sm + SM_ALO + row * ROWB + (qb + i) * 8) = lo;
                }
            } else if (s == 1) {
                mid_epi(sm, acc, b1, mbase, nbase, lane);
            } else if (s == 2) {
                mid_epi(sm, acc, b2, mbase, nbase, lane);
            }
        }
    }

    final_dump(sm, acc, b3, mbase, nbase, lane);
    __syncthreads();
    ln_stats(sm, tid);
    __syncthreads();

    {
        const int tc = tid & 15, tr = tid >> 4;
        const float* sv = (const float*)sm;
        const float* smean = (const float*)(sm + SM_BB0);
        const float* srstd = (const float*)(sm + SM_BB0 + 256);
        float gv[8], bv[8];
#pragma unroll
        for (int j = 0; j < 8; ++j) {
            gv[j] = __ldg(gw + tc * 8 + j);
            bv[j] = __ldg(bw + tc * 8 + j);
        }
        for (int r8 = 0; r8 < 8; ++r8) {
            const int row = r8 * 8 + tr;
            const long long gr = n0 + row;
            if (gr < NN) {
                const float mean = smean[row], rstd = srstd[row];
                float4 ra = __ldg((const float4*)x + gr * 32 + tc * 2);
                float4 rb = __ldg((const float4*)x + gr * 32 + tc * 2 + 1);
                float o[8];
#pragma unroll
                for (int j = 0; j < 8; ++j)
                    o[j] = (sv[row * SVS + tc * 8 + j] - mean) * rstd * gv[j] + bv[j];
                o[0] += ra.x; o[1] += ra.y; o[2] += ra.z; o[3] += ra.w;
                o[4] += rb.x; o[5] += rb.y; o[6] += rb.z; o[7] += rb.w;
                ((float4*)out_x)[gr * 32 + tc * 2]     = make_float4(o[0], o[1], o[2], o[3]);
                ((float4*)out_x)[gr * 32 + tc * 2 + 1] = make_float4(o[4], o[5], o[6], o[7]);
            }
        }
    }
}

// ---------------------------------------------------------------------------
// Weight prep: split into bf16 hi/lo, transpose to [n][k], row stride 272B.
// ---------------------------------------------------------------------------
__global__ void prep_w(const float* __restrict__ ew1, const float* __restrict__ ew2,
                       const float* __restrict__ ew3, const float* __restrict__ nw1,
                       const float* __restrict__ nw2, const float* __restrict__ nw3) {
    int i = blockIdx.x * blockDim.x + threadIdx.x;
    if (i >= 9 * 16384) return;
    unsigned char* dst;
    float val;
    int cs = i >> 14, r = i & 16383;
    int kl = r >> 7, n = r & 127;
    if (cs < 5) {
        if (cs < 3)       val = ew1[(cs * 128 + kl) * 128 + n];
        else if (cs == 3) val = ew2[kl * 128 + n];
        else              val = ew3[kl * 128 + n];
        dst = g_we + (size_t)cs * WCHUNK;
    } else {
        int ns = cs - 5;
        if (ns < 2)       val = nw1[(ns * 128 + kl) * 128 + n];
        else if (ns == 2) val = nw2[kl * 128 + n];
        else              val = nw3[kl * 128 + n];
        dst = g_wn + (size_t)ns * WCHUNK;
    }
    u32 h = pack_bf16x2(val, 0.f);
    u32 l = pack_bf16x2(val - bf_lo_f(h), 0.f);
    *(unsigned short*)(dst + n * ROWB + kl * 2)      = (unsigned short)(h & 0xffff);
    *(unsigned short*)(dst + HB + n * ROWB + kl * 2) = (unsigned short)(l & 0xffff);
}

__global__ void zero_agg_kernel() {
    int i = blockIdx.x * blockDim.x + threadIdx.x;
    if (i < NN * 32)
        ((float4*)g_agg)[i] = make_float4(0.f, 0.f, 0.f, 0.f);
}

// ---------------------------------------------------------------------------
extern "C" void kernel_launch(void* const* d_in, const int* in_sizes, int n_in,
                              void* d_out, int out_size) {
    const float* x    = (const float*)d_in[0];
    const int*   eidx = (const int*)d_in[1];
    const float* ea   = (const float*)d_in[2];
    const float* ew1  = (const float*)d_in[3];
    const float* eb1  = (const float*)d_in[4];
    const float* ew2  = (const float*)d_in[5];
    const float* eb2  = (const float*)d_in[6];
    const float* ew3  = (const float*)d_in[7];
    const float* eb3  = (const float*)d_in[8];
    const float* eg   = (const float*)d_in[9];
    const float* ebt  = (const float*)d_in[10];
    const float* nw1  = (const float*)d_in[11];
    const float* nb1  = (const float*)d_in[12];
    const float* nw2  = (const float*)d_in[13];
    const float* nb2  = (const float*)d_in[14];
    const float* nw3  = (const float*)d_in[15];
    const float* nb3  = (const float*)d_in[16];
    const float* ng   = (const float*)d_in[17];
    const float* nbt  = (const float*)d_in[18];

    float* out_x = (float*)d_out;                       // [50000, 128]
    float* out_e = (float*)d_out + (size_t)NN * 128;    // [800000, 128]

    cudaFuncSetAttribute(edge_kernel, cudaFuncAttributeMaxDynamicSharedMemorySize, SM_BYTES);
    cudaFuncSetAttribute(node_kernel, cudaFuncAttributeMaxDynamicSharedMemorySize, SM_BYTES);

    zero_agg_kernel<<<(NN * 32 + 255) / 256, 256>>>();
    prep_w<<<(9 * 16384 + 255) / 256, 256>>>(ew1, ew2, ew3, nw1, nw2, nw3);
    edge_kernel<<<NE / MROWS, NTHREADS, SM_BYTES>>>(x, eidx, ea, eb1, eb2, eb3, eg, ebt, out_e);
    node_kernel<<<(NN + MROWS - 1) / MROWS, NTHREADS, SM_BYTES>>>(x, nb1, nb2, nb3, ng, nbt, out_x);
}

// round 10
// speedup vs baseline: 1.1616x; 1.1200x over previous
#include <cuda_runtime.h>

#define NN 50000
#define NE 800000

typedef unsigned int u32;
typedef unsigned long long u64;

// ---------------------------------------------------------------------------
// Device scratch (no cudaMalloc allowed)
// ---------------------------------------------------------------------------
__device__ float g_agg[(size_t)NN * 128];
// Pre-split bf16 weights, transposed to [n][k], row stride 272B.
// Chunk = [hi 34816][lo 34816]; halves are consecutive 34816-byte blocks.
#define HB 34816
#define WCHUNK (2 * HB)
__device__ __align__(16) unsigned char g_we[5 * WCHUNK]; // edge: L1 x3, L2, L3
__device__ __align__(16) unsigned char g_wn[4 * WCHUNK]; // node: L1 x2, L2, L3

// ---------------------------------------------------------------------------
// SMEM: A_hi, A_lo (64 rows), two B half-buffers (128 rows each).
// ---------------------------------------------------------------------------
#define ROWB 272
#define SM_AHI 0
#define SM_ALO 17408             // 64*272
#define SM_BB0 34816
#define SM_BB1 (34816 + HB)      // 69632
#define SM_BYTES (34816 + 2 * HB) // 104448  -> 2 blocks/SM

#define MROWS 64
#define NTHREADS 128

// ---------------------------------------------------------------------------
// Helpers
// ---------------------------------------------------------------------------
__device__ __forceinline__ u32 smem_u32(const void* p) {
    u32 a;
    asm("{ .reg .u64 t; cvta.to.shared.u64 t, %1; cvt.u32.u64 %0, t; }"
        : "=r"(a) : "l"(p));
    return a;
}
__device__ __forceinline__ u32 pack_bf16x2(float e0, float e1) {
    u32 r;
    asm("cvt.rn.bf16x2.f32 %0, %1, %2;" : "=r"(r) : "f"(e1), "f"(e0));
    return r;
}
__device__ __forceinline__ float bf_lo_f(u32 p) { return __uint_as_float(p << 16); }
__device__ __forceinline__ float bf_hi_f(u32 p) { return __uint_as_float(p & 0xffff0000u); }
__device__ __forceinline__ float silu_f(float v) { return __fdividef(v, 1.0f + __expf(-v)); }

__device__ __forceinline__ void ldsm4(u32& r0, u32& r1, u32& r2, u32& r3, u32 addr) {
    asm volatile("ldmatrix.sync.aligned.m8n8.x4.shared.b16 {%0,%1,%2,%3}, [%4];"
                 : "=r"(r0), "=r"(r1), "=r"(r2), "=r"(r3) : "r"(addr));
}
__device__ __forceinline__ void mma16816(float* c, const u32* a, u32 b0, u32 b1) {
    asm volatile(
        "mma.sync.aligned.m16n8k16.row.col.f32.bf16.bf16.f32 "
        "{%0,%1,%2,%3}, {%4,%5,%6,%7}, {%8,%9}, {%0,%1,%2,%3};"
        : "+f"(c[0]), "+f"(c[1]), "+f"(c[2]), "+f"(c[3])
        : "r"(a[0]), "r"(a[1]), "r"(a[2]), "r"(a[3]), "r"(b0), "r"(b1));
}
__device__ __forceinline__ void split4(float v0, float v1, float v2, float v3,
                                       u64& hi, u64& lo) {
    u32 h0 = pack_bf16x2(v0, v1), h1 = pack_bf16x2(v2, v3);
    u32 l0 = pack_bf16x2(v0 - bf_lo_f(h0), v1 - bf_hi_f(h0));
    u32 l1 = pack_bf16x2(v2 - bf_lo_f(h1), v3 - bf_hi_f(h1));
    hi = (u64)h0 | ((u64)h1 << 32);
    lo = (u64)l0 | ((u64)l1 << 32);
}

// ---- register gather prefetch (16 float4 per thread, held across MMA) ----
__device__ __forceinline__ void issue_gather(float4* pre, const float4* src,
                                             long long g, int qb) {
#pragma unroll
    for (int i = 0; i < 16; ++i)
        pre[i] = __ldg(src + g * 32 + qb + i);
}
__device__ __forceinline__ void issue_gather_guard(float4* pre, const float4* src,
                                                   int g, int qb) {
#pragma unroll
    for (int i = 0; i < 16; ++i) {
        float4 v = make_float4(0.f, 0.f, 0.f, 0.f);
        if (g < NN) v = __ldg(src + (size_t)g * 32 + qb + i);
        pre[i] = v;
    }
}
__device__ __forceinline__ void convert_gather(char* sm, const float4* pre,
                                               int row, int qb) {
#pragma unroll
    for (int i = 0; i < 16; ++i) {
        u64 hi, lo;
        split4(pre[i].x, pre[i].y, pre[i].z, pre[i].w, hi, lo);
        *(u64*)(sm + SM_AHI + row * ROWB + (qb + i) * 8) = hi;
        *(u64*)(sm + SM_ALO + row * ROWB + (qb + i) * 8) = lo;
    }
}

// ---- cp.async ----
__device__ __forceinline__ void cp16(u32 dst, const void* src) {
    asm volatile("cp.async.cg.shared.global [%0], [%1], 16;" :: "r"(dst), "l"(src));
}
#define CP_COMMIT() asm volatile("cp.async.commit_group;" ::: "memory")
#define CP_WAIT(n)  asm volatile("cp.async.wait_group %0;" :: "n"(n) : "memory")

// Prefetch one 34816-B weight half (2176 x 16B, 128 threads -> 17 each).
__device__ __forceinline__ void fill_half(u32 dst, const unsigned char* w, int tid) {
#pragma unroll
    for (int i = 0; i < 17; ++i) {
        int t = tid + i * NTHREADS;
        cp16(dst + t * 16, w + t * 16);
    }
}

// ---------------------------------------------------------------------------
// MMA halves over one 128-K chunk. Warp tile 32x64. acc[2][8][4].
// even: hh + lh on B-hi half. odd: hl on B-lo half.
// ---------------------------------------------------------------------------
__device__ __forceinline__ void mma_even(u32 smb, u32 bbuf, float acc[2][8][4],
                                         int mbase, int nbase, int lane) {
    const u32 a_off = (u32)(mbase + (lane & 15)) * ROWB + (u32)(lane >> 4) * 16;
    const u32 b_off = (u32)(nbase + (lane & 7) + ((lane >> 4) & 1) * 8) * ROWB
                    + (u32)((lane >> 3) & 1) * 16;
#pragma unroll
    for (int ks = 0; ks < 8; ++ks) {
        const u32 kb = (u32)ks * 32;
        u32 ah[2][4], al[2][4], b[4][4];
#pragma unroll
        for (int mg = 0; mg < 2; ++mg)
            ldsm4(ah[mg][0], ah[mg][1], ah[mg][2], ah[mg][3],
                  smb + SM_AHI + a_off + (u32)mg * (16 * ROWB) + kb);
#pragma unroll
        for (int g = 0; g < 4; ++g)
            ldsm4(b[g][0], b[g][1], b[g][2], b[g][3],
                  bbuf + b_off + (u32)g * (16 * ROWB) + kb);
#pragma unroll
        for (int mg = 0; mg < 2; ++mg)
#pragma unroll
            for (int ng = 0; ng < 8; ++ng)
                mma16816(acc[mg][ng], ah[mg], b[ng >> 1][(ng & 1) * 2], b[ng >> 1][(ng & 1) * 2 + 1]);
#pragma unroll
        for (int mg = 0; mg < 2; ++mg)
            ldsm4(al[mg][0], al[mg][1], al[mg][2], al[mg][3],
                  smb + SM_ALO + a_off + (u32)mg * (16 * ROWB) + kb);
#pragma unroll
        for (int mg = 0; mg < 2; ++mg)
#pragma unroll
            for (int ng = 0; ng < 8; ++ng)
                mma16816(acc[mg][ng], al[mg], b[ng >> 1][(ng & 1) * 2], b[ng >> 1][(ng & 1) * 2 + 1]);
    }
}

__device__ __forceinline__ void mma_odd(u32 smb, u32 bbuf, float acc[2][8][4],
                                        int mbase, int nbase, int lane) {
    const u32 a_off = (u32)(mbase + (lane & 15)) * ROWB + (u32)(lane >> 4) * 16;
    const u32 b_off = (u32)(nbase + (lane & 7) + ((lane >> 4) & 1) * 8) * ROWB
                    + (u32)((lane >> 3) & 1) * 16;
#pragma unroll
    for (int ks = 0; ks < 8; ++ks) {
        const u32 kb = (u32)ks * 32;
        u32 ah[2][4], b[4][4];
#pragma unroll
        for (int mg = 0; mg < 2; ++mg)
            ldsm4(ah[mg][0], ah[mg][1], ah[mg][2], ah[mg][3],
                  smb + SM_AHI + a_off + (u32)mg * (16 * ROWB) + kb);
#pragma unroll
        for (int g = 0; g < 4; ++g)
            ldsm4(b[g][0], b[g][1], b[g][2], b[g][3],
                  bbuf + b_off + (u32)g * (16 * ROWB) + kb);
#pragma unroll
        for (int mg = 0; mg < 2; ++mg)
#pragma unroll
            for (int ng = 0; ng < 8; ++ng)
                mma16816(acc[mg][ng], ah[mg], b[ng >> 1][(ng & 1) * 2], b[ng >> 1][(ng & 1) * 2 + 1]);
    }
}

// bias + SiLU from acc -> A smem (hi/lo), zero acc
__device__ __forceinline__ void mid_epi(char* sm, float acc[2][8][4],
                                        const float* __restrict__ bias,
                                        int mbase, int nbase, int lane) {
    const int q = lane & 3, r = lane >> 2;
#pragma unroll
    for (int mg = 0; mg < 2; ++mg) {
#pragma unroll
        for (int ng = 0; ng < 8; ++ng) {
            const int col = nbase + ng * 8 + q * 2;
            const float bx = __ldg(bias + col), by = __ldg(bias + col + 1);
            const int r0 = mbase + mg * 16 + r, r1 = r0 + 8;
            float v0 = silu_f(acc[mg][ng][0] + bx);
            float v1 = silu_f(acc[mg][ng][1] + by);
            float v2 = silu_f(acc[mg][ng][2] + bx);
            float v3 = silu_f(acc[mg][ng][3] + by);
            u32 h0 = pack_bf16x2(v0, v1);
            u32 l0 = pack_bf16x2(v0 - bf_lo_f(h0), v1 - bf_hi_f(h0));
            u32 h1 = pack_bf16x2(v2, v3);
            u32 l1 = pack_bf16x2(v2 - bf_lo_f(h1), v3 - bf_hi_f(h1));
            *(u32*)(sm + SM_AHI + r0 * ROWB + col * 2) = h0;
            *(u32*)(sm + SM_ALO + r0 * ROWB + col * 2) = l0;
            *(u32*)(sm + SM_AHI + r1 * ROWB + col * 2) = h1;
            *(u32*)(sm + SM_ALO + r1 * ROWB + col * 2) = l1;
            acc[mg][ng][0] = 0.f; acc[mg][ng][1] = 0.f;
            acc[mg][ng][2] = 0.f; acc[mg][ng][3] = 0.f;
        }
    }
}

#define SVS 130  // float scratch stride; 64*130*4 = 33280 <= A region

__device__ __forceinline__ void final_dump(char* sm, float acc[2][8][4],
                                           const float* __restrict__ b3,
                                           int mbase, int nbase, int lane) {
    float* sv = (float*)sm;
    const int q = lane & 3, r = lane >> 2;
#pragma unroll
    for (int mg = 0; mg < 2; ++mg) {
#pragma unroll
        for (int ng = 0; ng < 8; ++ng) {
            const int col = nbase + ng * 8 + q * 2;
            const float bx = __ldg(b3 + col), by = __ldg(b3 + col + 1);
            const int r0 = mbase + mg * 16 + r, r1 = r0 + 8;
            *(float2*)(sv + r0 * SVS + col) = make_float2(acc[mg][ng][0] + bx, acc[mg][ng][1] + by);
            *(float2*)(sv + r1 * SVS + col) = make_float2(acc[mg][ng][2] + bx, acc[mg][ng][3] + by);
        }
    }
}

// per-row mean/rstd; stats in B0 region (dead by then)
__device__ __forceinline__ void ln_stats(char* sm, int tid) {
    if (tid < MROWS) {
        const float* sv = (float*)sm;
        float s1 = 0.f, s2 = 0.f;
#pragma unroll 16
        for (int c = 0; c < 128; c += 2) {
            float2 v = *(const float2*)(sv + tid * SVS + c);
            s1 += v.x + v.y;
            s2 += v.x * v.x + v.y * v.y;
        }
        float mean = s1 * (1.0f / 128.0f);
        float var = s2 * (1.0f / 128.0f) - mean * mean;
        ((float*)(sm + SM_BB0))[tid] = mean;
        ((float*)(sm + SM_BB0 + 256))[tid] = rsqrtf(var + 1e-5f);
    }
}

// ---------------------------------------------------------------------------
// Edge kernel: 64 edges/block, 128 threads (4 warps), 2 blocks/SM
// ---------------------------------------------------------------------------
__global__ __launch_bounds__(NTHREADS)
void edge_kernel(const float* __restrict__ x, const int* __restrict__ eidx,
                 const float* __restrict__ ea,
                 const float* __restrict__ b1, const float* __restrict__ b2,
                 const float* __restrict__ b3,
                 const float* __restrict__ gw, const float* __restrict__ bw,
                 float* __restrict__ out_e) {
    extern __shared__ char sm[];
    const u32 smb = smem_u32(sm);
    const int tid = threadIdx.x, wid = tid >> 5, lane = tid & 31;
    const int mbase = (wid >> 1) * 32, nbase = (wid & 1) * 64;
    const int e0 = blockIdx.x * MROWS;
    const int grow = tid >> 1, gqb = (tid & 1) * 16;  // gather mapping

    float acc[2][8][4];
#pragma unroll
    for (int mg = 0; mg < 2; ++mg)
#pragma unroll
        for (int ng = 0; ng < 8; ++ng)
#pragma unroll
            for (int k = 0; k < 4; ++k) acc[mg][ng][k] = 0.f;

    // prologue: prefetch first two weight halves
    fill_half(smb + SM_BB0, g_we, tid);       CP_COMMIT();
    fill_half(smb + SM_BB1, g_we + HB, tid);  CP_COMMIT();

    float4 pre[16];
    // gather A(0) = x[i], convert immediately
    issue_gather(pre, (const float4*)x, (long long)__ldg(eidx + e0 + grow), gqb);
    convert_gather(sm, pre, grow, gqb);
    // early-issue A(1) = x[j]; held in regs across chunk-0 MMA
    issue_gather(pre, (const float4*)x, (long long)__ldg(eidx + NE + e0 + grow), gqb);

    // 5 chunks = 10 half-steps
#pragma unroll 1
    for (int t = 0; t < 10; ++t) {
        const u32 bbuf = smb + SM_BB0 + (u32)(t & 1) * HB;
        CP_WAIT(1);
        __syncthreads();
        if (t & 1) mma_odd(smb, bbuf, acc, mbase, nbase, lane);
        else       mma_even(smb, bbuf, acc, mbase, nbase, lane);
        __syncthreads();
        if (t + 2 < 10) {
            fill_half(bbuf, g_we + (size_t)(t + 2) * HB, tid);
            CP_COMMIT();
        }
        if (t & 1) {
            const int s = t >> 1;
            if (s < 2) {
                // convert held regs into A smem (chunk s+1)
                convert_gather(sm, pre, grow, gqb);
                if (s == 0) {
                    // early-issue A(2) = edge_attr; held across chunk-1 MMA
                    issue_gather(pre, (const float4*)ea, (long long)(e0 + grow), gqb);
                }
            } else if (s == 2) {
                mid_epi(sm, acc, b1, mbase, nbase, lane);
            } else if (s == 3) {
                mid_epi(sm, acc, b2, mbase, nbase, lane);
            }
        }
    }

    // ---- final: bias3 -> LN -> residual -> store + scatter ----
    final_dump(sm, acc, b3, mbase, nbase, lane);
    __syncthreads();
    ln_stats(sm, tid);
    __syncthreads();

    {
        const int tc = tid & 15, tr = tid >> 4;   // tr 0..7
        const float* sv = (const float*)sm;
        const float* smean = (const float*)(sm + SM_BB0);
        const float* srstd = (const float*)(sm + SM_BB0 + 256);
        float gv[8], bv[8];
#pragma unroll
        for (int j = 0; j < 8; ++j) {
            gv[j] = __ldg(gw + tc * 8 + j);
            bv[j] = __ldg(bw + tc * 8 + j);
        }
        // 128 threads x 8 iters: rows 0..63, 16 col-groups
        for (int r8 = 0; r8 < 8; ++r8) {
            const int row = r8 * 8 + tr;
            const long long gr = e0 + row;
            const float mean = smean[row], rstd = srstd[row];
            float4 ra = __ldg((const float4*)ea + gr * 32 + tc * 2);
            float4 rb = __ldg((const float4*)ea + gr * 32 + tc * 2 + 1);
            float o[8];
#pragma unroll
            for (int j = 0; j < 8; ++j)
                o[j] = (sv[row * SVS + tc * 8 + j] - mean) * rstd * gv[j] + bv[j];
            o[0] += ra.x; o[1] += ra.y; o[2] += ra.z; o[3] += ra.w;
            o[4] += rb.x; o[5] += rb.y; o[6] += rb.z; o[7] += rb.w;
            ((float4*)out_e)[gr * 32 + tc * 2]     = make_float4(o[0], o[1], o[2], o[3]);
            ((float4*)out_e)[gr * 32 + tc * 2 + 1] = make_float4(o[4], o[5], o[6], o[7]);
            const int dj = __ldg(eidx + NE + gr);
            float* ap = g_agg + (size_t)dj * 128 + tc * 8;
#pragma unroll
            for (int j = 0; j < 8; ++j) atomicAdd(ap + j, o[j]);
        }
    }
}

// ---------------------------------------------------------------------------
// Node kernel: 64 nodes/block, 128 threads, 2 blocks/SM
// ---------------------------------------------------------------------------
__global__ __launch_bounds__(NTHREADS)
void node_kernel(const float* __restrict__ x,
                 const float* __restrict__ b1, const float* __restrict__ b2,
                 const float* __restrict__ b3,
                 const float* __restrict__ gw, const float* __restrict__ bw,
                 float* __restrict__ out_x) {
    extern __shared__ char sm[];
    const u32 smb = smem_u32(sm);
    const int tid = threadIdx.x, wid = tid >> 5, lane = tid & 31;
    const int mbase = (wid >> 1) * 32, nbase = (wid & 1) * 64;
    const int n0 = blockIdx.x * MROWS;
    const int grow = tid >> 1, gqb = (tid & 1) * 16;

    float acc[2][8][4];
#pragma unroll
    for (int mg = 0; mg < 2; ++mg)
#pragma unroll
        for (int ng = 0; ng < 8; ++ng)
#pragma unroll
            for (int k = 0; k < 4; ++k) acc[mg][ng][k] = 0.f;

    fill_half(smb + SM_BB0, g_wn, tid);       CP_COMMIT();
    fill_half(smb + SM_BB1, g_wn + HB, tid);  CP_COMMIT();

    float4 pre[16];
    // gather A(0) = x, convert immediately
    issue_gather_guard(pre, (const float4*)x, n0 + grow, gqb);
    convert_gather(sm, pre, grow, gqb);
    // early-issue A(1) = agg
    issue_gather_guard(pre, (const float4*)g_agg, n0 + grow, gqb);

    // 4 chunks = 8 half-steps
#pragma unroll 1
    for (int t = 0; t < 8; ++t) {
        const u32 bbuf = smb + SM_BB0 + (u32)(t & 1) * HB;
        CP_WAIT(1);
        __syncthreads();
        if (t & 1) mma_odd(smb, bbuf, acc, mbase, nbase, lane);
        else       mma_even(smb, bbuf, acc, mbase, nbase, lane);
        __syncthreads();
        if (t + 2 < 8) {
            fill_half(bbuf, g_wn + (size_t)(t + 2) * HB, tid);
            CP_COMMIT();
        }
        if (t & 1) {
            const int s = t >> 1;
            if (s == 0) {
                convert_gather(sm, pre, grow, gqb);
            } else if (s == 1) {
                mid_epi(sm, acc, b1, mbase, nbase, lane);
            } else if (s == 2) {
                mid_epi(sm, acc, b2, mbase, nbase, lane);
            }
        }
    }

    final_dump(sm, acc, b3, mbase, nbase, lane);
    __syncthreads();
    ln_stats(sm, tid);
    __syncthreads();

    {
        const int tc = tid & 15, tr = tid >> 4;
        const float* sv = (const float*)sm;
        const float* smean = (const float*)(sm + SM_BB0);
        const float* srstd = (const float*)(sm + SM_BB0 + 256);
        float gv[8], bv[8];
#pragma unroll
        for (int j = 0; j < 8; ++j) {
            gv[j] = __ldg(gw + tc * 8 + j);
            bv[j] = __ldg(bw + tc * 8 + j);
        }
        for (int r8 = 0; r8 < 8; ++r8) {
            const int row = r8 * 8 + tr;
            const long long gr = n0 + row;
            if (gr < NN) {
                const float mean = smean[row], rstd = srstd[row];
                float4 ra = __ldg((const float4*)x + gr * 32 + tc * 2);
                float4 rb = __ldg((const float4*)x + gr * 32 + tc * 2 + 1);
                float o[8];
#pragma unroll
                for (int j = 0; j < 8; ++j)
                    o[j] = (sv[row * SVS + tc * 8 + j] - mean) * rstd * gv[j] + bv[j];
                o[0] += ra.x; o[1] += ra.y; o[2] += ra.z; o[3] += ra.w;
                o[4] += rb.x; o[5] += rb.y; o[6] += rb.z; o[7] += rb.w;
                ((float4*)out_x)[gr * 32 + tc * 2]     = make_float4(o[0], o[1], o[2], o[3]);
                ((float4*)out_x)[gr * 32 + tc * 2 + 1] = make_float4(o[4], o[5], o[6], o[7]);
            }
        }
    }
}

// ---------------------------------------------------------------------------
// Weight prep: split into bf16 hi/lo, transpose to [n][k], row stride 272B.
// ---------------------------------------------------------------------------
__global__ void prep_w(const float* __restrict__ ew1, const float* __restrict__ ew2,
                       const float* __restrict__ ew3, const float* __restrict__ nw1,
                       const float* __restrict__ nw2, const float* __restrict__ nw3) {
    int i = blockIdx.x * blockDim.x + threadIdx.x;
    if (i >= 9 * 16384) return;
    unsigned char* dst;
    float val;
    int cs = i >> 14, r = i & 16383;
    int kl = r >> 7, n = r & 127;
    if (cs < 5) {
        if (cs < 3)       val = ew1[(cs * 128 + kl) * 128 + n];
        else if (cs == 3) val = ew2[kl * 128 + n];
        else              val = ew3[kl * 128 + n];
        dst = g_we + (size_t)cs * WCHUNK;
    } else {
        int ns = cs - 5;
        if (ns < 2)       val = nw1[(ns * 128 + kl) * 128 + n];
        else if (ns == 2) val = nw2[kl * 128 + n];
        else              val = nw3[kl * 128 + n];
        dst = g_wn + (size_t)ns * WCHUNK;
    }
    u32 h = pack_bf16x2(val, 0.f);
    u32 l = pack_bf16x2(val - bf_lo_f(h), 0.f);
    *(unsigned short*)(dst + n * ROWB + kl * 2)      = (unsigned short)(h & 0xffff);
    *(unsigned short*)(dst + HB + n * ROWB + kl * 2) = (unsigned short)(l & 0xffff);
}

__global__ void zero_agg_kernel() {
    int i = blockIdx.x * blockDim.x + threadIdx.x;
    if (i < NN * 32)
        ((float4*)g_agg)[i] = make_float4(0.f, 0.f, 0.f, 0.f);
}

// ---------------------------------------------------------------------------
extern "C" void kernel_launch(void* const* d_in, const int* in_sizes, int n_in,
                              void* d_out, int out_size) {
    const float* x    = (const float*)d_in[0];
    const int*   eidx = (const int*)d_in[1];
    const float* ea   = (const float*)d_in[2];
    const float* ew1  = (const float*)d_in[3];
    const float* eb1  = (const float*)d_in[4];
    const float* ew2  = (const float*)d_in[5];
    const float* eb2  = (const float*)d_in[6];
    const float* ew3  = (const float*)d_in[7];
    const float* eb3  = (const float*)d_in[8];
    const float* eg   = (const float*)d_in[9];
    const float* ebt  = (const float*)d_in[10];
    const float* nw1  = (const float*)d_in[11];
    const float* nb1  = (const float*)d_in[12];
    const float* nw2  = (const float*)d_in[13];
    const float* nb2  = (const float*)d_in[14];
    const float* nw3  = (const float*)d_in[15];
    const float* nb3  = (const float*)d_in[16];
    const float* ng   = (const float*)d_in[17];
    const float* nbt  = (const float*)d_in[18];

    float* out_x = (float*)d_out;                       // [50000, 128]
    float* out_e = (float*)d_out + (size_t)NN * 128;    // [800000, 128]

    cudaFuncSetAttribute(edge_kernel, cudaFuncAttributeMaxDynamicSharedMemorySize, SM_BYTES);
    cudaFuncSetAttribute(node_kernel, cudaFuncAttributeMaxDynamicSharedMemorySize, SM_BYTES);

    zero_agg_kernel<<<(NN * 32 + 255) / 256, 256>>>();
    prep_w<<<(9 * 16384 + 255) / 256, 256>>>(ew1, ew2, ew3, nw1, nw2, nw3);
    edge_kernel<<<NE / MROWS, NTHREADS, SM_BYTES>>>(x, eidx, ea, eb1, eb2, eb3, eg, ebt, out_e);
    node_kernel<<<(NN + MROWS - 1) / MROWS, NTHREADS, SM_BYTES>>>(x, nb1, nb2, nb3, ng, nbt, out_x);
}

// round 11
// speedup vs baseline: 1.2367x; 1.0647x over previous
#include <cuda_runtime.h>

#define NN 50000
#define NE 800000

typedef unsigned int u32;
typedef unsigned long long u64;

// ---------------------------------------------------------------------------
// Device scratch (no cudaMalloc allowed)
// ---------------------------------------------------------------------------
__device__ float g_agg[(size_t)NN * 128];
// Pre-split bf16 weights, transposed to [n][k], row stride 272B.
// Chunk = [hi 34816][lo 34816]; halves are consecutive 34816-byte blocks.
#define HB 34816
#define WCHUNK (2 * HB)
__device__ __align__(16) unsigned char g_we[5 * WCHUNK]; // edge: L1 x3, L2, L3
__device__ __align__(16) unsigned char g_wn[4 * WCHUNK]; // node: L1 x2, L2, L3

// ---------------------------------------------------------------------------
// SMEM: A_hi, A_lo (64 rows), two B half-buffers (128 rows each).
// ---------------------------------------------------------------------------
#define ROWB 272
#define SM_AHI 0
#define SM_ALO 17408             // 64*272
#define SM_BB0 34816
#define SM_BB1 (34816 + HB)      // 69632
#define SM_BYTES (34816 + 2 * HB) // 104448  -> 2 blocks/SM

#define MROWS 64
#define NTHREADS 256

// ---------------------------------------------------------------------------
// Helpers
// ---------------------------------------------------------------------------
__device__ __forceinline__ u32 smem_u32(const void* p) {
    u32 a;
    asm("{ .reg .u64 t; cvta.to.shared.u64 t, %1; cvt.u32.u64 %0, t; }"
        : "=r"(a) : "l"(p));
    return a;
}
__device__ __forceinline__ u32 pack_bf16x2(float e0, float e1) {
    u32 r;
    asm("cvt.rn.bf16x2.f32 %0, %1, %2;" : "=r"(r) : "f"(e1), "f"(e0));
    return r;
}
__device__ __forceinline__ float bf_lo_f(u32 p) { return __uint_as_float(p << 16); }
__device__ __forceinline__ float bf_hi_f(u32 p) { return __uint_as_float(p & 0xffff0000u); }
__device__ __forceinline__ float silu_f(float v) { return __fdividef(v, 1.0f + __expf(-v)); }

__device__ __forceinline__ void ldsm4(u32& r0, u32& r1, u32& r2, u32& r3, u32 addr) {
    asm volatile("ldmatrix.sync.aligned.m8n8.x4.shared.b16 {%0,%1,%2,%3}, [%4];"
                 : "=r"(r0), "=r"(r1), "=r"(r2), "=r"(r3) : "r"(addr));
}
__device__ __forceinline__ void mma16816(float* c, const u32* a, u32 b0, u32 b1) {
    asm volatile(
        "mma.sync.aligned.m16n8k16.row.col.f32.bf16.bf16.f32 "
        "{%0,%1,%2,%3}, {%4,%5,%6,%7}, {%8,%9}, {%0,%1,%2,%3};"
        : "+f"(c[0]), "+f"(c[1]), "+f"(c[2]), "+f"(c[3])
        : "r"(a[0]), "r"(a[1]), "r"(a[2]), "r"(a[3]), "r"(b0), "r"(b1));
}
__device__ __forceinline__ void split4(float v0, float v1, float v2, float v3,
                                       u64& hi, u64& lo) {
    u32 h0 = pack_bf16x2(v0, v1), h1 = pack_bf16x2(v2, v3);
    u32 l0 = pack_bf16x2(v0 - bf_lo_f(h0), v1 - bf_hi_f(h0));
    u32 l1 = pack_bf16x2(v2 - bf_lo_f(h1), v3 - bf_hi_f(h1));
    hi = (u64)h0 | ((u64)h1 << 32);
    lo = (u64)l0 | ((u64)l1 << 32);
}
// vector reduction (sm_90+): 4 floats per instruction, fire-and-forget
__device__ __forceinline__ void red4(float* p, float a, float b, float c, float d) {
    asm volatile("red.global.add.v4.f32 [%0], {%1,%2,%3,%4};"
                 :: "l"(p), "f"(a), "f"(b), "f"(c), "f"(d) : "memory");
}

// ---- register gather prefetch (8 float4 per thread, held across MMA) ----
__device__ __forceinline__ void issue_gather(float4* pre, const float4* src,
                                             long long g, int qb) {
#pragma unroll
    for (int i = 0; i < 8; ++i)
        pre[i] = __ldg(src + g * 32 + qb + i);
}
__device__ __forceinline__ void issue_gather_guard(float4* pre, const float4* src,
                                                   int g, int qb) {
#pragma unroll
    for (int i = 0; i < 8; ++i) {
        float4 v = make_float4(0.f, 0.f, 0.f, 0.f);
        if (g < NN) v = __ldg(src + (size_t)g * 32 + qb + i);
        pre[i] = v;
    }
}
__device__ __forceinline__ void convert_gather(char* sm, const float4* pre,
                                               int row, int qb) {
#pragma unroll
    for (int i = 0; i < 8; ++i) {
        u64 hi, lo;
        split4(pre[i].x, pre[i].y, pre[i].z, pre[i].w, hi, lo);
        *(u64*)(sm + SM_AHI + row * ROWB + (qb + i) * 8) = hi;
        *(u64*)(sm + SM_ALO + row * ROWB + (qb + i) * 8) = lo;
    }
}

// ---- cp.async ----
__device__ __forceinline__ void cp16(u32 dst, const void* src) {
    asm volatile("cp.async.cg.shared.global [%0], [%1], 16;" :: "r"(dst), "l"(src));
}
#define CP_COMMIT() asm volatile("cp.async.commit_group;" ::: "memory")
#define CP_WAIT(n)  asm volatile("cp.async.wait_group %0;" :: "n"(n) : "memory")

// Prefetch one 34816-B weight half (2176 x 16B, 256 threads).
__device__ __forceinline__ void fill_half(u32 dst, const unsigned char* w, int tid) {
#pragma unroll
    for (int i = 0; i < 9; ++i) {
        int t = tid + i * NTHREADS;
        if (t < HB / 16) cp16(dst + t * 16, w + t * 16);
    }
}

// ---------------------------------------------------------------------------
// MMA halves over one 128-K chunk. Warp tile 16x64. acc[8][4].
// even: hh + lh on B-hi half. odd: hl on B-lo half.
// ---------------------------------------------------------------------------
__device__ __forceinline__ void mma_even(u32 smb, u32 bbuf, float acc[8][4],
                                         int mbase, int nbase, int lane) {
    const u32 a_off = (u32)(mbase + (lane & 15)) * ROWB + (u32)(lane >> 4) * 16;
    const u32 b_off = (u32)(nbase + (lane & 7) + ((lane >> 4) & 1) * 8) * ROWB
                    + (u32)((lane >> 3) & 1) * 16;
#pragma unroll
    for (int ks = 0; ks < 8; ++ks) {
        const u32 kb = (u32)ks * 32;
        u32 ah[4], al[4], b[4][4];
        ldsm4(ah[0], ah[1], ah[2], ah[3], smb + SM_AHI + a_off + kb);
#pragma unroll
        for (int g = 0; g < 4; ++g)
            ldsm4(b[g][0], b[g][1], b[g][2], b[g][3],
                  bbuf + b_off + (u32)g * (16 * ROWB) + kb);
#pragma unroll
        for (int ng = 0; ng < 8; ++ng)
            mma16816(acc[ng], ah, b[ng >> 1][(ng & 1) * 2], b[ng >> 1][(ng & 1) * 2 + 1]);
        ldsm4(al[0], al[1], al[2], al[3], smb + SM_ALO + a_off + kb);
#pragma unroll
        for (int ng = 0; ng < 8; ++ng)
            mma16816(acc[ng], al, b[ng >> 1][(ng & 1) * 2], b[ng >> 1][(ng & 1) * 2 + 1]);
    }
}

__device__ __forceinline__ void mma_odd(u32 smb, u32 bbuf, float acc[8][4],
                                        int mbase, int nbase, int lane) {
    const u32 a_off = (u32)(mbase + (lane & 15)) * ROWB + (u32)(lane >> 4) * 16;
    const u32 b_off = (u32)(nbase + (lane & 7) + ((lane >> 4) & 1) * 8) * ROWB
                    + (u32)((lane >> 3) & 1) * 16;
#pragma unroll
    for (int ks = 0; ks < 8; ++ks) {
        const u32 kb = (u32)ks * 32;
        u32 ah[4], b[4][4];
        ldsm4(ah[0], ah[1], ah[2], ah[3], smb + SM_AHI + a_off + kb);
#pragma unroll
        for (int g = 0; g < 4; ++g)
            ldsm4(b[g][0], b[g][1], b[g][2], b[g][3],
                  bbuf + b_off + (u32)g * (16 * ROWB) + kb);
#pragma unroll
        for (int ng = 0; ng < 8; ++ng)
            mma16816(acc[ng], ah, b[ng >> 1][(ng & 1) * 2], b[ng >> 1][(ng & 1) * 2 + 1]);
    }
}

// bias + SiLU from acc -> A smem (hi/lo), zero acc
__device__ __forceinline__ void mid_epi(char* sm, float acc[8][4],
                                        const float* __restrict__ bias,
                                        int mbase, int nbase, int lane) {
    const int q = lane & 3, r = lane >> 2;
#pragma unroll
    for (int ng = 0; ng < 8; ++ng) {
        const int col = nbase + ng * 8 + q * 2;
        const float bx = __ldg(bias + col), by = __ldg(bias + col + 1);
        const int r0 = mbase + r, r1 = r0 + 8;
        float v0 = silu_f(acc[ng][0] + bx);
        float v1 = silu_f(acc[ng][1] + by);
        float v2 = silu_f(acc[ng][2] + bx);
        float v3 = silu_f(acc[ng][3] + by);
        u32 h0 = pack_bf16x2(v0, v1);
        u32 l0 = pack_bf16x2(v0 - bf_lo_f(h0), v1 - bf_hi_f(h0));
        u32 h1 = pack_bf16x2(v2, v3);
        u32 l1 = pack_bf16x2(v2 - bf_lo_f(h1), v3 - bf_hi_f(h1));
        *(u32*)(sm + SM_AHI + r0 * ROWB + col * 2) = h0;
        *(u32*)(sm + SM_ALO + r0 * ROWB + col * 2) = l0;
        *(u32*)(sm + SM_AHI + r1 * ROWB + col * 2) = h1;
        *(u32*)(sm + SM_ALO + r1 * ROWB + col * 2) = l1;
        acc[ng][0] = 0.f; acc[ng][1] = 0.f;
        acc[ng][2] = 0.f; acc[ng][3] = 0.f;
    }
}

#define SVS 130  // float scratch stride; 64*130*4 = 33280 <= A region

__device__ __forceinline__ void final_dump(char* sm, float acc[8][4],
                                           const float* __restrict__ b3,
                                           int mbase, int nbase, int lane) {
    float* sv = (float*)sm;
    const int q = lane & 3, r = lane >> 2;
#pragma unroll
    for (int ng = 0; ng < 8; ++ng) {
        const int col = nbase + ng * 8 + q * 2;
        const float bx = __ldg(b3 + col), by = __ldg(b3 + col + 1);
        const int r0 = mbase + r, r1 = r0 + 8;
        *(float2*)(sv + r0 * SVS + col) = make_float2(acc[ng][0] + bx, acc[ng][1] + by);
        *(float2*)(sv + r1 * SVS + col) = make_float2(acc[ng][2] + bx, acc[ng][3] + by);
    }
}

// per-row mean/rstd; stats in B0 region (dead by then)
__device__ __forceinline__ void ln_stats(char* sm, int tid) {
    if (tid < MROWS) {
        const float* sv = (float*)sm;
        float s1 = 0.f, s2 = 0.f;
#pragma unroll 16
        for (int c = 0; c < 128; c += 2) {
            float2 v = *(const float2*)(sv + tid * SVS + c);
            s1 += v.x + v.y;
            s2 += v.x * v.x + v.y * v.y;
        }
        float mean = s1 * (1.0f / 128.0f);
        float var = s2 * (1.0f / 128.0f) - mean * mean;
        ((float*)(sm + SM_BB0))[tid] = mean;
        ((float*)(sm + SM_BB0 + 256))[tid] = rsqrtf(var + 1e-5f);
    }
}

// ---------------------------------------------------------------------------
// Edge kernel: 64 edges/block, 256 threads (8 warps), 2 blocks/SM
// ---------------------------------------------------------------------------
__global__ __launch_bounds__(NTHREADS, 2)
void edge_kernel(const float* __restrict__ x, const int* __restrict__ eidx,
                 const float* __restrict__ ea,
                 const float* __restrict__ b1, const float* __restrict__ b2,
                 const float* __restrict__ b3,
                 const float* __restrict__ gw, const float* __restrict__ bw,
                 float* __restrict__ out_e) {
    extern __shared__ char sm[];
    const u32 smb = smem_u32(sm);
    const int tid = threadIdx.x, wid = tid >> 5, lane = tid & 31;
    const int mbase = (wid >> 1) * 16, nbase = (wid & 1) * 64;
    const int e0 = blockIdx.x * MROWS;
    const int grow = tid >> 2, gqb = (tid & 3) * 8;  // gather mapping

    float acc[8][4];
#pragma unroll
    for (int ng = 0; ng < 8; ++ng)
#pragma unroll
        for (int k = 0; k < 4; ++k) acc[ng][k] = 0.f;

    // prologue: prefetch first two weight halves
    fill_half(smb + SM_BB0, g_we, tid);       CP_COMMIT();
    fill_half(smb + SM_BB1, g_we + HB, tid);  CP_COMMIT();

    float4 pre[8];
    // gather A(0) = x[i], convert immediately
    issue_gather(pre, (const float4*)x, (long long)__ldg(eidx + e0 + grow), gqb);
    convert_gather(sm, pre, grow, gqb);
    // early-issue A(1) = x[j]; held in regs across chunk-0 MMA
    issue_gather(pre, (const float4*)x, (long long)__ldg(eidx + NE + e0 + grow), gqb);

    // 5 chunks = 10 half-steps
#pragma unroll 1
    for (int t = 0; t < 10; ++t) {
        const u32 bbuf = smb + SM_BB0 + (u32)(t & 1) * HB;
        CP_WAIT(1);
        __syncthreads();
        if (t & 1) mma_odd(smb, bbuf, acc, mbase, nbase, lane);
        else       mma_even(smb, bbuf, acc, mbase, nbase, lane);
        __syncthreads();
        if (t + 2 < 10) {
            fill_half(bbuf, g_we + (size_t)(t + 2) * HB, tid);
            CP_COMMIT();
        }
        if (t & 1) {
            const int s = t >> 1;
            if (s < 2) {
                convert_gather(sm, pre, grow, gqb);
                if (s == 0) {
                    issue_gather(pre, (const float4*)ea, (long long)(e0 + grow), gqb);
                }
            } else if (s == 2) {
                mid_epi(sm, acc, b1, mbase, nbase, lane);
            } else if (s == 3) {
                mid_epi(sm, acc, b2, mbase, nbase, lane);
            }
        }
    }

    // ---- final: bias3 -> LN -> residual -> store + scatter ----
    final_dump(sm, acc, b3, mbase, nbase, lane);
    __syncthreads();
    ln_stats(sm, tid);
    __syncthreads();

    {
        const int tc = tid & 15, tr = tid >> 4;   // tr 0..15
        const float* sv = (const float*)sm;
        const float* smean = (const float*)(sm + SM_BB0);
        const float* srstd = (const float*)(sm + SM_BB0 + 256);
        float gv[8], bv[8];
#pragma unroll
        for (int j = 0; j < 8; ++j) {
            gv[j] = __ldg(gw + tc * 8 + j);
            bv[j] = __ldg(bw + tc * 8 + j);
        }
        // 256 threads x 4 iters: rows 0..63, 16 col-groups
        for (int r4 = 0; r4 < 4; ++r4) {
            const int row = r4 * 16 + tr;
            const long long gr = e0 + row;
            const float mean = smean[row], rstd = srstd[row];
            float4 ra = __ldg((const float4*)ea + gr * 32 + tc * 2);
            float4 rb = __ldg((const float4*)ea + gr * 32 + tc * 2 + 1);
            float o[8];
#pragma unroll
            for (int j = 0; j < 8; ++j)
                o[j] = (sv[row * SVS + tc * 8 + j] - mean) * rstd * gv[j] + bv[j];
            o[0] += ra.x; o[1] += ra.y; o[2] += ra.z; o[3] += ra.w;
            o[4] += rb.x; o[5] += rb.y; o[6] += rb.z; o[7] += rb.w;
            ((float4*)out_e)[gr * 32 + tc * 2]     = make_float4(o[0], o[1], o[2], o[3]);
            ((float4*)out_e)[gr * 32 + tc * 2 + 1] = make_float4(o[4], o[5], o[6], o[7]);
            const int dj = __ldg(eidx + NE + gr);
            float* ap = g_agg + (size_t)dj * 128 + tc * 8;
            red4(ap,     o[0], o[1], o[2], o[3]);
            red4(ap + 4, o[4], o[5], o[6], o[7]);
        }
    }
}

// ---------------------------------------------------------------------------
// Node kernel: 64 nodes/block, 256 threads, 2 blocks/SM
// ---------------------------------------------------------------------------
__global__ __launch_bounds__(NTHREADS, 2)
void node_kernel(const float* __restrict__ x,
                 const float* __restrict__ b1, const float* __restrict__ b2,
                 const float* __restrict__ b3,
                 const float* __restrict__ gw, const float* __restrict__ bw,
                 float* __restrict__ out_x) {
    extern __shared__ char sm[];
    const u32 smb = smem_u32(sm);
    const int tid = threadIdx.x, wid = tid >> 5, lane = tid & 31;
    const int mbase = (wid >> 1) * 16, nbase = (wid & 1) * 64;
    const int n0 = blockIdx.x * MROWS;
    const int grow = tid >> 2, gqb = (tid & 3) * 8;

    float acc[8][4];
#pragma unroll
    for (int ng = 0; ng < 8; ++ng)
#pragma unroll
        for (int k = 0; k < 4; ++k) acc[ng][k] = 0.f;

    fill_half(smb + SM_BB0, g_wn, tid);       CP_COMMIT();
    fill_half(smb + SM_BB1, g_wn + HB, tid);  CP_COMMIT();

    float4 pre[8];
    issue_gather_guard(pre, (const float4*)x, n0 + grow, gqb);
    convert_gather(sm, pre, grow, gqb);
    issue_gather_guard(pre, (const float4*)g_agg, n0 + grow, gqb);

    // 4 chunks = 8 half-steps
#pragma unroll 1
    for (int t = 0; t < 8; ++t) {
        const u32 bbuf = smb + SM_BB0 + (u32)(t & 1) * HB;
        CP_WAIT(1);
        __syncthreads();
        if (t & 1) mma_odd(smb, bbuf, acc, mbase, nbase, lane);
        else       mma_even(smb, bbuf, acc, mbase, nbase, lane);
        __syncthreads();
        if (t + 2 < 8) {
            fill_half(bbuf, g_wn + (size_t)(t + 2) * HB, tid);
            CP_COMMIT();
        }
        if (t & 1) {
            const int s = t >> 1;
            if (s == 0) {
                convert_gather(sm, pre, grow, gqb);
            } else if (s == 1) {
                mid_epi(sm, acc, b1, mbase, nbase, lane);
            } else if (s == 2) {
                mid_epi(sm, acc, b2, mbase, nbase, lane);
            }
        }
    }

    final_dump(sm, acc, b3, mbase, nbase, lane);
    __syncthreads();
    ln_stats(sm, tid);
    __syncthreads();

    {
        const int tc = tid & 15, tr = tid >> 4;
        const float* sv = (const float*)sm;
        const float* smean = (const float*)(sm + SM_BB0);
        const float* srstd = (const float*)(sm + SM_BB0 + 256);
        float gv[8], bv[8];
#pragma unroll
        for (int j = 0; j < 8; ++j) {
            gv[j] = __ldg(gw + tc * 8 + j);
            bv[j] = __ldg(bw + tc * 8 + j);
        }
        for (int r4 = 0; r4 < 4; ++r4) {
            const int row = r4 * 16 + tr;
            const long long gr = n0 + row;
            if (gr < NN) {
                const float mean = smean[row], rstd = srstd[row];
                float4 ra = __ldg((const float4*)x + gr * 32 + tc * 2);
                float4 rb = __ldg((const float4*)x + gr * 32 + tc * 2 + 1);
                float o[8];
#pragma unroll
                for (int j = 0; j < 8; ++j)
                    o[j] = (sv[row * SVS + tc * 8 + j] - mean) * rstd * gv[j] + bv[j];
                o[0] += ra.x; o[1] += ra.y; o[2] += ra.z; o[3] += ra.w;
                o[4] += rb.x; o[5] += rb.y; o[6] += rb.z; o[7] += rb.w;
                ((float4*)out_x)[gr * 32 + tc * 2]     = make_float4(o[0], o[1], o[2], o[3]);
                ((float4*)out_x)[gr * 32 + tc * 2 + 1] = make_float4(o[4], o[5], o[6], o[7]);
            }
        }
    }
}

// ---------------------------------------------------------------------------
// Weight prep: split into bf16 hi/lo, transpose to [n][k], row stride 272B.
// ---------------------------------------------------------------------------
__global__ void prep_w(const float* __restrict__ ew1, const float* __restrict__ ew2,
                       const float* __restrict__ ew3, const float* __restrict__ nw1,
                       const float* __restrict__ nw2, const float* __restrict__ nw3) {
    int i = blockIdx.x * blockDim.x + threadIdx.x;
    if (i >= 9 * 16384) return;
    unsigned char* dst;
    float val;
    int cs = i >> 14, r = i & 16383;
    int kl = r >> 7, n = r & 127;
    if (cs < 5) {
        if (cs < 3)       val = ew1[(cs * 128 + kl) * 128 + n];
        else if (cs == 3) val = ew2[kl * 128 + n];
        else              val = ew3[kl * 128 + n];
        dst = g_we + (size_t)cs * WCHUNK;
    } else {
        int ns = cs - 5;
        if (ns < 2)       val = nw1[(ns * 128 + kl) * 128 + n];
        else if (ns == 2) val = nw2[kl * 128 + n];
        else              val = nw3[kl * 128 + n];
        dst = g_wn + (size_t)ns * WCHUNK;
    }
    u32 h = pack_bf16x2(val, 0.f);
    u32 l = pack_bf16x2(val - bf_lo_f(h), 0.f);
    *(unsigned short*)(dst + n * ROWB + kl * 2)      = (unsigned short)(h & 0xffff);
    *(unsigned short*)(dst + HB + n * ROWB + kl * 2) = (unsigned short)(l & 0xffff);
}

__global__ void zero_agg_kernel() {
    int i = blockIdx.x * blockDim.x + threadIdx.x;
    if (i < NN * 32)
        ((float4*)g_agg)[i] = make_float4(0.f, 0.f, 0.f, 0.f);
}

// ---------------------------------------------------------------------------
extern "C" void kernel_launch(void* const* d_in, const int* in_sizes, int n_in,
                              void* d_out, int out_size) {
    const float* x    = (const float*)d_in[0];
    const int*   eidx = (const int*)d_in[1];
    const float* ea   = (const float*)d_in[2];
    const float* ew1  = (const float*)d_in[3];
    const float* eb1  = (const float*)d_in[4];
    const float* ew2  = (const float*)d_in[5];
    const float* eb2  = (const float*)d_in[6];
    const float* ew3  = (const float*)d_in[7];
    const float* eb3  = (const float*)d_in[8];
    const float* eg   = (const float*)d_in[9];
    const float* ebt  = (const float*)d_in[10];
    const float* nw1  = (const float*)d_in[11];
    const float* nb1  = (const float*)d_in[12];
    const float* nw2  = (const float*)d_in[13];
    const float* nb2  = (const float*)d_in[14];
    const float* nw3  = (const float*)d_in[15];
    const float* nb3  = (const float*)d_in[16];
    const float* ng   = (const float*)d_in[17];
    const float* nbt  = (const float*)d_in[18];

    float* out_x = (float*)d_out;                       // [50000, 128]
    float* out_e = (float*)d_out + (size_t)NN * 128;    // [800000, 128]

    cudaFuncSetAttribute(edge_kernel, cudaFuncAttributeMaxDynamicSharedMemorySize, SM_BYTES);
    cudaFuncSetAttribute(node_kernel, cudaFuncAttributeMaxDynamicSharedMemorySize, SM_BYTES);

    zero_agg_kernel<<<(NN * 32 + 255) / 256, 256>>>();
    prep_w<<<(9 * 16384 + 255) / 256, 256>>>(ew1, ew2, ew3, nw1, nw2, nw3);
    edge_kernel<<<NE / MROWS, NTHREADS, SM_BYTES>>>(x, eidx, ea, eb1, eb2, eb3, eg, ebt, out_e);
    node_kernel<<<(NN + MROWS - 1) / MROWS, NTHREADS, SM_BYTES>>>(x, nb1, nb2, nb3, ng, nbt, out_x);
}

// round 12
// speedup vs baseline: 1.2373x; 1.0005x over previous
#include <cuda_runtime.h>

#define NN 50000
#define NE 800000

typedef unsigned int u32;
typedef unsigned long long u64;

// ---------------------------------------------------------------------------
// Device scratch (no cudaMalloc allowed)
// ---------------------------------------------------------------------------
__device__ float g_agg[(size_t)NN * 128];
__device__ float g_P[(size_t)NN * 128];   // x @ W1a (edge layer-1, x_i part)
__device__ float g_Q[(size_t)NN * 128];   // x @ W1b (edge layer-1, x_j part)
// Pre-split bf16 weights, transposed to [n][k], row stride 272B.
// Chunk = [hi 34816][lo 34816].
#define HB 34816
#define WCHUNK (2 * HB)
__device__ __align__(16) unsigned char g_we[5 * WCHUNK]; // W1a,W1b,W1c,W2,W3
__device__ __align__(16) unsigned char g_wn[4 * WCHUNK]; // node: L1 x2, L2, L3

// ---------------------------------------------------------------------------
// SMEM: A_hi, A_lo (64 rows), two B half-buffers; edge adds PQ fp32 buffer.
// ---------------------------------------------------------------------------
#define ROWB 272
#define SM_AHI 0
#define SM_ALO 17408             // 64*272
#define SM_BB0 34816
#define SM_BB1 (34816 + HB)      // 69632
#define SM_BYTES (34816 + 2 * HB)        // 104448 (node/pq kernels, 2 blk/SM)
#define SM_PQ   SM_BYTES                  // edge-only PQ fp32 buffer
#define PQS 132                           // float stride
#define SM_BYTES_E (SM_BYTES + 64 * PQS * 4) // 138240 (edge, 1 blk/SM)

#define MROWS 64
#define NTHREADS 256

// ---------------------------------------------------------------------------
// Helpers
// ---------------------------------------------------------------------------
__device__ __forceinline__ u32 smem_u32(const void* p) {
    u32 a;
    asm("{ .reg .u64 t; cvta.to.shared.u64 t, %1; cvt.u32.u64 %0, t; }"
        : "=r"(a) : "l"(p));
    return a;
}
__device__ __forceinline__ u32 pack_bf16x2(float e0, float e1) {
    u32 r;
    asm("cvt.rn.bf16x2.f32 %0, %1, %2;" : "=r"(r) : "f"(e1), "f"(e0));
    return r;
}
__device__ __forceinline__ float bf_lo_f(u32 p) { return __uint_as_float(p << 16); }
__device__ __forceinline__ float bf_hi_f(u32 p) { return __uint_as_float(p & 0xffff0000u); }
__device__ __forceinline__ float silu_f(float v) { return __fdividef(v, 1.0f + __expf(-v)); }

__device__ __forceinline__ void ldsm4(u32& r0, u32& r1, u32& r2, u32& r3, u32 addr) {
    asm volatile("ldmatrix.sync.aligned.m8n8.x4.shared.b16 {%0,%1,%2,%3}, [%4];"
                 : "=r"(r0), "=r"(r1), "=r"(r2), "=r"(r3) : "r"(addr));
}
__device__ __forceinline__ void mma16816(float* c, const u32* a, u32 b0, u32 b1) {
    asm volatile(
        "mma.sync.aligned.m16n8k16.row.col.f32.bf16.bf16.f32 "
        "{%0,%1,%2,%3}, {%4,%5,%6,%7}, {%8,%9}, {%0,%1,%2,%3};"
        : "+f"(c[0]), "+f"(c[1]), "+f"(c[2]), "+f"(c[3])
        : "r"(a[0]), "r"(a[1]), "r"(a[2]), "r"(a[3]), "r"(b0), "r"(b1));
}
__device__ __forceinline__ void split4(float v0, float v1, float v2, float v3,
                                       u64& hi, u64& lo) {
    u32 h0 = pack_bf16x2(v0, v1), h1 = pack_bf16x2(v2, v3);
    u32 l0 = pack_bf16x2(v0 - bf_lo_f(h0), v1 - bf_hi_f(h0));
    u32 l1 = pack_bf16x2(v2 - bf_lo_f(h1), v3 - bf_hi_f(h1));
    hi = (u64)h0 | ((u64)h1 << 32);
    lo = (u64)l0 | ((u64)l1 << 32);
}
__device__ __forceinline__ void red4(float* p, float a, float b, float c, float d) {
    asm volatile("red.global.add.v4.f32 [%0], {%1,%2,%3,%4};"
                 :: "l"(p), "f"(a), "f"(b), "f"(c), "f"(d) : "memory");
}

// ---- register gather prefetch (8 float4 per thread) ----
__device__ __forceinline__ void issue_gather(float4* pre, const float4* src,
                                             long long g, int qb) {
#pragma unroll
    for (int i = 0; i < 8; ++i)
        pre[i] = __ldg(src + g * 32 + qb + i);
}
__device__ __forceinline__ void issue_gather_guard(float4* pre, const float4* src,
                                                   int g, int qb) {
#pragma unroll
    for (int i = 0; i < 8; ++i) {
        float4 v = make_float4(0.f, 0.f, 0.f, 0.f);
        if (g < NN) v = __ldg(src + (size_t)g * 32 + qb + i);
        pre[i] = v;
    }
}
__device__ __forceinline__ void convert_gather(char* sm, const float4* pre,
                                               int row, int qb) {
#pragma unroll
    for (int i = 0; i < 8; ++i) {
        u64 hi, lo;
        split4(pre[i].x, pre[i].y, pre[i].z, pre[i].w, hi, lo);
        *(u64*)(sm + SM_AHI + row * ROWB + (qb + i) * 8) = hi;
        *(u64*)(sm + SM_ALO + row * ROWB + (qb + i) * 8) = lo;
    }
}

// ---- cp.async ----
__device__ __forceinline__ void cp16(u32 dst, const void* src) {
    asm volatile("cp.async.cg.shared.global [%0], [%1], 16;" :: "r"(dst), "l"(src));
}
#define CP_COMMIT() asm volatile("cp.async.commit_group;" ::: "memory")
#define CP_WAIT(n)  asm volatile("cp.async.wait_group %0;" :: "n"(n) : "memory")

__device__ __forceinline__ void fill_half(u32 dst, const unsigned char* w, int tid) {
#pragma unroll
    for (int i = 0; i < 9; ++i) {
        int t = tid + i * NTHREADS;
        if (t < HB / 16) cp16(dst + t * 16, w + t * 16);
    }
}

// ---------------------------------------------------------------------------
// MMA halves over one 128-K chunk. Warp tile 16x64. acc[8][4].
// ---------------------------------------------------------------------------
__device__ __forceinline__ void mma_even(u32 smb, u32 bbuf, float acc[8][4],
                                         int mbase, int nbase, int lane) {
    const u32 a_off = (u32)(mbase + (lane & 15)) * ROWB + (u32)(lane >> 4) * 16;
    const u32 b_off = (u32)(nbase + (lane & 7) + ((lane >> 4) & 1) * 8) * ROWB
                    + (u32)((lane >> 3) & 1) * 16;
#pragma unroll
    for (int ks = 0; ks < 8; ++ks) {
        const u32 kb = (u32)ks * 32;
        u32 ah[4], al[4], b[4][4];
        ldsm4(ah[0], ah[1], ah[2], ah[3], smb + SM_AHI + a_off + kb);
#pragma unroll
        for (int g = 0; g < 4; ++g)
            ldsm4(b[g][0], b[g][1], b[g][2], b[g][3],
                  bbuf + b_off + (u32)g * (16 * ROWB) + kb);
#pragma unroll
        for (int ng = 0; ng < 8; ++ng)
            mma16816(acc[ng], ah, b[ng >> 1][(ng & 1) * 2], b[ng >> 1][(ng & 1) * 2 + 1]);
        ldsm4(al[0], al[1], al[2], al[3], smb + SM_ALO + a_off + kb);
#pragma unroll
        for (int ng = 0; ng < 8; ++ng)
            mma16816(acc[ng], al, b[ng >> 1][(ng & 1) * 2], b[ng >> 1][(ng & 1) * 2 + 1]);
    }
}

__device__ __forceinline__ void mma_odd(u32 smb, u32 bbuf, float acc[8][4],
                                        int mbase, int nbase, int lane) {
    const u32 a_off = (u32)(mbase + (lane & 15)) * ROWB + (u32)(lane >> 4) * 16;
    const u32 b_off = (u32)(nbase + (lane & 7) + ((lane >> 4) & 1) * 8) * ROWB
                    + (u32)((lane >> 3) & 1) * 16;
#pragma unroll
    for (int ks = 0; ks < 8; ++ks) {
        const u32 kb = (u32)ks * 32;
        u32 ah[4], b[4][4];
        ldsm4(ah[0], ah[1], ah[2], ah[3], smb + SM_AHI + a_off + kb);
#pragma unroll
        for (int g = 0; g < 4; ++g)
            ldsm4(b[g][0], b[g][1], b[g][2], b[g][3],
                  bbuf + b_off + (u32)g * (16 * ROWB) + kb);
#pragma unroll
        for (int ng = 0; ng < 8; ++ng)
            mma16816(acc[ng], ah, b[ng >> 1][(ng & 1) * 2], b[ng >> 1][(ng & 1) * 2 + 1]);
    }
}

// bias + SiLU from acc -> A smem (hi/lo), zero acc
__device__ __forceinline__ void mid_epi(char* sm, float acc[8][4],
                                        const float* __restrict__ bias,
                                        int mbase, int nbase, int lane) {
    const int q = lane & 3, r = lane >> 2;
#pragma unroll
    for (int ng = 0; ng < 8; ++ng) {
        const int col = nbase + ng * 8 + q * 2;
        const float bx = __ldg(bias + col), by = __ldg(bias + col + 1);
        const int r0 = mbase + r, r1 = r0 + 8;
        float v0 = silu_f(acc[ng][0] + bx);
        float v1 = silu_f(acc[ng][1] + by);
        float v2 = silu_f(acc[ng][2] + bx);
        float v3 = silu_f(acc[ng][3] + by);
        u32 h0 = pack_bf16x2(v0, v1);
        u32 l0 = pack_bf16x2(v0 - bf_lo_f(h0), v1 - bf_hi_f(h0));
        u32 h1 = pack_bf16x2(v2, v3);
        u32 l1 = pack_bf16x2(v2 - bf_lo_f(h1), v3 - bf_hi_f(h1));
        *(u32*)(sm + SM_AHI + r0 * ROWB + col * 2) = h0;
        *(u32*)(sm + SM_ALO + r0 * ROWB + col * 2) = l0;
        *(u32*)(sm + SM_AHI + r1 * ROWB + col * 2) = h1;
        *(u32*)(sm + SM_ALO + r1 * ROWB + col * 2) = l1;
        acc[ng][0] = 0.f; acc[ng][1] = 0.f;
        acc[ng][2] = 0.f; acc[ng][3] = 0.f;
    }
}

// layer-1 variant: also add PQ (precomputed x_i@W1a + x_j@W1b) from smem
__device__ __forceinline__ void mid_epi_pq(char* sm, float acc[8][4],
                                           const float* __restrict__ bias,
                                           int mbase, int nbase, int lane) {
    const float* pqs = (const float*)(sm + SM_PQ);
    const int q = lane & 3, r = lane >> 2;
#pragma unroll
    for (int ng = 0; ng < 8; ++ng) {
        const int col = nbase + ng * 8 + q * 2;
        const float bx = __ldg(bias + col), by = __ldg(bias + col + 1);
        const int r0 = mbase + r, r1 = r0 + 8;
        float2 p0 = *(const float2*)(pqs + r0 * PQS + col);
        float2 p1 = *(const float2*)(pqs + r1 * PQS + col);
        float v0 = silu_f(acc[ng][0] + bx + p0.x);
        float v1 = silu_f(acc[ng][1] + by + p0.y);
        float v2 = silu_f(acc[ng][2] + bx + p1.x);
        float v3 = silu_f(acc[ng][3] + by + p1.y);
        u32 h0 = pack_bf16x2(v0, v1);
        u32 l0 = pack_bf16x2(v0 - bf_lo_f(h0), v1 - bf_hi_f(h0));
        u32 h1 = pack_bf16x2(v2, v3);
        u32 l1 = pack_bf16x2(v2 - bf_lo_f(h1), v3 - bf_hi_f(h1));
        *(u32*)(sm + SM_AHI + r0 * ROWB + col * 2) = h0;
        *(u32*)(sm + SM_ALO + r0 * ROWB + col * 2) = l0;
        *(u32*)(sm + SM_AHI + r1 * ROWB + col * 2) = h1;
        *(u32*)(sm + SM_ALO + r1 * ROWB + col * 2) = l1;
        acc[ng][0] = 0.f; acc[ng][1] = 0.f;
        acc[ng][2] = 0.f; acc[ng][3] = 0.f;
    }
}

#define SVS 130  // float scratch stride; 64*130*4 = 33280 <= A region

__device__ __forceinline__ void final_dump(char* sm, float acc[8][4],
                                           const float* __restrict__ b3,
                                           int mbase, int nbase, int lane) {
    float* sv = (float*)sm;
    const int q = lane & 3, r = lane >> 2;
#pragma unroll
    for (int ng = 0; ng < 8; ++ng) {
        const int col = nbase + ng * 8 + q * 2;
        const float bx = __ldg(b3 + col), by = __ldg(b3 + col + 1);
        const int r0 = mbase + r, r1 = r0 + 8;
        *(float2*)(sv + r0 * SVS + col) = make_float2(acc[ng][0] + bx, acc[ng][1] + by);
        *(float2*)(sv + r1 * SVS + col) = make_float2(acc[ng][2] + bx, acc[ng][3] + by);
    }
}

__device__ __forceinline__ void ln_stats(char* sm, int tid) {
    if (tid < MROWS) {
        const float* sv = (float*)sm;
        float s1 = 0.f, s2 = 0.f;
#pragma unroll 16
        for (int c = 0; c < 128; c += 2) {
            float2 v = *(const float2*)(sv + tid * SVS + c);
            s1 += v.x + v.y;
            s2 += v.x * v.x + v.y * v.y;
        }
        float mean = s1 * (1.0f / 128.0f);
        float var = s2 * (1.0f / 128.0f) - mean * mean;
        ((float*)(sm + SM_BB0))[tid] = mean;
        ((float*)(sm + SM_BB0 + 256))[tid] = rsqrtf(var + 1e-5f);
    }
}

// ---------------------------------------------------------------------------
// PQ precompute: P = x@W1a, Q = x@W1b (64 rows/block, 256 threads)
// ---------------------------------------------------------------------------
__device__ __forceinline__ void store_pq(float* dst, float acc[8][4],
                                         int n0, int mbase, int nbase, int lane) {
    const int q = lane & 3, r = lane >> 2;
#pragma unroll
    for (int ng = 0; ng < 8; ++ng) {
        const int col = nbase + ng * 8 + q * 2;
        const int r0 = mbase + r, r1 = r0 + 8;
        if (n0 + r0 < NN)
            *(float2*)(dst + (size_t)(n0 + r0) * 128 + col) = make_float2(acc[ng][0], acc[ng][1]);
        if (n0 + r1 < NN)
            *(float2*)(dst + (size_t)(n0 + r1) * 128 + col) = make_float2(acc[ng][2], acc[ng][3]);
        acc[ng][0] = 0.f; acc[ng][1] = 0.f;
        acc[ng][2] = 0.f; acc[ng][3] = 0.f;
    }
}

__global__ __launch_bounds__(NTHREADS, 2)
void pq_kernel(const float* __restrict__ x) {
    extern __shared__ char sm[];
    const u32 smb = smem_u32(sm);
    const int tid = threadIdx.x, wid = tid >> 5, lane = tid & 31;
    const int mbase = (wid >> 1) * 16, nbase = (wid & 1) * 64;
    const int n0 = blockIdx.x * MROWS;
    const int grow = tid >> 2, gqb = (tid & 3) * 8;

    float acc[8][4];
#pragma unroll
    for (int ng = 0; ng < 8; ++ng)
#pragma unroll
        for (int k = 0; k < 4; ++k) acc[ng][k] = 0.f;

    fill_half(smb + SM_BB0, g_we, tid);       CP_COMMIT();
    fill_half(smb + SM_BB1, g_we + HB, tid);  CP_COMMIT();

    float4 pre[8];
    issue_gather_guard(pre, (const float4*)x, n0 + grow, gqb);
    convert_gather(sm, pre, grow, gqb);

    // 2 chunks (W1a, W1b) = 4 half-steps; same A both chunks
#pragma unroll 1
    for (int t = 0; t < 4; ++t) {
        const u32 bbuf = smb + SM_BB0 + (u32)(t & 1) * HB;
        if (t < 3) { CP_WAIT(1); } else { CP_WAIT(0); }
        __syncthreads();
        if (t & 1) mma_odd(smb, bbuf, acc, mbase, nbase, lane);
        else       mma_even(smb, bbuf, acc, mbase, nbase, lane);
        __syncthreads();
        if (t + 2 < 4) {
            fill_half(bbuf, g_we + (size_t)(t + 2) * HB, tid);
            CP_COMMIT();
        }
        if (t == 1) store_pq(g_P, acc, n0, mbase, nbase, lane);
    }
    store_pq(g_Q, acc, n0, mbase, nbase, lane);
}

// ---------------------------------------------------------------------------
// Edge kernel: 64 edges/block, 256 threads, 3 MMA chunks (W1c, W2, W3)
// ---------------------------------------------------------------------------
__global__ __launch_bounds__(NTHREADS)
void edge_kernel(const int* __restrict__ eidx,
                 const float* __restrict__ ea,
                 const float* __restrict__ b1, const float* __restrict__ b2,
                 const float* __restrict__ b3,
                 const float* __restrict__ gw, const float* __restrict__ bw,
                 float* __restrict__ out_e) {
    extern __shared__ char sm[];
    const u32 smb = smem_u32(sm);
    const int tid = threadIdx.x, wid = tid >> 5, lane = tid & 31;
    const int mbase = (wid >> 1) * 16, nbase = (wid & 1) * 64;
    const int e0 = blockIdx.x * MROWS;
    const int grow = tid >> 2, gqb = (tid & 3) * 8;
    const unsigned char* wbase = g_we + 2 * WCHUNK;  // chunks W1c, W2, W3

    float acc[8][4];
#pragma unroll
    for (int ng = 0; ng < 8; ++ng)
#pragma unroll
        for (int k = 0; k < 4; ++k) acc[ng][k] = 0.f;

    fill_half(smb + SM_BB0, wbase, tid);       CP_COMMIT();
    fill_half(smb + SM_BB1, wbase + HB, tid);  CP_COMMIT();

    // gathers: ea (A operand), P[i], Q[j] (layer-1 additive)
    {
        const int i_idx = __ldg(eidx + e0 + grow);
        const int j_idx = __ldg(eidx + NE + e0 + grow);
        float4 preA[8], preP[8], preQ[8];
        issue_gather(preA, (const float4*)ea, (long long)(e0 + grow), gqb);
        issue_gather(preP, (const float4*)g_P, (long long)i_idx, gqb);
        issue_gather(preQ, (const float4*)g_Q, (long long)j_idx, gqb);
        convert_gather(sm, preA, grow, gqb);
        float* pqs = (float*)(sm + SM_PQ);
#pragma unroll
        for (int i = 0; i < 8; ++i) {
            float4 s = make_float4(preP[i].x + preQ[i].x, preP[i].y + preQ[i].y,
                                   preP[i].z + preQ[i].z, preP[i].w + preQ[i].w);
            *(float4*)(pqs + grow * PQS + (gqb + i) * 4) = s;
        }
    }

    // 3 chunks = 6 half-steps
#pragma unroll 1
    for (int t = 0; t < 6; ++t) {
        const u32 bbuf = smb + SM_BB0 + (u32)(t & 1) * HB;
        if (t < 5) { CP_WAIT(1); } else { CP_WAIT(0); }
        __syncthreads();
        if (t & 1) mma_odd(smb, bbuf, acc, mbase, nbase, lane);
        else       mma_even(smb, bbuf, acc, mbase, nbase, lane);
        __syncthreads();
        if (t + 2 < 6) {
            fill_half(bbuf, wbase + (size_t)(t + 2) * HB, tid);
            CP_COMMIT();
        }
        if (t == 1)      mid_epi_pq(sm, acc, b1, mbase, nbase, lane);
        else if (t == 3) mid_epi(sm, acc, b2, mbase, nbase, lane);
    }

    // ---- final: bias3 -> LN -> residual -> store + scatter ----
    final_dump(sm, acc, b3, mbase, nbase, lane);
    __syncthreads();
    ln_stats(sm, tid);
    __syncthreads();

    {
        const int tc = tid & 15, tr = tid >> 4;
        const float* sv = (const float*)sm;
        const float* smean = (const float*)(sm + SM_BB0);
        const float* srstd = (const float*)(sm + SM_BB0 + 256);
        float gv[8], bv[8];
#pragma unroll
        for (int j = 0; j < 8; ++j) {
            gv[j] = __ldg(gw + tc * 8 + j);
            bv[j] = __ldg(bw + tc * 8 + j);
        }
        for (int r4 = 0; r4 < 4; ++r4) {
            const int row = r4 * 16 + tr;
            const long long gr = e0 + row;
            const float mean = smean[row], rstd = srstd[row];
            float4 ra = __ldg((const float4*)ea + gr * 32 + tc * 2);
            float4 rb = __ldg((const float4*)ea + gr * 32 + tc * 2 + 1);
            float o[8];
#pragma unroll
            for (int j = 0; j < 8; ++j)
                o[j] = (sv[row * SVS + tc * 8 + j] - mean) * rstd * gv[j] + bv[j];
            o[0] += ra.x; o[1] += ra.y; o[2] += ra.z; o[3] += ra.w;
            o[4] += rb.x; o[5] += rb.y; o[6] += rb.z; o[7] += rb.w;
            ((float4*)out_e)[gr * 32 + tc * 2]     = make_float4(o[0], o[1], o[2], o[3]);
            ((float4*)out_e)[gr * 32 + tc * 2 + 1] = make_float4(o[4], o[5], o[6], o[7]);
            const int dj = __ldg(eidx + NE + gr);
            float* ap = g_agg + (size_t)dj * 128 + tc * 8;
            red4(ap,     o[0], o[1], o[2], o[3]);
            red4(ap + 4, o[4], o[5], o[6], o[7]);
        }
    }
}

// ---------------------------------------------------------------------------
// Node kernel: 64 nodes/block, 256 threads, 2 blocks/SM (unchanged)
// ---------------------------------------------------------------------------
__global__ __launch_bounds__(NTHREADS, 2)
void node_kernel(const float* __restrict__ x,
                 const float* __restrict__ b1, const float* __restrict__ b2,
                 const float* __restrict__ b3,
                 const float* __restrict__ gw, const float* __restrict__ bw,
                 float* __restrict__ out_x) {
    extern __shared__ char sm[];
    const u32 smb = smem_u32(sm);
    const int tid = threadIdx.x, wid = tid >> 5, lane = tid & 31;
    const int mbase = (wid >> 1) * 16, nbase = (wid & 1) * 64;
    const int n0 = blockIdx.x * MROWS;
    const int grow = tid >> 2, gqb = (tid & 3) * 8;

    float acc[8][4];
#pragma unroll
    for (int ng = 0; ng < 8; ++ng)
#pragma unroll
        for (int k = 0; k < 4; ++k) acc[ng][k] = 0.f;

    fill_half(smb + SM_BB0, g_wn, tid);       CP_COMMIT();
    fill_half(smb + SM_BB1, g_wn + HB, tid);  CP_COMMIT();

    float4 pre[8];
    issue_gather_guard(pre, (const float4*)x, n0 + grow, gqb);
    convert_gather(sm, pre, grow, gqb);
    issue_gather_guard(pre, (const float4*)g_agg, n0 + grow, gqb);

    // 4 chunks = 8 half-steps
#pragma unroll 1
    for (int t = 0; t < 8; ++t) {
        const u32 bbuf = smb + SM_BB0 + (u32)(t & 1) * HB;
        if (t < 7) { CP_WAIT(1); } else { CP_WAIT(0); }
        __syncthreads();
        if (t & 1) mma_odd(smb, bbuf, acc, mbase, nbase, lane);
        else       mma_even(smb, bbuf, acc, mbase, nbase, lane);
        __syncthreads();
        if (t + 2 < 8) {
            fill_half(bbuf, g_wn + (size_t)(t + 2) * HB, tid);
            CP_COMMIT();
        }
        if (t & 1) {
            const int s = t >> 1;
            if (s == 0) {
                convert_gather(sm, pre, grow, gqb);
            } else if (s == 1) {
                mid_epi(sm, acc, b1, mbase, nbase, lane);
            } else if (s == 2) {
                mid_epi(sm, acc, b2, mbase, nbase, lane);
            }
        }
    }

    final_dump(sm, acc, b3, mbase, nbase, lane);
    __syncthreads();
    ln_stats(sm, tid);
    __syncthreads();

    {
        const int tc = tid & 15, tr = tid >> 4;
        const float* sv = (const float*)sm;
        const float* smean = (const float*)(sm + SM_BB0);
        const float* srstd = (const float*)(sm + SM_BB0 + 256);
        float gv[8], bv[8];
#pragma unroll
        for (int j = 0; j < 8; ++j) {
            gv[j] = __ldg(gw + tc * 8 + j);
            bv[j] = __ldg(bw + tc * 8 + j);
        }
        for (int r4 = 0; r4 < 4; ++r4) {
            const int row = r4 * 16 + tr;
            const long long gr = n0 + row;
            if (gr < NN) {
                const float mean = smean[row], rstd = srstd[row];
                float4 ra = __ldg((const float4*)x + gr * 32 + tc * 2);
                float4 rb = __ldg((const float4*)x + gr * 32 + tc * 2 + 1);
                float o[8];
#pragma unroll
                for (int j = 0; j < 8; ++j)
                    o[j] = (sv[row * SVS + tc * 8 + j] - mean) * rstd * gv[j] + bv[j];
                o[0] += ra.x; o[1] += ra.y; o[2] += ra.z; o[3] += ra.w;
                o[4] += rb.x; o[5] += rb.y; o[6] += rb.z; o[7] += rb.w;
                ((float4*)out_x)[gr * 32 + tc * 2]     = make_float4(o[0], o[1], o[2], o[3]);
                ((float4*)out_x)[gr * 32 + tc * 2 + 1] = make_float4(o[4], o[5], o[6], o[7]);
            }
        }
    }
}

// ---------------------------------------------------------------------------
// Weight prep: split into bf16 hi/lo, transpose to [n][k], row stride 272B.
// ---------------------------------------------------------------------------
__global__ void prep_w(const float* __restrict__ ew1, const float* __restrict__ ew2,
                       const float* __restrict__ ew3, const float* __restrict__ nw1,
                       const float* __restrict__ nw2, const float* __restrict__ nw3) {
    int i = blockIdx.x * blockDim.x + threadIdx.x;
    if (i >= 9 * 16384) return;
    unsigned char* dst;
    float val;
    int cs = i >> 14, r = i & 16383;
    int kl = r >> 7, n = r & 127;
    if (cs < 5) {
        if (cs < 3)       val = ew1[(cs * 128 + kl) * 128 + n];
        else if (cs == 3) val = ew2[kl * 128 + n];
        else              val = ew3[kl * 128 + n];
        dst = g_we + (size_t)cs * WCHUNK;
    } else {
        int ns = cs - 5;
        if (ns < 2)       val = nw1[(ns * 128 + kl) * 128 + n];
        else if (ns == 2) val = nw2[kl * 128 + n];
        else              val = nw3[kl * 128 + n];
        dst = g_wn + (size_t)ns * WCHUNK;
    }
    u32 h = pack_bf16x2(val, 0.f);
    u32 l = pack_bf16x2(val - bf_lo_f(h), 0.f);
    *(unsigned short*)(dst + n * ROWB + kl * 2)      = (unsigned short)(h & 0xffff);
    *(unsigned short*)(dst + HB + n * ROWB + kl * 2) = (unsigned short)(l & 0xffff);
}

__global__ void zero_agg_kernel() {
    int i = blockIdx.x * blockDim.x + threadIdx.x;
    if (i < NN * 32)
        ((float4*)g_agg)[i] = make_float4(0.f, 0.f, 0.f, 0.f);
}

// ---------------------------------------------------------------------------
extern "C" void kernel_launch(void* const* d_in, const int* in_sizes, int n_in,
                              void* d_out, int out_size) {
    const float* x    = (const float*)d_in[0];
    const int*   eidx = (const int*)d_in[1];
    const float* ea   = (const float*)d_in[2];
    const float* ew1  = (const float*)d_in[3];
    const float* eb1  = (const float*)d_in[4];
    const float* ew2  = (const float*)d_in[5];
    const float* eb2  = (const float*)d_in[6];
    const float* ew3  = (const float*)d_in[7];
    const float* eb3  = (const float*)d_in[8];
    const float* eg   = (const float*)d_in[9];
    const float* ebt  = (const float*)d_in[10];
    const float* nw1  = (const float*)d_in[11];
    const float* nb1  = (const float*)d_in[12];
    const float* nw2  = (const float*)d_in[13];
    const float* nb2  = (const float*)d_in[14];
    const float* nw3  = (const float*)d_in[15];
    const float* nb3  = (const float*)d_in[16];
    const float* ng   = (const float*)d_in[17];
    const float* nbt  = (const float*)d_in[18];

    float* out_x = (float*)d_out;                       // [50000, 128]
    float* out_e = (float*)d_out + (size_t)NN * 128;    // [800000, 128]

    cudaFuncSetAttribute(pq_kernel,   cudaFuncAttributeMaxDynamicSharedMemorySize, SM_BYTES);
    cudaFuncSetAttribute(edge_kernel, cudaFuncAttributeMaxDynamicSharedMemorySize, SM_BYTES_E);
    cudaFuncSetAttribute(node_kernel, cudaFuncAttributeMaxDynamicSharedMemorySize, SM_BYTES);

    zero_agg_kernel<<<(NN * 32 + 255) / 256, 256>>>();
    prep_w<<<(9 * 16384 + 255) / 256, 256>>>(ew1, ew2, ew3, nw1, nw2, nw3);
    pq_kernel<<<(NN + MROWS - 1) / MROWS, NTHREADS, SM_BYTES>>>(x);
    edge_kernel<<<NE / MROWS, NTHREADS, SM_BYTES_E>>>(eidx, ea, eb1, eb2, eb3, eg, ebt, out_e);
    node_kernel<<<(NN + MROWS - 1) / MROWS, NTHREADS, SM_BYTES>>>(x, nb1, nb2, nb3, ng, nbt, out_x);
}

// round 13
// speedup vs baseline: 1.5588x; 1.2598x over previous
#include <cuda_runtime.h>

#define NN 50000
#define NE 800000

typedef unsigned int u32;
typedef unsigned long long u64;

// ---------------------------------------------------------------------------
// Device scratch (no cudaMalloc allowed)
// ---------------------------------------------------------------------------
__device__ float g_agg[(size_t)NN * 128];
__device__ float g_P[(size_t)NN * 128];   // x @ W1a (edge layer-1, x_i part)
__device__ float g_Q[(size_t)NN * 128];   // x @ W1b (edge layer-1, x_j part)
// Pre-split bf16 weights, transposed to [n][k], row stride 272B.
// Chunk = [hi 34816][lo 34816].
#define HB 34816
#define WCHUNK (2 * HB)
__device__ __align__(16) unsigned char g_we[5 * WCHUNK]; // W1a,W1b,W1c,W2,W3
__device__ __align__(16) unsigned char g_wn[4 * WCHUNK]; // node: L1 x2, L2, L3

// ---------------------------------------------------------------------------
// SMEM: A_hi, A_lo (64 rows), two B half-buffers. 104448 B -> 2 blocks/SM.
// ---------------------------------------------------------------------------
#define ROWB 272
#define SM_AHI 0
#define SM_ALO 17408             // 64*272
#define SM_BB0 34816
#define SM_BB1 (34816 + HB)      // 69632
#define SM_BYTES (34816 + 2 * HB) // 104448

#define MROWS 64
#define NTHREADS 256

// ---------------------------------------------------------------------------
// Helpers
// ---------------------------------------------------------------------------
__device__ __forceinline__ u32 smem_u32(const void* p) {
    u32 a;
    asm("{ .reg .u64 t; cvta.to.shared.u64 t, %1; cvt.u32.u64 %0, t; }"
        : "=r"(a) : "l"(p));
    return a;
}
__device__ __forceinline__ u32 pack_bf16x2(float e0, float e1) {
    u32 r;
    asm("cvt.rn.bf16x2.f32 %0, %1, %2;" : "=r"(r) : "f"(e1), "f"(e0));
    return r;
}
__device__ __forceinline__ float bf_lo_f(u32 p) { return __uint_as_float(p << 16); }
__device__ __forceinline__ float bf_hi_f(u32 p) { return __uint_as_float(p & 0xffff0000u); }
__device__ __forceinline__ float silu_f(float v) { return __fdividef(v, 1.0f + __expf(-v)); }

__device__ __forceinline__ void ldsm4(u32& r0, u32& r1, u32& r2, u32& r3, u32 addr) {
    asm volatile("ldmatrix.sync.aligned.m8n8.x4.shared.b16 {%0,%1,%2,%3}, [%4];"
                 : "=r"(r0), "=r"(r1), "=r"(r2), "=r"(r3) : "r"(addr));
}
__device__ __forceinline__ void mma16816(float* c, const u32* a, u32 b0, u32 b1) {
    asm volatile(
        "mma.sync.aligned.m16n8k16.row.col.f32.bf16.bf16.f32 "
        "{%0,%1,%2,%3}, {%4,%5,%6,%7}, {%8,%9}, {%0,%1,%2,%3};"
        : "+f"(c[0]), "+f"(c[1]), "+f"(c[2]), "+f"(c[3])
        : "r"(a[0]), "r"(a[1]), "r"(a[2]), "r"(a[3]), "r"(b0), "r"(b1));
}
__device__ __forceinline__ void split4(float v0, float v1, float v2, float v3,
                                       u64& hi, u64& lo) {
    u32 h0 = pack_bf16x2(v0, v1), h1 = pack_bf16x2(v2, v3);
    u32 l0 = pack_bf16x2(v0 - bf_lo_f(h0), v1 - bf_hi_f(h0));
    u32 l1 = pack_bf16x2(v2 - bf_lo_f(h1), v3 - bf_hi_f(h1));
    hi = (u64)h0 | ((u64)h1 << 32);
    lo = (u64)l0 | ((u64)l1 << 32);
}
__device__ __forceinline__ void red4(float* p, float a, float b, float c, float d) {
    asm volatile("red.global.add.v4.f32 [%0], {%1,%2,%3,%4};"
                 :: "l"(p), "f"(a), "f"(b), "f"(c), "f"(d) : "memory");
}

// ---- register gather prefetch (8 float4 per thread) ----
__device__ __forceinline__ void issue_gather(float4* pre, const float4* src,
                                             long long g, int qb) {
#pragma unroll
    for (int i = 0; i < 8; ++i)
        pre[i] = __ldg(src + g * 32 + qb + i);
}
__device__ __forceinline__ void issue_gather_guard(float4* pre, const float4* src,
                                                   int g, int qb) {
#pragma unroll
    for (int i = 0; i < 8; ++i) {
        float4 v = make_float4(0.f, 0.f, 0.f, 0.f);
        if (g < NN) v = __ldg(src + (size_t)g * 32 + qb + i);
        pre[i] = v;
    }
}
__device__ __forceinline__ void convert_gather(char* sm, const float4* pre,
                                               int row, int qb) {
#pragma unroll
    for (int i = 0; i < 8; ++i) {
        u64 hi, lo;
        split4(pre[i].x, pre[i].y, pre[i].z, pre[i].w, hi, lo);
        *(u64*)(sm + SM_AHI + row * ROWB + (qb + i) * 8) = hi;
        *(u64*)(sm + SM_ALO + row * ROWB + (qb + i) * 8) = lo;
    }
}

// ---- cp.async ----
__device__ __forceinline__ void cp16(u32 dst, const void* src) {
    asm volatile("cp.async.cg.shared.global [%0], [%1], 16;" :: "r"(dst), "l"(src));
}
#define CP_COMMIT() asm volatile("cp.async.commit_group;" ::: "memory")
#define CP_WAIT(n)  asm volatile("cp.async.wait_group %0;" :: "n"(n) : "memory")

__device__ __forceinline__ void fill_half(u32 dst, const unsigned char* w, int tid) {
#pragma unroll
    for (int i = 0; i < 9; ++i) {
        int t = tid + i * NTHREADS;
        if (t < HB / 16) cp16(dst + t * 16, w + t * 16);
    }
}

// ---------------------------------------------------------------------------
// MMA halves over one 128-K chunk. Warp tile 16x64. acc[8][4].
// ---------------------------------------------------------------------------
__device__ __forceinline__ void mma_even(u32 smb, u32 bbuf, float acc[8][4],
                                         int mbase, int nbase, int lane) {
    const u32 a_off = (u32)(mbase + (lane & 15)) * ROWB + (u32)(lane >> 4) * 16;
    const u32 b_off = (u32)(nbase + (lane & 7) + ((lane >> 4) & 1) * 8) * ROWB
                    + (u32)((lane >> 3) & 1) * 16;
#pragma unroll
    for (int ks = 0; ks < 8; ++ks) {
        const u32 kb = (u32)ks * 32;
        u32 ah[4], al[4], b[4][4];
        ldsm4(ah[0], ah[1], ah[2], ah[3], smb + SM_AHI + a_off + kb);
#pragma unroll
        for (int g = 0; g < 4; ++g)
            ldsm4(b[g][0], b[g][1], b[g][2], b[g][3],
                  bbuf + b_off + (u32)g * (16 * ROWB) + kb);
#pragma unroll
        for (int ng = 0; ng < 8; ++ng)
            mma16816(acc[ng], ah, b[ng >> 1][(ng & 1) * 2], b[ng >> 1][(ng & 1) * 2 + 1]);
        ldsm4(al[0], al[1], al[2], al[3], smb + SM_ALO + a_off + kb);
#pragma unroll
        for (int ng = 0; ng < 8; ++ng)
            mma16816(acc[ng], al, b[ng >> 1][(ng & 1) * 2], b[ng >> 1][(ng & 1) * 2 + 1]);
    }
}

__device__ __forceinline__ void mma_odd(u32 smb, u32 bbuf, float acc[8][4],
                                        int mbase, int nbase, int lane) {
    const u32 a_off = (u32)(mbase + (lane & 15)) * ROWB + (u32)(lane >> 4) * 16;
    const u32 b_off = (u32)(nbase + (lane & 7) + ((lane >> 4) & 1) * 8) * ROWB
                    + (u32)((lane >> 3) & 1) * 16;
#pragma unroll
    for (int ks = 0; ks < 8; ++ks) {
        const u32 kb = (u32)ks * 32;
        u32 ah[4], b[4][4];
        ldsm4(ah[0], ah[1], ah[2], ah[3], smb + SM_AHI + a_off + kb);
#pragma unroll
        for (int g = 0; g < 4; ++g)
            ldsm4(b[g][0], b[g][1], b[g][2], b[g][3],
                  bbuf + b_off + (u32)g * (16 * ROWB) + kb);
#pragma unroll
        for (int ng = 0; ng < 8; ++ng)
            mma16816(acc[ng], ah, b[ng >> 1][(ng & 1) * 2], b[ng >> 1][(ng & 1) * 2 + 1]);
    }
}

// bias + SiLU from acc -> A smem (hi/lo), zero acc
__device__ __forceinline__ void mid_epi(char* sm, float acc[8][4],
                                        const float* __restrict__ bias,
                                        int mbase, int nbase, int lane) {
    const int q = lane & 3, r = lane >> 2;
#pragma unroll
    for (int ng = 0; ng < 8; ++ng) {
        const int col = nbase + ng * 8 + q * 2;
        const float bx = __ldg(bias + col), by = __ldg(bias + col + 1);
        const int r0 = mbase + r, r1 = r0 + 8;
        float v0 = silu_f(acc[ng][0] + bx);
        float v1 = silu_f(acc[ng][1] + by);
        float v2 = silu_f(acc[ng][2] + bx);
        float v3 = silu_f(acc[ng][3] + by);
        u32 h0 = pack_bf16x2(v0, v1);
        u32 l0 = pack_bf16x2(v0 - bf_lo_f(h0), v1 - bf_hi_f(h0));
        u32 h1 = pack_bf16x2(v2, v3);
        u32 l1 = pack_bf16x2(v2 - bf_lo_f(h1), v3 - bf_hi_f(h1));
        *(u32*)(sm + SM_AHI + r0 * ROWB + col * 2) = h0;
        *(u32*)(sm + SM_ALO + r0 * ROWB + col * 2) = l0;
        *(u32*)(sm + SM_AHI + r1 * ROWB + col * 2) = h1;
        *(u32*)(sm + SM_ALO + r1 * ROWB + col * 2) = l1;
        acc[ng][0] = 0.f; acc[ng][1] = 0.f;
        acc[ng][2] = 0.f; acc[ng][3] = 0.f;
    }
}

#define SVS 130  // float scratch stride; 64*130*4 = 33280 <= A region

__device__ __forceinline__ void final_dump(char* sm, float acc[8][4],
                                           const float* __restrict__ b3,
                                           int mbase, int nbase, int lane) {
    float* sv = (float*)sm;
    const int q = lane & 3, r = lane >> 2;
#pragma unroll
    for (int ng = 0; ng < 8; ++ng) {
        const int col = nbase + ng * 8 + q * 2;
        const float bx = __ldg(b3 + col), by = __ldg(b3 + col + 1);
        const int r0 = mbase + r, r1 = r0 + 8;
        *(float2*)(sv + r0 * SVS + col) = make_float2(acc[ng][0] + bx, acc[ng][1] + by);
        *(float2*)(sv + r1 * SVS + col) = make_float2(acc[ng][2] + bx, acc[ng][3] + by);
    }
}

__device__ __forceinline__ void ln_stats(char* sm, int tid) {
    if (tid < MROWS) {
        const float* sv = (float*)sm;
        float s1 = 0.f, s2 = 0.f;
#pragma unroll 16
        for (int c = 0; c < 128; c += 2) {
            float2 v = *(const float2*)(sv + tid * SVS + c);
            s1 += v.x + v.y;
            s2 += v.x * v.x + v.y * v.y;
        }
        float mean = s1 * (1.0f / 128.0f);
        float var = s2 * (1.0f / 128.0f) - mean * mean;
        ((float*)(sm + SM_BB0))[tid] = mean;
        ((float*)(sm + SM_BB0 + 256))[tid] = rsqrtf(var + 1e-5f);
    }
}

// ---------------------------------------------------------------------------
// PQ precompute: P = x@W1a, Q = x@W1b (64 rows/block, 256 threads)
// ---------------------------------------------------------------------------
__device__ __forceinline__ void store_pq(float* dst, float acc[8][4],
                                         int n0, int mbase, int nbase, int lane) {
    const int q = lane & 3, r = lane >> 2;
#pragma unroll
    for (int ng = 0; ng < 8; ++ng) {
        const int col = nbase + ng * 8 + q * 2;
        const int r0 = mbase + r, r1 = r0 + 8;
        if (n0 + r0 < NN)
            *(float2*)(dst + (size_t)(n0 + r0) * 128 + col) = make_float2(acc[ng][0], acc[ng][1]);
        if (n0 + r1 < NN)
            *(float2*)(dst + (size_t)(n0 + r1) * 128 + col) = make_float2(acc[ng][2], acc[ng][3]);
        acc[ng][0] = 0.f; acc[ng][1] = 0.f;
        acc[ng][2] = 0.f; acc[ng][3] = 0.f;
    }
}

__global__ __launch_bounds__(NTHREADS, 2)
void pq_kernel(const float* __restrict__ x) {
    extern __shared__ char sm[];
    const u32 smb = smem_u32(sm);
    const int tid = threadIdx.x, wid = tid >> 5, lane = tid & 31;
    const int mbase = (wid >> 1) * 16, nbase = (wid & 1) * 64;
    const int n0 = blockIdx.x * MROWS;
    const int grow = tid >> 2, gqb = (tid & 3) * 8;

    float acc[8][4];
#pragma unroll
    for (int ng = 0; ng < 8; ++ng)
#pragma unroll
        for (int k = 0; k < 4; ++k) acc[ng][k] = 0.f;

    fill_half(smb + SM_BB0, g_we, tid);       CP_COMMIT();
    fill_half(smb + SM_BB1, g_we + HB, tid);  CP_COMMIT();

    float4 pre[8];
    issue_gather_guard(pre, (const float4*)x, n0 + grow, gqb);
    convert_gather(sm, pre, grow, gqb);

    // 2 chunks (W1a, W1b) = 4 half-steps; same A both chunks
#pragma unroll 1
    for (int t = 0; t < 4; ++t) {
        const u32 bbuf = smb + SM_BB0 + (u32)(t & 1) * HB;
        if (t < 3) { CP_WAIT(1); } else { CP_WAIT(0); }
        __syncthreads();
        if (t & 1) mma_odd(smb, bbuf, acc, mbase, nbase, lane);
        else       mma_even(smb, bbuf, acc, mbase, nbase, lane);
        __syncthreads();
        if (t + 2 < 4) {
            fill_half(bbuf, g_we + (size_t)(t + 2) * HB, tid);
            CP_COMMIT();
        }
        if (t == 1) store_pq(g_P, acc, n0, mbase, nbase, lane);
    }
    store_pq(g_Q, acc, n0, mbase, nbase, lane);
}

// ---------------------------------------------------------------------------
// Edge kernel: 64 edges/block, 256 threads, 3 MMA chunks (W1c, W2, W3).
// Layer-1 acc initialized from P[i]/Q[j] fragment loads (global, fp32).
// ---------------------------------------------------------------------------
__global__ __launch_bounds__(NTHREADS, 2)
void edge_kernel(const int* __restrict__ eidx,
                 const float* __restrict__ ea,
                 const float* __restrict__ b1, const float* __restrict__ b2,
                 const float* __restrict__ b3,
                 const float* __restrict__ gw, const float* __restrict__ bw,
                 float* __restrict__ out_e) {
    extern __shared__ char sm[];
    const u32 smb = smem_u32(sm);
    const int tid = threadIdx.x, wid = tid >> 5, lane = tid & 31;
    const int mbase = (wid >> 1) * 16, nbase = (wid & 1) * 64;
    const int e0 = blockIdx.x * MROWS;
    const int grow = tid >> 2, gqb = (tid & 3) * 8;
    const unsigned char* wbase = g_we + 2 * WCHUNK;  // chunks W1c, W2, W3

    fill_half(smb + SM_BB0, wbase, tid);       CP_COMMIT();
    fill_half(smb + SM_BB1, wbase + HB, tid);  CP_COMMIT();

    // ea gather (A operand for chunk 0)
    float4 preA[8];
    issue_gather(preA, (const float4*)ea, (long long)(e0 + grow), gqb);

    // acc init = P[i] + Q[j] at this thread's fragment positions
    float acc[8][4];
    {
        const int q = lane & 3, r = lane >> 2;
        const int row0 = mbase + r, row1 = row0 + 8;
        const size_t i0 = (size_t)__ldg(eidx + e0 + row0) * 128;
        const size_t i1 = (size_t)__ldg(eidx + e0 + row1) * 128;
        const size_t j0 = (size_t)__ldg(eidx + NE + e0 + row0) * 128;
        const size_t j1 = (size_t)__ldg(eidx + NE + e0 + row1) * 128;
#pragma unroll
        for (int ng = 0; ng < 8; ++ng) {
            const int col = nbase + ng * 8 + q * 2;
            float2 p0 = __ldg((const float2*)(g_P + i0 + col));
            float2 q0 = __ldg((const float2*)(g_Q + j0 + col));
            float2 p1 = __ldg((const float2*)(g_P + i1 + col));
            float2 q1 = __ldg((const float2*)(g_Q + j1 + col));
            acc[ng][0] = p0.x + q0.x;
            acc[ng][1] = p0.y + q0.y;
            acc[ng][2] = p1.x + q1.x;
            acc[ng][3] = p1.y + q1.y;
        }
    }
    convert_gather(sm, preA, grow, gqb);

    // 3 chunks = 6 half-steps
#pragma unroll 1
    for (int t = 0; t < 6; ++t) {
        const u32 bbuf = smb + SM_BB0 + (u32)(t & 1) * HB;
        if (t < 5) { CP_WAIT(1); } else { CP_WAIT(0); }
        __syncthreads();
        if (t & 1) mma_odd(smb, bbuf, acc, mbase, nbase, lane);
        else       mma_even(smb, bbuf, acc, mbase, nbase, lane);
        __syncthreads();
        if (t + 2 < 6) {
            fill_half(bbuf, wbase + (size_t)(t + 2) * HB, tid);
            CP_COMMIT();
        }
        if (t == 1)      mid_epi(sm, acc, b1, mbase, nbase, lane);
        else if (t == 3) mid_epi(sm, acc, b2, mbase, nbase, lane);
    }

    // ---- final: bias3 -> LN -> residual -> store + scatter ----
    final_dump(sm, acc, b3, mbase, nbase, lane);
    __syncthreads();
    ln_stats(sm, tid);
    __syncthreads();

    {
        const int tc = tid & 15, tr = tid >> 4;
        const float* sv = (const float*)sm;
        const float* smean = (const float*)(sm + SM_BB0);
        const float* srstd = (const float*)(sm + SM_BB0 + 256);
        float gv[8], bv[8];
#pragma unroll
        for (int j = 0; j < 8; ++j) {
            gv[j] = __ldg(gw + tc * 8 + j);
            bv[j] = __ldg(bw + tc * 8 + j);
        }
        for (int r4 = 0; r4 < 4; ++r4) {
            const int row = r4 * 16 + tr;
            const long long gr = e0 + row;
            const float mean = smean[row], rstd = srstd[row];
            float4 ra = __ldg((const float4*)ea + gr * 32 + tc * 2);
            float4 rb = __ldg((const float4*)ea + gr * 32 + tc * 2 + 1);
            float o[8];
#pragma unroll
            for (int j = 0; j < 8; ++j)
                o[j] = (sv[row * SVS + tc * 8 + j] - mean) * rstd * gv[j] + bv[j];
            o[0] += ra.x; o[1] += ra.y; o[2] += ra.z; o[3] += ra.w;
            o[4] += rb.x; o[5] += rb.y; o[6] += rb.z; o[7] += rb.w;
            ((float4*)out_e)[gr * 32 + tc * 2]     = make_float4(o[0], o[1], o[2], o[3]);
            ((float4*)out_e)[gr * 32 + tc * 2 + 1] = make_float4(o[4], o[5], o[6], o[7]);
            const int dj = __ldg(eidx + NE + gr);
            float* ap = g_agg + (size_t)dj * 128 + tc * 8;
            red4(ap,     o[0], o[1], o[2], o[3]);
            red4(ap + 4, o[4], o[5], o[6], o[7]);
        }
    }
}

// ---------------------------------------------------------------------------
// Node kernel: 64 nodes/block, 256 threads, 2 blocks/SM (unchanged)
// ---------------------------------------------------------------------------
__global__ __launch_bounds__(NTHREADS, 2)
void node_kernel(const float* __restrict__ x,
                 const float* __restrict__ b1, const float* __restrict__ b2,
                 const float* __restrict__ b3,
                 const float* __restrict__ gw, const float* __restrict__ bw,
                 float* __restrict__ out_x) {
    extern __shared__ char sm[];
    const u32 smb = smem_u32(sm);
    const int tid = threadIdx.x, wid = tid >> 5, lane = tid & 31;
    const int mbase = (wid >> 1) * 16, nbase = (wid & 1) * 64;
    const int n0 = blockIdx.x * MROWS;
    const int grow = tid >> 2, gqb = (tid & 3) * 8;

    float acc[8][4];
#pragma unroll
    for (int ng = 0; ng < 8; ++ng)
#pragma unroll
        for (int k = 0; k < 4; ++k) acc[ng][k] = 0.f;

    fill_half(smb + SM_BB0, g_wn, tid);       CP_COMMIT();
    fill_half(smb + SM_BB1, g_wn + HB, tid);  CP_COMMIT();

    float4 pre[8];
    issue_gather_guard(pre, (const float4*)x, n0 + grow, gqb);
    convert_gather(sm, pre, grow, gqb);
    issue_gather_guard(pre, (const float4*)g_agg, n0 + grow, gqb);

    // 4 chunks = 8 half-steps
#pragma unroll 1
    for (int t = 0; t < 8; ++t) {
        const u32 bbuf = smb + SM_BB0 + (u32)(t & 1) * HB;
        if (t < 7) { CP_WAIT(1); } else { CP_WAIT(0); }
        __syncthreads();
        if (t & 1) mma_odd(smb, bbuf, acc, mbase, nbase, lane);
        else       mma_even(smb, bbuf, acc, mbase, nbase, lane);
        __syncthreads();
        if (t + 2 < 8) {
            fill_half(bbuf, g_wn + (size_t)(t + 2) * HB, tid);
            CP_COMMIT();
        }
        if (t & 1) {
            const int s = t >> 1;
            if (s == 0) {
                convert_gather(sm, pre, grow, gqb);
            } else if (s == 1) {
                mid_epi(sm, acc, b1, mbase, nbase, lane);
            } else if (s == 2) {
                mid_epi(sm, acc, b2, mbase, nbase, lane);
            }
        }
    }

    final_dump(sm, acc, b3, mbase, nbase, lane);
    __syncthreads();
    ln_stats(sm, tid);
    __syncthreads();

    {
        const int tc = tid & 15, tr = tid >> 4;
        const float* sv = (const float*)sm;
        const float* smean = (const float*)(sm + SM_BB0);
        const float* srstd = (const float*)(sm + SM_BB0 + 256);
        float gv[8], bv[8];
#pragma unroll
        for (int j = 0; j < 8; ++j) {
            gv[j] = __ldg(gw + tc * 8 + j);
            bv[j] = __ldg(bw + tc * 8 + j);
        }
        for (int r4 = 0; r4 < 4; ++r4) {
            const int row = r4 * 16 + tr;
            const long long gr = n0 + row;
            if (gr < NN) {
                const float mean = smean[row], rstd = srstd[row];
                float4 ra = __ldg((const float4*)x + gr * 32 + tc * 2);
                float4 rb = __ldg((const float4*)x + gr * 32 + tc * 2 + 1);
                float o[8];
#pragma unroll
                for (int j = 0; j < 8; ++j)
                    o[j] = (sv[row * SVS + tc * 8 + j] - mean) * rstd * gv[j] + bv[j];
                o[0] += ra.x; o[1] += ra.y; o[2] += ra.z; o[3] += ra.w;
                o[4] += rb.x; o[5] += rb.y; o[6] += rb.z; o[7] += rb.w;
                ((float4*)out_x)[gr * 32 + tc * 2]     = make_float4(o[0], o[1], o[2], o[3]);
                ((float4*)out_x)[gr * 32 + tc * 2 + 1] = make_float4(o[4], o[5], o[6], o[7]);
            }
        }
    }
}

// ---------------------------------------------------------------------------
// Weight prep: split into bf16 hi/lo, transpose to [n][k], row stride 272B.
// ---------------------------------------------------------------------------
__global__ void prep_w(const float* __restrict__ ew1, const float* __restrict__ ew2,
                       const float* __restrict__ ew3, const float* __restrict__ nw1,
                       const float* __restrict__ nw2, const float* __restrict__ nw3) {
    int i = blockIdx.x * blockDim.x + threadIdx.x;
    if (i >= 9 * 16384) return;
    unsigned char* dst;
    float val;
    int cs = i >> 14, r = i & 16383;
    int kl = r >> 7, n = r & 127;
    if (cs < 5) {
        if (cs < 3)       val = ew1[(cs * 128 + kl) * 128 + n];
        else if (cs == 3) val = ew2[kl * 128 + n];
        else              val = ew3[kl * 128 + n];
        dst = g_we + (size_t)cs * WCHUNK;
    } else {
        int ns = cs - 5;
        if (ns < 2)       val = nw1[(ns * 128 + kl) * 128 + n];
        else if (ns == 2) val = nw2[kl * 128 + n];
        else              val = nw3[kl * 128 + n];
        dst = g_wn + (size_t)ns * WCHUNK;
    }
    u32 h = pack_bf16x2(val, 0.f);
    u32 l = pack_bf16x2(val - bf_lo_f(h), 0.f);
    *(unsigned short*)(dst + n * ROWB + kl * 2)      = (unsigned short)(h & 0xffff);
    *(unsigned short*)(dst + HB + n * ROWB + kl * 2) = (unsigned short)(l & 0xffff);
}

__global__ void zero_agg_kernel() {
    int i = blockIdx.x * blockDim.x + threadIdx.x;
    if (i < NN * 32)
        ((float4*)g_agg)[i] = make_float4(0.f, 0.f, 0.f, 0.f);
}

// ---------------------------------------------------------------------------
extern "C" void kernel_launch(void* const* d_in, const int* in_sizes, int n_in,
                              void* d_out, int out_size) {
    const float* x    = (const float*)d_in[0];
    const int*   eidx = (const int*)d_in[1];
    const float* ea   = (const float*)d_in[2];
    const float* ew1  = (const float*)d_in[3];
    const float* eb1  = (const float*)d_in[4];
    const float* ew2  = (const float*)d_in[5];
    const float* eb2  = (const float*)d_in[6];
    const float* ew3  = (const float*)d_in[7];
    const float* eb3  = (const float*)d_in[8];
    const float* eg   = (const float*)d_in[9];
    const float* ebt  = (const float*)d_in[10];
    const float* nw1  = (const float*)d_in[11];
    const float* nb1  = (const float*)d_in[12];
    const float* nw2  = (const float*)d_in[13];
    const float* nb2  = (const float*)d_in[14];
    const float* nw3  = (const float*)d_in[15];
    const float* nb3  = (const float*)d_in[16];
    const float* ng   = (const float*)d_in[17];
    const float* nbt  = (const float*)d_in[18];

    float* out_x = (float*)d_out;                       // [50000, 128]
    float* out_e = (float*)d_out + (size_t)NN * 128;    // [800000, 128]

    cudaFuncSetAttribute(pq_kernel,   cudaFuncAttributeMaxDynamicSharedMemorySize, SM_BYTES);
    cudaFuncSetAttribute(edge_kernel, cudaFuncAttributeMaxDynamicSharedMemorySize, SM_BYTES);
    cudaFuncSetAttribute(node_kernel, cudaFuncAttributeMaxDynamicSharedMemorySize, SM_BYTES);

    zero_agg_kernel<<<(NN * 32 + 255) / 256, 256>>>();
    prep_w<<<(9 * 16384 + 255) / 256, 256>>>(ew1, ew2, ew3, nw1, nw2, nw3);
    pq_kernel<<<(NN + MROWS - 1) / MROWS, NTHREADS, SM_BYTES>>>(x);
    edge_kernel<<<NE / MROWS, NTHREADS, SM_BYTES>>>(eidx, ea, eb1, eb2, eb3, eg, ebt, out_e);
    node_kernel<<<(NN + MROWS - 1) / MROWS, NTHREADS, SM_BYTES>>>(x, nb1, nb2, nb3, ng, nbt, out_x);
}

// round 14
// speedup vs baseline: 1.6614x; 1.0658x over previous
#include <cuda_runtime.h>

#define NN 50000
#define NE 800000

typedef unsigned int u32;
typedef unsigned long long u64;

// ---------------------------------------------------------------------------
// Device scratch (no cudaMalloc allowed)
// ---------------------------------------------------------------------------
__device__ float g_agg[(size_t)NN * 128];
__device__ float g_P[(size_t)NN * 128];   // x @ W1a (edge layer-1, x_i part)
__device__ float g_Q[(size_t)NN * 128];   // x @ W1b (edge layer-1, x_j part)
// Pre-split bf16 weights, transposed to [n][k], row stride 272B.
// Chunk = [hi 34816][lo 34816].
#define HB 34816
#define WCHUNK (2 * HB)
__device__ __align__(16) unsigned char g_we[5 * WCHUNK]; // W1a,W1b,W1c,W2,W3
__device__ __align__(16) unsigned char g_wn[4 * WCHUNK]; // node: L1 x2, L2, L3

// ---------------------------------------------------------------------------
// SMEM: A_hi, A_lo (64 rows), two B half-buffers. 104448 B -> 2 blocks/SM.
// ---------------------------------------------------------------------------
#define ROWB 272
#define SM_AHI 0
#define SM_ALO 17408             // 64*272
#define SM_BB0 34816
#define SM_BB1 (34816 + HB)      // 69632
#define SM_BYTES (34816 + 2 * HB) // 104448

#define MROWS 64
#define NTHREADS 256

// ---------------------------------------------------------------------------
// Helpers
// ---------------------------------------------------------------------------
__device__ __forceinline__ u32 smem_u32(const void* p) {
    u32 a;
    asm("{ .reg .u64 t; cvta.to.shared.u64 t, %1; cvt.u32.u64 %0, t; }"
        : "=r"(a) : "l"(p));
    return a;
}
__device__ __forceinline__ u32 pack_bf16x2(float e0, float e1) {
    u32 r;
    asm("cvt.rn.bf16x2.f32 %0, %1, %2;" : "=r"(r) : "f"(e1), "f"(e0));
    return r;
}
__device__ __forceinline__ float bf_lo_f(u32 p) { return __uint_as_float(p << 16); }
__device__ __forceinline__ float bf_hi_f(u32 p) { return __uint_as_float(p & 0xffff0000u); }
__device__ __forceinline__ float silu_f(float v) { return __fdividef(v, 1.0f + __expf(-v)); }

__device__ __forceinline__ void ldsm4(u32& r0, u32& r1, u32& r2, u32& r3, u32 addr) {
    asm volatile("ldmatrix.sync.aligned.m8n8.x4.shared.b16 {%0,%1,%2,%3}, [%4];"
                 : "=r"(r0), "=r"(r1), "=r"(r2), "=r"(r3) : "r"(addr));
}
__device__ __forceinline__ void mma16816(float* c, const u32* a, u32 b0, u32 b1) {
    asm volatile(
        "mma.sync.aligned.m16n8k16.row.col.f32.bf16.bf16.f32 "
        "{%0,%1,%2,%3}, {%4,%5,%6,%7}, {%8,%9}, {%0,%1,%2,%3};"
        : "+f"(c[0]), "+f"(c[1]), "+f"(c[2]), "+f"(c[3])
        : "r"(a[0]), "r"(a[1]), "r"(a[2]), "r"(a[3]), "r"(b0), "r"(b1));
}
__device__ __forceinline__ void split4(float v0, float v1, float v2, float v3,
                                       u64& hi, u64& lo) {
    u32 h0 = pack_bf16x2(v0, v1), h1 = pack_bf16x2(v2, v3);
    u32 l0 = pack_bf16x2(v0 - bf_lo_f(h0), v1 - bf_hi_f(h0));
    u32 l1 = pack_bf16x2(v2 - bf_lo_f(h1), v3 - bf_hi_f(h1));
    hi = (u64)h0 | ((u64)h1 << 32);
    lo = (u64)l0 | ((u64)l1 << 32);
}
__device__ __forceinline__ void red2(float* p, float a, float b) {
    asm volatile("red.global.add.v2.f32 [%0], {%1,%2};"
                 :: "l"(p), "f"(a), "f"(b) : "memory");
}

// ---- register gather prefetch (8 float4 per thread) ----
__device__ __forceinline__ void issue_gather(float4* pre, const float4* src,
                                             long long g, int qb) {
#pragma unroll
    for (int i = 0; i < 8; ++i)
        pre[i] = __ldg(src + g * 32 + qb + i);
}
__device__ __forceinline__ void issue_gather_guard(float4* pre, const float4* src,
                                                   int g, int qb) {
#pragma unroll
    for (int i = 0; i < 8; ++i) {
        float4 v = make_float4(0.f, 0.f, 0.f, 0.f);
        if (g < NN) v = __ldg(src + (size_t)g * 32 + qb + i);
        pre[i] = v;
    }
}
__device__ __forceinline__ void convert_gather(char* sm, const float4* pre,
                                               int row, int qb) {
#pragma unroll
    for (int i = 0; i < 8; ++i) {
        u64 hi, lo;
        split4(pre[i].x, pre[i].y, pre[i].z, pre[i].w, hi, lo);
        *(u64*)(sm + SM_AHI + row * ROWB + (qb + i) * 8) = hi;
        *(u64*)(sm + SM_ALO + row * ROWB + (qb + i) * 8) = lo;
    }
}

// ---- cp.async ----
__device__ __forceinline__ void cp16(u32 dst, const void* src) {
    asm volatile("cp.async.cg.shared.global [%0], [%1], 16;" :: "r"(dst), "l"(src));
}
#define CP_COMMIT() asm volatile("cp.async.commit_group;" ::: "memory")
#define CP_WAIT(n)  asm volatile("cp.async.wait_group %0;" :: "n"(n) : "memory")

__device__ __forceinline__ void fill_half(u32 dst, const unsigned char* w, int tid) {
#pragma unroll
    for (int i = 0; i < 9; ++i) {
        int t = tid + i * NTHREADS;
        if (t < HB / 16) cp16(dst + t * 16, w + t * 16);
    }
}

// ---------------------------------------------------------------------------
// MMA halves over one 128-K chunk. Warp tile 16x64. acc[8][4].
// ---------------------------------------------------------------------------
__device__ __forceinline__ void mma_even(u32 smb, u32 bbuf, float acc[8][4],
                                         int mbase, int nbase, int lane) {
    const u32 a_off = (u32)(mbase + (lane & 15)) * ROWB + (u32)(lane >> 4) * 16;
    const u32 b_off = (u32)(nbase + (lane & 7) + ((lane >> 4) & 1) * 8) * ROWB
                    + (u32)((lane >> 3) & 1) * 16;
#pragma unroll
    for (int ks = 0; ks < 8; ++ks) {
        const u32 kb = (u32)ks * 32;
        u32 ah[4], al[4], b[4][4];
        ldsm4(ah[0], ah[1], ah[2], ah[3], smb + SM_AHI + a_off + kb);
#pragma unroll
        for (int g = 0; g < 4; ++g)
            ldsm4(b[g][0], b[g][1], b[g][2], b[g][3],
                  bbuf + b_off + (u32)g * (16 * ROWB) + kb);
#pragma unroll
        for (int ng = 0; ng < 8; ++ng)
            mma16816(acc[ng], ah, b[ng >> 1][(ng & 1) * 2], b[ng >> 1][(ng & 1) * 2 + 1]);
        ldsm4(al[0], al[1], al[2], al[3], smb + SM_ALO + a_off + kb);
#pragma unroll
        for (int ng = 0; ng < 8; ++ng)
            mma16816(acc[ng], al, b[ng >> 1][(ng & 1) * 2], b[ng >> 1][(ng & 1) * 2 + 1]);
    }
}

__device__ __forceinline__ void mma_odd(u32 smb, u32 bbuf, float acc[8][4],
                                        int mbase, int nbase, int lane) {
    const u32 a_off = (u32)(mbase + (lane & 15)) * ROWB + (u32)(lane >> 4) * 16;
    const u32 b_off = (u32)(nbase + (lane & 7) + ((lane >> 4) & 1) * 8) * ROWB
                    + (u32)((lane >> 3) & 1) * 16;
#pragma unroll
    for (int ks = 0; ks < 8; ++ks) {
        const u32 kb = (u32)ks * 32;
        u32 ah[4], b[4][4];
        ldsm4(ah[0], ah[1], ah[2], ah[3], smb + SM_AHI + a_off + kb);
#pragma unroll
        for (int g = 0; g < 4; ++g)
            ldsm4(b[g][0], b[g][1], b[g][2], b[g][3],
                  bbuf + b_off + (u32)g * (16 * ROWB) + kb);
#pragma unroll
        for (int ng = 0; ng < 8; ++ng)
            mma16816(acc[ng], ah, b[ng >> 1][(ng & 1) * 2], b[ng >> 1][(ng & 1) * 2 + 1]);
    }
}

// bias + SiLU from acc -> A smem (hi/lo), zero acc
__device__ __forceinline__ void mid_epi(char* sm, float acc[8][4],
                                        const float* __restrict__ bias,
                                        int mbase, int nbase, int lane) {
    const int q = lane & 3, r = lane >> 2;
#pragma unroll
    for (int ng = 0; ng < 8; ++ng) {
        const int col = nbase + ng * 8 + q * 2;
        const float bx = __ldg(bias + col), by = __ldg(bias + col + 1);
        const int r0 = mbase + r, r1 = r0 + 8;
        float v0 = silu_f(acc[ng][0] + bx);
        float v1 = silu_f(acc[ng][1] + by);
        float v2 = silu_f(acc[ng][2] + bx);
        float v3 = silu_f(acc[ng][3] + by);
        u32 h0 = pack_bf16x2(v0, v1);
        u32 l0 = pack_bf16x2(v0 - bf_lo_f(h0), v1 - bf_hi_f(h0));
        u32 h1 = pack_bf16x2(v2, v3);
        u32 l1 = pack_bf16x2(v2 - bf_lo_f(h1), v3 - bf_hi_f(h1));
        *(u32*)(sm + SM_AHI + r0 * ROWB + col * 2) = h0;
        *(u32*)(sm + SM_ALO + r0 * ROWB + col * 2) = l0;
        *(u32*)(sm + SM_AHI + r1 * ROWB + col * 2) = h1;
        *(u32*)(sm + SM_ALO + r1 * ROWB + col * 2) = l1;
        acc[ng][0] = 0.f; acc[ng][1] = 0.f;
        acc[ng][2] = 0.f; acc[ng][3] = 0.f;
    }
}

// In-register LN: bias + per-row stats via 4-lane butterfly + cross-warp
// exchange in SM_BB0 (free after last MMA). Returns mean/rstd for both rows.
__device__ __forceinline__ void ln_reg(char* sm, float acc[8][4],
                                       const float* __restrict__ b3,
                                       int nbase, int q, int r0, int r1,
                                       float& m0, float& rs0, float& m1, float& rs1) {
    float s1a = 0.f, s2a = 0.f, s1b = 0.f, s2b = 0.f;
#pragma unroll
    for (int ng = 0; ng < 8; ++ng) {
        const int col = nbase + ng * 8 + q * 2;
        const float bx = __ldg(b3 + col), by = __ldg(b3 + col + 1);
        float v0 = acc[ng][0] + bx, v1 = acc[ng][1] + by;
        float v2 = acc[ng][2] + bx, v3 = acc[ng][3] + by;
        acc[ng][0] = v0; acc[ng][1] = v1; acc[ng][2] = v2; acc[ng][3] = v3;
        s1a += v0 + v1; s2a += v0 * v0 + v1 * v1;
        s1b += v2 + v3; s2b += v2 * v2 + v3 * v3;
    }
#pragma unroll
    for (int m = 1; m <= 2; m <<= 1) {
        s1a += __shfl_xor_sync(0xffffffffu, s1a, m, 32);
        s2a += __shfl_xor_sync(0xffffffffu, s2a, m, 32);
        s1b += __shfl_xor_sync(0xffffffffu, s1b, m, 32);
        s2b += __shfl_xor_sync(0xffffffffu, s2b, m, 32);
    }
    float2* ex = (float2*)(sm + SM_BB0);   // [64 rows][2 halves]
    const int half = nbase >> 6;
    if (q == 0) {
        ex[r0 * 2 + half] = make_float2(s1a, s2a);
        ex[r1 * 2 + half] = make_float2(s1b, s2b);
    }
    __syncthreads();
    float2 a0 = ex[r0 * 2], a1 = ex[r0 * 2 + 1];
    float2 b0 = ex[r1 * 2], b1 = ex[r1 * 2 + 1];
    m0 = (a0.x + a1.x) * (1.0f / 128.0f);
    float v0 = (a0.y + a1.y) * (1.0f / 128.0f) - m0 * m0;
    rs0 = rsqrtf(v0 + 1e-5f);
    m1 = (b0.x + b1.x) * (1.0f / 128.0f);
    float v1 = (b0.y + b1.y) * (1.0f / 128.0f) - m1 * m1;
    rs1 = rsqrtf(v1 + 1e-5f);
}

// ---------------------------------------------------------------------------
// PQ precompute: P = x@W1a, Q = x@W1b (64 rows/block, 256 threads)
// ---------------------------------------------------------------------------
__device__ __forceinline__ void store_pq(float* dst, float acc[8][4],
                                         int n0, int mbase, int nbase, int lane) {
    const int q = lane & 3, r = lane >> 2;
#pragma unroll
    for (int ng = 0; ng < 8; ++ng) {
        const int col = nbase + ng * 8 + q * 2;
        const int r0 = mbase + r, r1 = r0 + 8;
        if (n0 + r0 < NN)
            *(float2*)(dst + (size_t)(n0 + r0) * 128 + col) = make_float2(acc[ng][0], acc[ng][1]);
        if (n0 + r1 < NN)
            *(float2*)(dst + (size_t)(n0 + r1) * 128 + col) = make_float2(acc[ng][2], acc[ng][3]);
        acc[ng][0] = 0.f; acc[ng][1] = 0.f;
        acc[ng][2] = 0.f; acc[ng][3] = 0.f;
    }
}

__global__ __launch_bounds__(NTHREADS, 2)
void pq_kernel(const float* __restrict__ x) {
    extern __shared__ char sm[];
    const u32 smb = smem_u32(sm);
    const int tid = threadIdx.x, wid = tid >> 5, lane = tid & 31;
    const int mbase = (wid >> 1) * 16, nbase = (wid & 1) * 64;
    const int n0 = blockIdx.x * MROWS;
    const int grow = tid >> 2, gqb = (tid & 3) * 8;

    float acc[8][4];
#pragma unroll
    for (int ng = 0; ng < 8; ++ng)
#pragma unroll
        for (int k = 0; k < 4; ++k) acc[ng][k] = 0.f;

    fill_half(smb + SM_BB0, g_we, tid);       CP_COMMIT();
    fill_half(smb + SM_BB1, g_we + HB, tid);  CP_COMMIT();

    float4 pre[8];
    issue_gather_guard(pre, (const float4*)x, n0 + grow, gqb);
    convert_gather(sm, pre, grow, gqb);

    // 2 chunks (W1a, W1b) = 4 half-steps; same A both chunks
#pragma unroll 1
    for (int t = 0; t < 4; ++t) {
        const u32 bbuf = smb + SM_BB0 + (u32)(t & 1) * HB;
        if (t < 3) { CP_WAIT(1); } else { CP_WAIT(0); }
        __syncthreads();
        if (t & 1) mma_odd(smb, bbuf, acc, mbase, nbase, lane);
        else       mma_even(smb, bbuf, acc, mbase, nbase, lane);
        __syncthreads();
        if (t + 2 < 4) {
            fill_half(bbuf, g_we + (size_t)(t + 2) * HB, tid);
            CP_COMMIT();
        }
        if (t == 1) store_pq(g_P, acc, n0, mbase, nbase, lane);
    }
    store_pq(g_Q, acc, n0, mbase, nbase, lane);
}

// ---------------------------------------------------------------------------
// Edge kernel: 64 edges/block, 256 threads, 3 MMA chunks (W1c, W2, W3).
// Layer-1 acc initialized from P[i]/Q[j] fragment loads (issued first).
// ---------------------------------------------------------------------------
__global__ __launch_bounds__(NTHREADS, 2)
void edge_kernel(const int* __restrict__ eidx,
                 const float* __restrict__ ea,
                 const float* __restrict__ b1, const float* __restrict__ b2,
                 const float* __restrict__ b3,
                 const float* __restrict__ gw, const float* __restrict__ bw,
                 float* __restrict__ out_e) {
    extern __shared__ char sm[];
    const u32 smb = smem_u32(sm);
    const int tid = threadIdx.x, wid = tid >> 5, lane = tid & 31;
    const int mbase = (wid >> 1) * 16, nbase = (wid & 1) * 64;
    const int e0 = blockIdx.x * MROWS;
    const int grow = tid >> 2, gqb = (tid & 3) * 8;
    const int q = lane & 3, r = lane >> 2;
    const int row0 = mbase + r, row1 = row0 + 8;
    const unsigned char* wbase = g_we + 2 * WCHUNK;  // chunks W1c, W2, W3

    // acc init = P[i] + Q[j] at fragment positions — issued FIRST so the
    // scattered LDG latency hides under fills/convert below.
    float acc[8][4];
    {
        const size_t i0 = (size_t)__ldg(eidx + e0 + row0) * 128;
        const size_t i1 = (size_t)__ldg(eidx + e0 + row1) * 128;
        const size_t j0 = (size_t)__ldg(eidx + NE + e0 + row0) * 128;
        const size_t j1 = (size_t)__ldg(eidx + NE + e0 + row1) * 128;
#pragma unroll
        for (int ng = 0; ng < 8; ++ng) {
            const int col = nbase + ng * 8 + q * 2;
            float2 p0 = __ldg((const float2*)(g_P + i0 + col));
            float2 q0 = __ldg((const float2*)(g_Q + j0 + col));
            float2 p1 = __ldg((const float2*)(g_P + i1 + col));
            float2 q1 = __ldg((const float2*)(g_Q + j1 + col));
            acc[ng][0] = p0.x + q0.x;
            acc[ng][1] = p0.y + q0.y;
            acc[ng][2] = p1.x + q1.x;
            acc[ng][3] = p1.y + q1.y;
        }
    }

    fill_half(smb + SM_BB0, wbase, tid);       CP_COMMIT();
    fill_half(smb + SM_BB1, wbase + HB, tid);  CP_COMMIT();

    float4 preA[8];
    issue_gather(preA, (const float4*)ea, (long long)(e0 + grow), gqb);
    convert_gather(sm, preA, grow, gqb);

    // 3 chunks = 6 half-steps
#pragma unroll 1
    for (int t = 0; t < 6; ++t) {
        const u32 bbuf = smb + SM_BB0 + (u32)(t & 1) * HB;
        if (t < 5) { CP_WAIT(1); } else { CP_WAIT(0); }
        __syncthreads();
        if (t & 1) mma_odd(smb, bbuf, acc, mbase, nbase, lane);
        else       mma_even(smb, bbuf, acc, mbase, nbase, lane);
        __syncthreads();
        if (t + 2 < 6) {
            fill_half(bbuf, wbase + (size_t)(t + 2) * HB, tid);
            CP_COMMIT();
        }
        if (t == 1)      mid_epi(sm, acc, b1, mbase, nbase, lane);
        else if (t == 3) mid_epi(sm, acc, b2, mbase, nbase, lane);
    }

    // ---- final: in-register bias3 + LN, then residual/store/scatter ----
    float m0, rs0, m1, rs1;
    ln_reg(sm, acc, b3, nbase, q, row0, row1, m0, rs0, m1, rs1);

    {
        const long long gr0 = e0 + row0, gr1 = e0 + row1;
        const int dj0 = __ldg(eidx + NE + gr0);
        const int dj1 = __ldg(eidx + NE + gr1);
        float* ap0 = g_agg + (size_t)dj0 * 128;
        float* ap1 = g_agg + (size_t)dj1 * 128;
#pragma unroll
        for (int ng = 0; ng < 8; ++ng) {
            const int col = nbase + ng * 8 + q * 2;
            float2 gv = *(const float2*)(gw + col);
            float2 bv = *(const float2*)(bw + col);
            float2 ra0 = __ldg((const float2*)(ea + gr0 * 128 + col));
            float2 ra1 = __ldg((const float2*)(ea + gr1 * 128 + col));
            float o0 = (acc[ng][0] - m0) * rs0 * gv.x + bv.x + ra0.x;
            float o1 = (acc[ng][1] - m0) * rs0 * gv.y + bv.y + ra0.y;
            float o2 = (acc[ng][2] - m1) * rs1 * gv.x + bv.x + ra1.x;
            float o3 = (acc[ng][3] - m1) * rs1 * gv.y + bv.y + ra1.y;
            *(float2*)(out_e + gr0 * 128 + col) = make_float2(o0, o1);
            *(float2*)(out_e + gr1 * 128 + col) = make_float2(o2, o3);
            red2(ap0 + col, o0, o1);
            red2(ap1 + col, o2, o3);
        }
    }
}

// ---------------------------------------------------------------------------
// Node kernel: 64 nodes/block, 256 threads, 2 blocks/SM
// ---------------------------------------------------------------------------
__global__ __launch_bounds__(NTHREADS, 2)
void node_kernel(const float* __restrict__ x,
                 const float* __restrict__ b1, const float* __restrict__ b2,
                 const float* __restrict__ b3,
                 const float* __restrict__ gw, const float* __restrict__ bw,
                 float* __restrict__ out_x) {
    extern __shared__ char sm[];
    const u32 smb = smem_u32(sm);
    const int tid = threadIdx.x, wid = tid >> 5, lane = tid & 31;
    const int mbase = (wid >> 1) * 16, nbase = (wid & 1) * 64;
    const int n0 = blockIdx.x * MROWS;
    const int grow = tid >> 2, gqb = (tid & 3) * 8;
    const int q = lane & 3, r = lane >> 2;
    const int row0 = mbase + r, row1 = row0 + 8;

    float acc[8][4];
#pragma unroll
    for (int ng = 0; ng < 8; ++ng)
#pragma unroll
        for (int k = 0; k < 4; ++k) acc[ng][k] = 0.f;

    fill_half(smb + SM_BB0, g_wn, tid);       CP_COMMIT();
    fill_half(smb + SM_BB1, g_wn + HB, tid);  CP_COMMIT();

    float4 pre[8];
    issue_gather_guard(pre, (const float4*)x, n0 + grow, gqb);
    convert_gather(sm, pre, grow, gqb);
    issue_gather_guard(pre, (const float4*)g_agg, n0 + grow, gqb);

    // 4 chunks = 8 half-steps
#pragma unroll 1
    for (int t = 0; t < 8; ++t) {
        const u32 bbuf = smb + SM_BB0 + (u32)(t & 1) * HB;
        if (t < 7) { CP_WAIT(1); } else { CP_WAIT(0); }
        __syncthreads();
        if (t & 1) mma_odd(smb, bbuf, acc, mbase, nbase, lane);
        else       mma_even(smb, bbuf, acc, mbase, nbase, lane);
        __syncthreads();
        if (t + 2 < 8) {
            fill_half(bbuf, g_wn + (size_t)(t + 2) * HB, tid);
            CP_COMMIT();
        }
        if (t & 1) {
            const int s = t >> 1;
            if (s == 0) {
                convert_gather(sm, pre, grow, gqb);
            } else if (s == 1) {
                mid_epi(sm, acc, b1, mbase, nbase, lane);
            } else if (s == 2) {
                mid_epi(sm, acc, b2, mbase, nbase, lane);
            }
        }
    }

    // ---- final: in-register bias3 + LN, residual + store ----
    float m0, rs0, m1, rs1;
    ln_reg(sm, acc, b3, nbase, q, row0, row1, m0, rs0, m1, rs1);

    {
        const long long gr0 = n0 + row0, gr1 = n0 + row1;
        const bool ok0 = gr0 < NN, ok1 = gr1 < NN;
#pragma unroll
        for (int ng = 0; ng < 8; ++ng) {
            const int col = nbase + ng * 8 + q * 2;
            float2 gv = *(const float2*)(gw + col);
            float2 bv = *(const float2*)(bw + col);
            if (ok0) {
                float2 ra = __ldg((const float2*)(x + gr0 * 128 + col));
                float o0 = (acc[ng][0] - m0) * rs0 * gv.x + bv.x + ra.x;
                float o1 = (acc[ng][1] - m0) * rs0 * gv.y + bv.y + ra.y;
                *(float2*)(out_x + gr0 * 128 + col) = make_float2(o0, o1);
            }
            if (ok1) {
                float2 ra = __ldg((const float2*)(x + gr1 * 128 + col));
                float o2 = (acc[ng][2] - m1) * rs1 * gv.x + bv.x + ra.x;
                float o3 = (acc[ng][3] - m1) * rs1 * gv.y + bv.y + ra.y;
                *(float2*)(out_x + gr1 * 128 + col) = make_float2(o2, o3);
            }
        }
    }
}

// ---------------------------------------------------------------------------
// Weight prep: split into bf16 hi/lo, transpose to [n][k], row stride 272B.
// ---------------------------------------------------------------------------
__global__ void prep_w(const float* __restrict__ ew1, const float* __restrict__ ew2,
                       const float* __restrict__ ew3, const float* __restrict__ nw1,
                       const float* __restrict__ nw2, const float* __restrict__ nw3) {
    int i = blockIdx.x * blockDim.x + threadIdx.x;
    if (i >= 9 * 16384) return;
    unsigned char* dst;
    float val;
    int cs = i >> 14, r = i & 16383;
    int kl = r >> 7, n = r & 127;
    if (cs < 5) {
        if (cs < 3)       val = ew1[(cs * 128 + kl) * 128 + n];
        else if (cs == 3) val = ew2[kl * 128 + n];
        else              val = ew3[kl * 128 + n];
        dst = g_we + (size_t)cs * WCHUNK;
    } else {
        int ns = cs - 5;
        if (ns < 2)       val = nw1[(ns * 128 + kl) * 128 + n];
        else if (ns == 2) val = nw2[kl * 128 + n];
        else              val = nw3[kl * 128 + n];
        dst = g_wn + (size_t)ns * WCHUNK;
    }
    u32 h = pack_bf16x2(val, 0.f);
    u32 l = pack_bf16x2(val - bf_lo_f(h), 0.f);
    *(unsigned short*)(dst + n * ROWB + kl * 2)      = (unsigned short)(h & 0xffff);
    *(unsigned short*)(dst + HB + n * ROWB + kl * 2) = (unsigned short)(l & 0xffff);
}

__global__ void zero_agg_kernel() {
    int i = blockIdx.x * blockDim.x + threadIdx.x;
    if (i < NN * 32)
        ((float4*)g_agg)[i] = make_float4(0.f, 0.f, 0.f, 0.f);
}

// ---------------------------------------------------------------------------
extern "C" void kernel_launch(void* const* d_in, const int* in_sizes, int n_in,
                              void* d_out, int out_size) {
    const float* x    = (const float*)d_in[0];
    const int*   eidx = (const int*)d_in[1];
    const float* ea   = (const float*)d_in[2];
    const float* ew1  = (const float*)d_in[3];
    const float* eb1  = (const float*)d_in[4];
    const float* ew2  = (const float*)d_in[5];
    const float* eb2  = (const float*)d_in[6];
    const float* ew3  = (const float*)d_in[7];
    const float* eb3  = (const float*)d_in[8];
    const float* eg   = (const float*)d_in[9];
    const float* ebt  = (const float*)d_in[10];
    const float* nw1  = (const float*)d_in[11];
    const float* nb1  = (const float*)d_in[12];
    const float* nw2  = (const float*)d_in[13];
    const float* nb2  = (const float*)d_in[14];
    const float* nw3  = (const float*)d_in[15];
    const float* nb3  = (const float*)d_in[16];
    const float* ng   = (const float*)d_in[17];
    const float* nbt  = (const float*)d_in[18];

    float* out_x = (float*)d_out;                       // [50000, 128]
    float* out_e = (float*)d_out + (size_t)NN * 128;    // [800000, 128]

    cudaFuncSetAttribute(pq_kernel,   cudaFuncAttributeMaxDynamicSharedMemorySize, SM_BYTES);
    cudaFuncSetAttribute(edge_kernel, cudaFuncAttributeMaxDynamicSharedMemorySize, SM_BYTES);
    cudaFuncSetAttribute(node_kernel, cudaFuncAttributeMaxDynamicSharedMemorySize, SM_BYTES);

    zero_agg_kernel<<<(NN * 32 + 255) / 256, 256>>>();
    prep_w<<<(9 * 16384 + 255) / 256, 256>>>(ew1, ew2, ew3, nw1, nw2, nw3);
    pq_kernel<<<(NN + MROWS - 1) / MROWS, NTHREADS, SM_BYTES>>>(x);
    edge_kernel<<<NE / MROWS, NTHREADS, SM_BYTES>>>(eidx, ea, eb1, eb2, eb3, eg, ebt, out_e);
    node_kernel<<<(NN + MROWS - 1) / MROWS, NTHREADS, SM_BYTES>>>(x, nb1, nb2, nb3, ng, nbt, out_x);
}

// round 15
// speedup vs baseline: 1.6705x; 1.0055x over previous
#include <cuda_runtime.h>

#define NN 50000
#define NE 800000

typedef unsigned int u32;
typedef unsigned long long u64;

// ---------------------------------------------------------------------------
// Device scratch (no cudaMalloc allowed)
// ---------------------------------------------------------------------------
__device__ float g_agg[(size_t)NN * 128];
__device__ float g_P[(size_t)NN * 128];   // x @ W1a (edge layer-1, x_i part)
__device__ float g_Q[(size_t)NN * 128];   // x @ W1b (edge layer-1, x_j part)
// Pre-split bf16 weights, transposed to [n][k], row stride 272B.
// Chunk = [hi 34816][lo 34816].
#define HB 34816
#define WCHUNK (2 * HB)
__device__ __align__(16) unsigned char g_we[5 * WCHUNK]; // W1a,W1b,W1c,W2,W3
__device__ __align__(16) unsigned char g_wn[4 * WCHUNK]; // node: L1 x2, L2, L3

// ---------------------------------------------------------------------------
// SMEM: A_hi, A_lo (64 rows), two B half-buffers. 104448 B -> 2 blocks/SM.
// ---------------------------------------------------------------------------
#define ROWB 272
#define SM_AHI 0
#define SM_ALO 17408             // 64*272
#define SM_BB0 34816
#define SM_BB1 (34816 + HB)      // 69632
#define SM_BYTES (34816 + 2 * HB) // 104448

#define MROWS 64
#define NTHREADS 256

// ---------------------------------------------------------------------------
// Helpers
// ---------------------------------------------------------------------------
__device__ __forceinline__ u32 smem_u32(const void* p) {
    u32 a;
    asm("{ .reg .u64 t; cvta.to.shared.u64 t, %1; cvt.u32.u64 %0, t; }"
        : "=r"(a) : "l"(p));
    return a;
}
__device__ __forceinline__ u32 pack_bf16x2(float e0, float e1) {
    u32 r;
    asm("cvt.rn.bf16x2.f32 %0, %1, %2;" : "=r"(r) : "f"(e1), "f"(e0));
    return r;
}
__device__ __forceinline__ float bf_lo_f(u32 p) { return __uint_as_float(p << 16); }
__device__ __forceinline__ float bf_hi_f(u32 p) { return __uint_as_float(p & 0xffff0000u); }
// silu via tanh.approx: silu(x) = 0.5*x*(1 + tanh(0.5*x)) — 1 MUFU op
__device__ __forceinline__ float silu_f(float v) {
    float t;
    asm("tanh.approx.f32 %0, %1;" : "=f"(t) : "f"(v * 0.5f));
    return 0.5f * v + 0.5f * v * t;
}
// de-phase-lock the two co-resident blocks: wave-1 slot blocks delay once
__device__ __forceinline__ void skew_delay(int bid) {
    if (bid >= 148 && bid < 296) {
        long long t0 = clock64();
        while (clock64() - t0 < 2048) {}
    }
}

__device__ __forceinline__ void ldsm4(u32& r0, u32& r1, u32& r2, u32& r3, u32 addr) {
    asm volatile("ldmatrix.sync.aligned.m8n8.x4.shared.b16 {%0,%1,%2,%3}, [%4];"
                 : "=r"(r0), "=r"(r1), "=r"(r2), "=r"(r3) : "r"(addr));
}
__device__ __forceinline__ void mma16816(float* c, const u32* a, u32 b0, u32 b1) {
    asm volatile(
        "mma.sync.aligned.m16n8k16.row.col.f32.bf16.bf16.f32 "
        "{%0,%1,%2,%3}, {%4,%5,%6,%7}, {%8,%9}, {%0,%1,%2,%3};"
        : "+f"(c[0]), "+f"(c[1]), "+f"(c[2]), "+f"(c[3])
        : "r"(a[0]), "r"(a[1]), "r"(a[2]), "r"(a[3]), "r"(b0), "r"(b1));
}
__device__ __forceinline__ void split4(float v0, float v1, float v2, float v3,
                                       u64& hi, u64& lo) {
    u32 h0 = pack_bf16x2(v0, v1), h1 = pack_bf16x2(v2, v3);
    u32 l0 = pack_bf16x2(v0 - bf_lo_f(h0), v1 - bf_hi_f(h0));
    u32 l1 = pack_bf16x2(v2 - bf_lo_f(h1), v3 - bf_hi_f(h1));
    hi = (u64)h0 | ((u64)h1 << 32);
    lo = (u64)l0 | ((u64)l1 << 32);
}
__device__ __forceinline__ void red2(float* p, float a, float b) {
    asm volatile("red.global.add.v2.f32 [%0], {%1,%2};"
                 :: "l"(p), "f"(a), "f"(b) : "memory");
}

// ---- register gather prefetch (8 float4 per thread) ----
__device__ __forceinline__ void issue_gather(float4* pre, const float4* src,
                                             long long g, int qb) {
#pragma unroll
    for (int i = 0; i < 8; ++i)
        pre[i] = __ldg(src + g * 32 + qb + i);
}
__device__ __forceinline__ void issue_gather_guard(float4* pre, const float4* src,
                                                   int g, int qb) {
#pragma unroll
    for (int i = 0; i < 8; ++i) {
        float4 v = make_float4(0.f, 0.f, 0.f, 0.f);
        if (g < NN) v = __ldg(src + (size_t)g * 32 + qb + i);
        pre[i] = v;
    }
}
__device__ __forceinline__ void convert_gather(char* sm, const float4* pre,
                                               int row, int qb) {
#pragma unroll
    for (int i = 0; i < 8; ++i) {
        u64 hi, lo;
        split4(pre[i].x, pre[i].y, pre[i].z, pre[i].w, hi, lo);
        *(u64*)(sm + SM_AHI + row * ROWB + (qb + i) * 8) = hi;
        *(u64*)(sm + SM_ALO + row * ROWB + (qb + i) * 8) = lo;
    }
}

// ---- cp.async ----
__device__ __forceinline__ void cp16(u32 dst, const void* src) {
    asm volatile("cp.async.cg.shared.global [%0], [%1], 16;" :: "r"(dst), "l"(src));
}
#define CP_COMMIT() asm volatile("cp.async.commit_group;" ::: "memory")
#define CP_WAIT(n)  asm volatile("cp.async.wait_group %0;" :: "n"(n) : "memory")

__device__ __forceinline__ void fill_half(u32 dst, const unsigned char* w, int tid) {
#pragma unroll
    for (int i = 0; i < 9; ++i) {
        int t = tid + i * NTHREADS;
        if (t < HB / 16) cp16(dst + t * 16, w + t * 16);
    }
}

// ---------------------------------------------------------------------------
// MMA halves over one 128-K chunk. Warp tile 16x64. acc[8][4].
// ---------------------------------------------------------------------------
__device__ __forceinline__ void mma_even(u32 smb, u32 bbuf, float acc[8][4],
                                         int mbase, int nbase, int lane) {
    const u32 a_off = (u32)(mbase + (lane & 15)) * ROWB + (u32)(lane >> 4) * 16;
    const u32 b_off = (u32)(nbase + (lane & 7) + ((lane >> 4) & 1) * 8) * ROWB
                    + (u32)((lane >> 3) & 1) * 16;
#pragma unroll
    for (int ks = 0; ks < 8; ++ks) {
        const u32 kb = (u32)ks * 32;
        u32 ah[4], al[4], b[4][4];
        ldsm4(ah[0], ah[1], ah[2], ah[3], smb + SM_AHI + a_off + kb);
#pragma unroll
        for (int g = 0; g < 4; ++g)
            ldsm4(b[g][0], b[g][1], b[g][2], b[g][3],
                  bbuf + b_off + (u32)g * (16 * ROWB) + kb);
#pragma unroll
        for (int ng = 0; ng < 8; ++ng)
            mma16816(acc[ng], ah, b[ng >> 1][(ng & 1) * 2], b[ng >> 1][(ng & 1) * 2 + 1]);
        ldsm4(al[0], al[1], al[2], al[3], smb + SM_ALO + a_off + kb);
#pragma unroll
        for (int ng = 0; ng < 8; ++ng)
            mma16816(acc[ng], al, b[ng >> 1][(ng & 1) * 2], b[ng >> 1][(ng & 1) * 2 + 1]);
    }
}

__device__ __forceinline__ void mma_odd(u32 smb, u32 bbuf, float acc[8][4],
                                        int mbase, int nbase, int lane) {
    const u32 a_off = (u32)(mbase + (lane & 15)) * ROWB + (u32)(lane >> 4) * 16;
    const u32 b_off = (u32)(nbase + (lane & 7) + ((lane >> 4) & 1) * 8) * ROWB
                    + (u32)((lane >> 3) & 1) * 16;
#pragma unroll
    for (int ks = 0; ks < 8; ++ks) {
        const u32 kb = (u32)ks * 32;
        u32 ah[4], b[4][4];
        ldsm4(ah[0], ah[1], ah[2], ah[3], smb + SM_AHI + a_off + kb);
#pragma unroll
        for (int g = 0; g < 4; ++g)
            ldsm4(b[g][0], b[g][1], b[g][2], b[g][3],
                  bbuf + b_off + (u32)g * (16 * ROWB) + kb);
#pragma unroll
        for (int ng = 0; ng < 8; ++ng)
            mma16816(acc[ng], ah, b[ng >> 1][(ng & 1) * 2], b[ng >> 1][(ng & 1) * 2 + 1]);
    }
}

// bias + SiLU from acc -> A smem (hi/lo), zero acc
__device__ __forceinline__ void mid_epi(char* sm, float acc[8][4],
                                        const float* __restrict__ bias,
                                        int mbase, int nbase, int lane) {
    const int q = lane & 3, r = lane >> 2;
#pragma unroll
    for (int ng = 0; ng < 8; ++ng) {
        const int col = nbase + ng * 8 + q * 2;
        const float bx = __ldg(bias + col), by = __ldg(bias + col + 1);
        const int r0 = mbase + r, r1 = r0 + 8;
        float v0 = silu_f(acc[ng][0] + bx);
        float v1 = silu_f(acc[ng][1] + by);
        float v2 = silu_f(acc[ng][2] + bx);
        float v3 = silu_f(acc[ng][3] + by);
        u32 h0 = pack_bf16x2(v0, v1);
        u32 l0 = pack_bf16x2(v0 - bf_lo_f(h0), v1 - bf_hi_f(h0));
        u32 h1 = pack_bf16x2(v2, v3);
        u32 l1 = pack_bf16x2(v2 - bf_lo_f(h1), v3 - bf_hi_f(h1));
        *(u32*)(sm + SM_AHI + r0 * ROWB + col * 2) = h0;
        *(u32*)(sm + SM_ALO + r0 * ROWB + col * 2) = l0;
        *(u32*)(sm + SM_AHI + r1 * ROWB + col * 2) = h1;
        *(u32*)(sm + SM_ALO + r1 * ROWB + col * 2) = l1;
        acc[ng][0] = 0.f; acc[ng][1] = 0.f;
        acc[ng][2] = 0.f; acc[ng][3] = 0.f;
    }
}

// In-register LN: bias + per-row stats via 4-lane butterfly + cross-warp
// exchange in SM_BB0 (free after last MMA). Returns mean/rstd for both rows.
__device__ __forceinline__ void ln_reg(char* sm, float acc[8][4],
                                       const float* __restrict__ b3,
                                       int nbase, int q, int r0, int r1,
                                       float& m0, float& rs0, float& m1, float& rs1) {
    float s1a = 0.f, s2a = 0.f, s1b = 0.f, s2b = 0.f;
#pragma unroll
    for (int ng = 0; ng < 8; ++ng) {
        const int col = nbase + ng * 8 + q * 2;
        const float bx = __ldg(b3 + col), by = __ldg(b3 + col + 1);
        float v0 = acc[ng][0] + bx, v1 = acc[ng][1] + by;
        float v2 = acc[ng][2] + bx, v3 = acc[ng][3] + by;
        acc[ng][0] = v0; acc[ng][1] = v1; acc[ng][2] = v2; acc[ng][3] = v3;
        s1a += v0 + v1; s2a += v0 * v0 + v1 * v1;
        s1b += v2 + v3; s2b += v2 * v2 + v3 * v3;
    }
#pragma unroll
    for (int m = 1; m <= 2; m <<= 1) {
        s1a += __shfl_xor_sync(0xffffffffu, s1a, m, 32);
        s2a += __shfl_xor_sync(0xffffffffu, s2a, m, 32);
        s1b += __shfl_xor_sync(0xffffffffu, s1b, m, 32);
        s2b += __shfl_xor_sync(0xffffffffu, s2b, m, 32);
    }
    float2* ex = (float2*)(sm + SM_BB0);   // [64 rows][2 halves]
    const int half = nbase >> 6;
    if (q == 0) {
        ex[r0 * 2 + half] = make_float2(s1a, s2a);
        ex[r1 * 2 + half] = make_float2(s1b, s2b);
    }
    __syncthreads();
    float2 a0 = ex[r0 * 2], a1 = ex[r0 * 2 + 1];
    float2 b0 = ex[r1 * 2], b1 = ex[r1 * 2 + 1];
    m0 = (a0.x + a1.x) * (1.0f / 128.0f);
    float v0 = (a0.y + a1.y) * (1.0f / 128.0f) - m0 * m0;
    rs0 = rsqrtf(v0 + 1e-5f);
    m1 = (b0.x + b1.x) * (1.0f / 128.0f);
    float v1 = (b0.y + b1.y) * (1.0f / 128.0f) - m1 * m1;
    rs1 = rsqrtf(v1 + 1e-5f);
}

// ---------------------------------------------------------------------------
// PQ precompute: P = x@W1a, Q = x@W1b (64 rows/block, 256 threads)
// ---------------------------------------------------------------------------
__device__ __forceinline__ void store_pq(float* dst, float acc[8][4],
                                         int n0, int mbase, int nbase, int lane) {
    const int q = lane & 3, r = lane >> 2;
#pragma unroll
    for (int ng = 0; ng < 8; ++ng) {
        const int col = nbase + ng * 8 + q * 2;
        const int r0 = mbase + r, r1 = r0 + 8;
        if (n0 + r0 < NN)
            *(float2*)(dst + (size_t)(n0 + r0) * 128 + col) = make_float2(acc[ng][0], acc[ng][1]);
        if (n0 + r1 < NN)
            *(float2*)(dst + (size_t)(n0 + r1) * 128 + col) = make_float2(acc[ng][2], acc[ng][3]);
        acc[ng][0] = 0.f; acc[ng][1] = 0.f;
        acc[ng][2] = 0.f; acc[ng][3] = 0.f;
    }
}

__global__ __launch_bounds__(NTHREADS, 2)
void pq_kernel(const float* __restrict__ x) {
    extern __shared__ char sm[];
    const u32 smb = smem_u32(sm);
    const int tid = threadIdx.x, wid = tid >> 5, lane = tid & 31;
    const int mbase = (wid >> 1) * 16, nbase = (wid & 1) * 64;
    const int n0 = blockIdx.x * MROWS;
    const int grow = tid >> 2, gqb = (tid & 3) * 8;

    float acc[8][4];
#pragma unroll
    for (int ng = 0; ng < 8; ++ng)
#pragma unroll
        for (int k = 0; k < 4; ++k) acc[ng][k] = 0.f;

    fill_half(smb + SM_BB0, g_we, tid);       CP_COMMIT();
    fill_half(smb + SM_BB1, g_we + HB, tid);  CP_COMMIT();

    float4 pre[8];
    issue_gather_guard(pre, (const float4*)x, n0 + grow, gqb);
    convert_gather(sm, pre, grow, gqb);

    // 2 chunks (W1a, W1b) = 4 half-steps; same A both chunks
#pragma unroll 1
    for (int t = 0; t < 4; ++t) {
        const u32 bbuf = smb + SM_BB0 + (u32)(t & 1) * HB;
        if (t < 3) { CP_WAIT(1); } else { CP_WAIT(0); }
        __syncthreads();
        if (t & 1) mma_odd(smb, bbuf, acc, mbase, nbase, lane);
        else       mma_even(smb, bbuf, acc, mbase, nbase, lane);
        __syncthreads();
        if (t + 2 < 4) {
            fill_half(bbuf, g_we + (size_t)(t + 2) * HB, tid);
            CP_COMMIT();
        }
        if (t == 1) store_pq(g_P, acc, n0, mbase, nbase, lane);
    }
    store_pq(g_Q, acc, n0, mbase, nbase, lane);
}

// ---------------------------------------------------------------------------
// Edge kernel: 64 edges/block, 256 threads, 3 MMA chunks (W1c, W2, W3).
// Layer-1 acc initialized from P[i]/Q[j] fragment loads (issued first).
// ---------------------------------------------------------------------------
__global__ __launch_bounds__(NTHREADS, 2)
void edge_kernel(const int* __restrict__ eidx,
                 const float* __restrict__ ea,
                 const float* __restrict__ b1, const float* __restrict__ b2,
                 const float* __restrict__ b3,
                 const float* __restrict__ gw, const float* __restrict__ bw,
                 float* __restrict__ out_e) {
    extern __shared__ char sm[];
    const u32 smb = smem_u32(sm);
    const int tid = threadIdx.x, wid = tid >> 5, lane = tid & 31;
    const int mbase = (wid >> 1) * 16, nbase = (wid & 1) * 64;
    const int e0 = blockIdx.x * MROWS;
    const int grow = tid >> 2, gqb = (tid & 3) * 8;
    const int q = lane & 3, r = lane >> 2;
    const int row0 = mbase + r, row1 = row0 + 8;
    const unsigned char* wbase = g_we + 2 * WCHUNK;  // chunks W1c, W2, W3

    skew_delay(blockIdx.x);

    // acc init = P[i] + Q[j] at fragment positions — issued FIRST so the
    // scattered LDG latency hides under fills/convert below.
    float acc[8][4];
    {
        const size_t i0 = (size_t)__ldg(eidx + e0 + row0) * 128;
        const size_t i1 = (size_t)__ldg(eidx + e0 + row1) * 128;
        const size_t j0 = (size_t)__ldg(eidx + NE + e0 + row0) * 128;
        const size_t j1 = (size_t)__ldg(eidx + NE + e0 + row1) * 128;
#pragma unroll
        for (int ng = 0; ng < 8; ++ng) {
            const int col = nbase + ng * 8 + q * 2;
            float2 p0 = __ldg((const float2*)(g_P + i0 + col));
            float2 q0 = __ldg((const float2*)(g_Q + j0 + col));
            float2 p1 = __ldg((const float2*)(g_P + i1 + col));
            float2 q1 = __ldg((const float2*)(g_Q + j1 + col));
            acc[ng][0] = p0.x + q0.x;
            acc[ng][1] = p0.y + q0.y;
            acc[ng][2] = p1.x + q1.x;
            acc[ng][3] = p1.y + q1.y;
        }
    }

    fill_half(smb + SM_BB0, wbase, tid);       CP_COMMIT();
    fill_half(smb + SM_BB1, wbase + HB, tid);  CP_COMMIT();

    float4 preA[8];
    issue_gather(preA, (const float4*)ea, (long long)(e0 + grow), gqb);
    convert_gather(sm, preA, grow, gqb);

    // 3 chunks = 6 half-steps
#pragma unroll 1
    for (int t = 0; t < 6; ++t) {
        const u32 bbuf = smb + SM_BB0 + (u32)(t & 1) * HB;
        if (t < 5) { CP_WAIT(1); } else { CP_WAIT(0); }
        __syncthreads();
        if (t & 1) mma_odd(smb, bbuf, acc, mbase, nbase, lane);
        else       mma_even(smb, bbuf, acc, mbase, nbase, lane);
        __syncthreads();
        if (t + 2 < 6) {
            fill_half(bbuf, wbase + (size_t)(t + 2) * HB, tid);
            CP_COMMIT();
        }
        if (t == 1)      mid_epi(sm, acc, b1, mbase, nbase, lane);
        else if (t == 3) mid_epi(sm, acc, b2, mbase, nbase, lane);
    }

    // ---- final: in-register bias3 + LN, then residual/store/scatter ----
    float m0, rs0, m1, rs1;
    ln_reg(sm, acc, b3, nbase, q, row0, row1, m0, rs0, m1, rs1);

    {
        const long long gr0 = e0 + row0, gr1 = e0 + row1;
        const int dj0 = __ldg(eidx + NE + gr0);
        const int dj1 = __ldg(eidx + NE + gr1);
        float* ap0 = g_agg + (size_t)dj0 * 128;
        float* ap1 = g_agg + (size_t)dj1 * 128;
#pragma unroll
        for (int ng = 0; ng < 8; ++ng) {
            const int col = nbase + ng * 8 + q * 2;
            float2 gv = *(const float2*)(gw + col);
            float2 bv = *(const float2*)(bw + col);
            float2 ra0 = __ldg((const float2*)(ea + gr0 * 128 + col));
            float2 ra1 = __ldg((const float2*)(ea + gr1 * 128 + col));
            float o0 = (acc[ng][0] - m0) * rs0 * gv.x + bv.x + ra0.x;
            float o1 = (acc[ng][1] - m0) * rs0 * gv.y + bv.y + ra0.y;
            float o2 = (acc[ng][2] - m1) * rs1 * gv.x + bv.x + ra1.x;
            float o3 = (acc[ng][3] - m1) * rs1 * gv.y + bv.y + ra1.y;
            *(float2*)(out_e + gr0 * 128 + col) = make_float2(o0, o1);
            *(float2*)(out_e + gr1 * 128 + col) = make_float2(o2, o3);
            red2(ap0 + col, o0, o1);
            red2(ap1 + col, o2, o3);
        }
    }
}

// ---------------------------------------------------------------------------
// Node kernel: 64 nodes/block, 256 threads, 2 blocks/SM
// ---------------------------------------------------------------------------
__global__ __launch_bounds__(NTHREADS, 2)
void node_kernel(const float* __restrict__ x,
                 const float* __restrict__ b1, const float* __restrict__ b2,
                 const float* __restrict__ b3,
                 const float* __restrict__ gw, const float* __restrict__ bw,
                 float* __restrict__ out_x) {
    extern __shared__ char sm[];
    const u32 smb = smem_u32(sm);
    const int tid = threadIdx.x, wid = tid >> 5, lane = tid & 31;
    const int mbase = (wid >> 1) * 16, nbase = (wid & 1) * 64;
    const int n0 = blockIdx.x * MROWS;
    const int grow = tid >> 2, gqb = (tid & 3) * 8;
    const int q = lane & 3, r = lane >> 2;
    const int row0 = mbase + r, row1 = row0 + 8;

    skew_delay(blockIdx.x);

    float acc[8][4];
#pragma unroll
    for (int ng = 0; ng < 8; ++ng)
#pragma unroll
        for (int k = 0; k < 4; ++k) acc[ng][k] = 0.f;

    fill_half(smb + SM_BB0, g_wn, tid);       CP_COMMIT();
    fill_half(smb + SM_BB1, g_wn + HB, tid);  CP_COMMIT();

    float4 pre[8];
    issue_gather_guard(pre, (const float4*)x, n0 + grow, gqb);
    convert_gather(sm, pre, grow, gqb);
    issue_gather_guard(pre, (const float4*)g_agg, n0 + grow, gqb);

    // 4 chunks = 8 half-steps
#pragma unroll 1
    for (int t = 0; t < 8; ++t) {
        const u32 bbuf = smb + SM_BB0 + (u32)(t & 1) * HB;
        if (t < 7) { CP_WAIT(1); } else { CP_WAIT(0); }
        __syncthreads();
        if (t & 1) mma_odd(smb, bbuf, acc, mbase, nbase, lane);
        else       mma_even(smb, bbuf, acc, mbase, nbase, lane);
        __syncthreads();
        if (t + 2 < 8) {
            fill_half(bbuf, g_wn + (size_t)(t + 2) * HB, tid);
            CP_COMMIT();
        }
        if (t & 1) {
            const int s = t >> 1;
            if (s == 0) {
                convert_gather(sm, pre, grow, gqb);
            } else if (s == 1) {
                mid_epi(sm, acc, b1, mbase, nbase, lane);
            } else if (s == 2) {
                mid_epi(sm, acc, b2, mbase, nbase, lane);
            }
        }
    }

    // ---- final: in-register bias3 + LN, residual + store ----
    float m0, rs0, m1, rs1;
    ln_reg(sm, acc, b3, nbase, q, row0, row1, m0, rs0, m1, rs1);

    {
        const long long gr0 = n0 + row0, gr1 = n0 + row1;
        const bool ok0 = gr0 < NN, ok1 = gr1 < NN;
#pragma unroll
        for (int ng = 0; ng < 8; ++ng) {
            const int col = nbase + ng * 8 + q * 2;
            float2 gv = *(const float2*)(gw + col);
            float2 bv = *(const float2*)(bw + col);
            if (ok0) {
                float2 ra = __ldg((const float2*)(x + gr0 * 128 + col));
                float o0 = (acc[ng][0] - m0) * rs0 * gv.x + bv.x + ra.x;
                float o1 = (acc[ng][1] - m0) * rs0 * gv.y + bv.y + ra.y;
                *(float2*)(out_x + gr0 * 128 + col) = make_float2(o0, o1);
            }
            if (ok1) {
                float2 ra = __ldg((const float2*)(x + gr1 * 128 + col));
                float o2 = (acc[ng][2] - m1) * rs1 * gv.x + bv.x + ra.x;
                float o3 = (acc[ng][3] - m1) * rs1 * gv.y + bv.y + ra.y;
                *(float2*)(out_x + gr1 * 128 + col) = make_float2(o2, o3);
            }
        }
    }
}

// ---------------------------------------------------------------------------
// Weight prep: split into bf16 hi/lo, transpose to [n][k], row stride 272B.
// ---------------------------------------------------------------------------
__global__ void prep_w(const float* __restrict__ ew1, const float* __restrict__ ew2,
                       const float* __restrict__ ew3, const float* __restrict__ nw1,
                       const float* __restrict__ nw2, const float* __restrict__ nw3) {
    int i = blockIdx.x * blockDim.x + threadIdx.x;
    if (i >= 9 * 16384) return;
    unsigned char* dst;
    float val;
    int cs = i >> 14, r = i & 16383;
    int kl = r >> 7, n = r & 127;
    if (cs < 5) {
        if (cs < 3)       val = ew1[(cs * 128 + kl) * 128 + n];
        else if (cs == 3) val = ew2[kl * 128 + n];
        else              val = ew3[kl * 128 + n];
        dst = g_we + (size_t)cs * WCHUNK;
    } else {
        int ns = cs - 5;
        if (ns < 2)       val = nw1[(ns * 128 + kl) * 128 + n];
        else if (ns == 2) val = nw2[kl * 128 + n];
        else              val = nw3[kl * 128 + n];
        dst = g_wn + (size_t)ns * WCHUNK;
    }
    u32 h = pack_bf16x2(val, 0.f);
    u32 l = pack_bf16x2(val - bf_lo_f(h), 0.f);
    *(unsigned short*)(dst + n * ROWB + kl * 2)      = (unsigned short)(h & 0xffff);
    *(unsigned short*)(dst + HB + n * ROWB + kl * 2) = (unsigned short)(l & 0xffff);
}

__global__ void zero_agg_kernel() {
    int i = blockIdx.x * blockDim.x + threadIdx.x;
    if (i < NN * 32)
        ((float4*)g_agg)[i] = make_float4(0.f, 0.f, 0.f, 0.f);
}

// ---------------------------------------------------------------------------
extern "C" void kernel_launch(void* const* d_in, const int* in_sizes, int n_in,
                              void* d_out, int out_size) {
    const float* x    = (const float*)d_in[0];
    const int*   eidx = (const int*)d_in[1];
    const float* ea   = (const float*)d_in[2];
    const float* ew1  = (const float*)d_in[3];
    const float* eb1  = (const float*)d_in[4];
    const float* ew2  = (const float*)d_in[5];
    const float* eb2  = (const float*)d_in[6];
    const float* ew3  = (const float*)d_in[7];
    const float* eb3  = (const float*)d_in[8];
    const float* eg   = (const float*)d_in[9];
    const float* ebt  = (const float*)d_in[10];
    const float* nw1  = (const float*)d_in[11];
    const float* nb1  = (const float*)d_in[12];
    const float* nw2  = (const float*)d_in[13];
    const float* nb2  = (const float*)d_in[14];
    const float* nw3  = (const float*)d_in[15];
    const float* nb3  = (const float*)d_in[16];
    const float* ng   = (const float*)d_in[17];
    const float* nbt  = (const float*)d_in[18];

    float* out_x = (float*)d_out;                       // [50000, 128]
    float* out_e = (float*)d_out + (size_t)NN * 128;    // [800000, 128]

    cudaFuncSetAttribute(pq_kernel,   cudaFuncAttributeMaxDynamicSharedMemorySize, SM_BYTES);
    cudaFuncSetAttribute(edge_kernel, cudaFuncAttributeMaxDynamicSharedMemorySize, SM_BYTES);
    cudaFuncSetAttribute(node_kernel, cudaFuncAttributeMaxDynamicSharedMemorySize, SM_BYTES);

    zero_agg_kernel<<<(NN * 32 + 255) / 256, 256>>>();
    prep_w<<<(9 * 16384 + 255) / 256, 256>>>(ew1, ew2, ew3, nw1, nw2, nw3);
    pq_kernel<<<(NN + MROWS - 1) / MROWS, NTHREADS, SM_BYTES>>>(x);
    edge_kernel<<<NE / MROWS, NTHREADS, SM_BYTES>>>(eidx, ea, eb1, eb2, eb3, eg, ebt, out_e);
    node_kernel<<<(NN + MROWS - 1) / MROWS, NTHREADS, SM_BYTES>>>(x, nb1, nb2, nb3, ng, nbt, out_x);
}

// round 16
// speedup vs baseline: 1.6937x; 1.0138x over previous
#include <cuda_runtime.h>

#define NN 50000
#define NE 800000

typedef unsigned int u32;
typedef unsigned long long u64;

// ---------------------------------------------------------------------------
// Device scratch (no cudaMalloc allowed)
// ---------------------------------------------------------------------------
__device__ float g_agg[(size_t)NN * 128];
__device__ float g_P[(size_t)NN * 128];   // x @ W1a (edge layer-1, x_i part)
__device__ float g_Q[(size_t)NN * 128];   // x @ W1b (edge layer-1, x_j part)
// Pre-split bf16 weights, transposed to [n][k], row stride 272B.
// Chunk = [hi 34816][lo 34816].
#define HB 34816
#define WCHUNK (2 * HB)
__device__ __align__(16) unsigned char g_we[5 * WCHUNK]; // W1a,W1b,W1c,W2,W3
__device__ __align__(16) unsigned char g_wn[4 * WCHUNK]; // node: L1 x2, L2, L3

// ---------------------------------------------------------------------------
// SMEM: A_hi, A_lo (64 rows), two B half-buffers. 104448 B -> 2 blocks/SM.
// ---------------------------------------------------------------------------
#define ROWB 272
#define SM_AHI 0
#define SM_ALO 17408             // 64*272
#define SM_BB0 34816
#define SM_BB1 (34816 + HB)      // 69632
#define SM_BYTES (34816 + 2 * HB) // 104448

#define MROWS 64
#define NTHREADS 256

// ---------------------------------------------------------------------------
// Helpers
// ---------------------------------------------------------------------------
__device__ __forceinline__ u32 smem_u32(const void* p) {
    u32 a;
    asm("{ .reg .u64 t; cvta.to.shared.u64 t, %1; cvt.u32.u64 %0, t; }"
        : "=r"(a) : "l"(p));
    return a;
}
__device__ __forceinline__ u32 pack_bf16x2(float e0, float e1) {
    u32 r;
    asm("cvt.rn.bf16x2.f32 %0, %1, %2;" : "=r"(r) : "f"(e1), "f"(e0));
    return r;
}
__device__ __forceinline__ float bf_lo_f(u32 p) { return __uint_as_float(p << 16); }
__device__ __forceinline__ float bf_hi_f(u32 p) { return __uint_as_float(p & 0xffff0000u); }
// silu via tanh.approx: silu(x) = 0.5*x*(1 + tanh(0.5*x)) — 1 MUFU op
__device__ __forceinline__ float silu_f(float v) {
    float t;
    asm("tanh.approx.f32 %0, %1;" : "=f"(t) : "f"(v * 0.5f));
    return 0.5f * v + 0.5f * v * t;
}
// de-phase-lock the two co-resident blocks: wave-1 slot blocks delay once
__device__ __forceinline__ void skew_delay(int bid) {
    if (bid >= 148 && bid < 296) {
        long long t0 = clock64();
        while (clock64() - t0 < 2048) {}
    }
}

__device__ __forceinline__ void ldsm4(u32& r0, u32& r1, u32& r2, u32& r3, u32 addr) {
    asm volatile("ldmatrix.sync.aligned.m8n8.x4.shared.b16 {%0,%1,%2,%3}, [%4];"
                 : "=r"(r0), "=r"(r1), "=r"(r2), "=r"(r3) : "r"(addr));
}
__device__ __forceinline__ void mma16816(float* c, const u32* a, u32 b0, u32 b1) {
    asm volatile(
        "mma.sync.aligned.m16n8k16.row.col.f32.bf16.bf16.f32 "
        "{%0,%1,%2,%3}, {%4,%5,%6,%7}, {%8,%9}, {%0,%1,%2,%3};"
        : "+f"(c[0]), "+f"(c[1]), "+f"(c[2]), "+f"(c[3])
        : "r"(a[0]), "r"(a[1]), "r"(a[2]), "r"(a[3]), "r"(b0), "r"(b1));
}
__device__ __forceinline__ void split4(float v0, float v1, float v2, float v3,
                                       u64& hi, u64& lo) {
    u32 h0 = pack_bf16x2(v0, v1), h1 = pack_bf16x2(v2, v3);
    u32 l0 = pack_bf16x2(v0 - bf_lo_f(h0), v1 - bf_hi_f(h0));
    u32 l1 = pack_bf16x2(v2 - bf_lo_f(h1), v3 - bf_hi_f(h1));
    hi = (u64)h0 | ((u64)h1 << 32);
    lo = (u64)l0 | ((u64)l1 << 32);
}
__device__ __forceinline__ void red2(float* p, float a, float b) {
    asm volatile("red.global.add.v2.f32 [%0], {%1,%2};"
                 :: "l"(p), "f"(a), "f"(b) : "memory");
}

// ---- register gather prefetch (8 float4 per thread) ----
__device__ __forceinline__ void issue_gather(float4* pre, const float4* src,
                                             long long g, int qb) {
#pragma unroll
    for (int i = 0; i < 8; ++i)
        pre[i] = __ldg(src + g * 32 + qb + i);
}
__device__ __forceinline__ void issue_gather_guard(float4* pre, const float4* src,
                                                   int g, int qb) {
#pragma unroll
    for (int i = 0; i < 8; ++i) {
        float4 v = make_float4(0.f, 0.f, 0.f, 0.f);
        if (g < NN) v = __ldg(src + (size_t)g * 32 + qb + i);
        pre[i] = v;
    }
}
__device__ __forceinline__ void convert_gather(char* sm, const float4* pre,
                                               int row, int qb) {
#pragma unroll
    for (int i = 0; i < 8; ++i) {
        u64 hi, lo;
        split4(pre[i].x, pre[i].y, pre[i].z, pre[i].w, hi, lo);
        *(u64*)(sm + SM_AHI + row * ROWB + (qb + i) * 8) = hi;
        *(u64*)(sm + SM_ALO + row * ROWB + (qb + i) * 8) = lo;
    }
}

// ---- cp.async ----
__device__ __forceinline__ void cp16(u32 dst, const void* src) {
    asm volatile("cp.async.cg.shared.global [%0], [%1], 16;" :: "r"(dst), "l"(src));
}
#define CP_COMMIT() asm volatile("cp.async.commit_group;" ::: "memory")
#define CP_WAIT(n)  asm volatile("cp.async.wait_group %0;" :: "n"(n) : "memory")

__device__ __forceinline__ void fill_half(u32 dst, const unsigned char* w, int tid) {
#pragma unroll
    for (int i = 0; i < 9; ++i) {
        int t = tid + i * NTHREADS;
        if (t < HB / 16) cp16(dst + t * 16, w + t * 16);
    }
}

// ---------------------------------------------------------------------------
// MMA halves over one 128-K chunk. Warp tile 16x64. acc[8][4].
// ---------------------------------------------------------------------------
__device__ __forceinline__ void mma_even(u32 smb, u32 bbuf, float acc[8][4],
                                         int mbase, int nbase, int lane) {
    const u32 a_off = (u32)(mbase + (lane & 15)) * ROWB + (u32)(lane >> 4) * 16;
    const u32 b_off = (u32)(nbase + (lane & 7) + ((lane >> 4) & 1) * 8) * ROWB
                    + (u32)((lane >> 3) & 1) * 16;
#pragma unroll
    for (int ks = 0; ks < 8; ++ks) {
        const u32 kb = (u32)ks * 32;
        u32 ah[4], al[4], b[4][4];
        ldsm4(ah[0], ah[1], ah[2], ah[3], smb + SM_AHI + a_off + kb);
#pragma unroll
        for (int g = 0; g < 4; ++g)
            ldsm4(b[g][0], b[g][1], b[g][2], b[g][3],
                  bbuf + b_off + (u32)g * (16 * ROWB) + kb);
#pragma unroll
        for (int ng = 0; ng < 8; ++ng)
            mma16816(acc[ng], ah, b[ng >> 1][(ng & 1) * 2], b[ng >> 1][(ng & 1) * 2 + 1]);
        ldsm4(al[0], al[1], al[2], al[3], smb + SM_ALO + a_off + kb);
#pragma unroll
        for (int ng = 0; ng < 8; ++ng)
            mma16816(acc[ng], al, b[ng >> 1][(ng & 1) * 2], b[ng >> 1][(ng & 1) * 2 + 1]);
    }
}

__device__ __forceinline__ void mma_odd(u32 smb, u32 bbuf, float acc[8][4],
                                        int mbase, int nbase, int lane) {
    const u32 a_off = (u32)(mbase + (lane & 15)) * ROWB + (u32)(lane >> 4) * 16;
    const u32 b_off = (u32)(nbase + (lane & 7) + ((lane >> 4) & 1) * 8) * ROWB
                    + (u32)((lane >> 3) & 1) * 16;
#pragma unroll
    for (int ks = 0; ks < 8; ++ks) {
        const u32 kb = (u32)ks * 32;
        u32 ah[4], b[4][4];
        ldsm4(ah[0], ah[1], ah[2], ah[3], smb + SM_AHI + a_off + kb);
#pragma unroll
        for (int g = 0; g < 4; ++g)
            ldsm4(b[g][0], b[g][1], b[g][2], b[g][3],
                  bbuf + b_off + (u32)g * (16 * ROWB) + kb);
#pragma unroll
        for (int ng = 0; ng < 8; ++ng)
            mma16816(acc[ng], ah, b[ng >> 1][(ng & 1) * 2], b[ng >> 1][(ng & 1) * 2 + 1]);
    }
}

// bias + SiLU from acc -> A smem (hi/lo), zero acc
__device__ __forceinline__ void mid_epi(char* sm, float acc[8][4],
                                        const float* __restrict__ bias,
                                        int mbase, int nbase, int lane) {
    const int q = lane & 3, r = lane >> 2;
#pragma unroll
    for (int ng = 0; ng < 8; ++ng) {
        const int col = nbase + ng * 8 + q * 2;
        const float bx = __ldg(bias + col), by = __ldg(bias + col + 1);
        const int r0 = mbase + r, r1 = r0 + 8;
        float v0 = silu_f(acc[ng][0] + bx);
        float v1 = silu_f(acc[ng][1] + by);
        float v2 = silu_f(acc[ng][2] + bx);
        float v3 = silu_f(acc[ng][3] + by);
        u32 h0 = pack_bf16x2(v0, v1);
        u32 l0 = pack_bf16x2(v0 - bf_lo_f(h0), v1 - bf_hi_f(h0));
        u32 h1 = pack_bf16x2(v2, v3);
        u32 l1 = pack_bf16x2(v2 - bf_lo_f(h1), v3 - bf_hi_f(h1));
        *(u32*)(sm + SM_AHI + r0 * ROWB + col * 2) = h0;
        *(u32*)(sm + SM_ALO + r0 * ROWB + col * 2) = l0;
        *(u32*)(sm + SM_AHI + r1 * ROWB + col * 2) = h1;
        *(u32*)(sm + SM_ALO + r1 * ROWB + col * 2) = l1;
        acc[ng][0] = 0.f; acc[ng][1] = 0.f;
        acc[ng][2] = 0.f; acc[ng][3] = 0.f;
    }
}

// In-register LN: bias + per-row stats via 4-lane butterfly + cross-warp
// exchange in SM_BB0 (free after last MMA). Returns mean/rstd for both rows.
__device__ __forceinline__ void ln_reg(char* sm, float acc[8][4],
                                       const float* __restrict__ b3,
                                       int nbase, int q, int r0, int r1,
                                       float& m0, float& rs0, float& m1, float& rs1) {
    float s1a = 0.f, s2a = 0.f, s1b = 0.f, s2b = 0.f;
#pragma unroll
    for (int ng = 0; ng < 8; ++ng) {
        const int col = nbase + ng * 8 + q * 2;
        const float bx = __ldg(b3 + col), by = __ldg(b3 + col + 1);
        float v0 = acc[ng][0] + bx, v1 = acc[ng][1] + by;
        float v2 = acc[ng][2] + bx, v3 = acc[ng][3] + by;
        acc[ng][0] = v0; acc[ng][1] = v1; acc[ng][2] = v2; acc[ng][3] = v3;
        s1a += v0 + v1; s2a += v0 * v0 + v1 * v1;
        s1b += v2 + v3; s2b += v2 * v2 + v3 * v3;
    }
#pragma unroll
    for (int m = 1; m <= 2; m <<= 1) {
        s1a += __shfl_xor_sync(0xffffffffu, s1a, m, 32);
        s2a += __shfl_xor_sync(0xffffffffu, s2a, m, 32);
        s1b += __shfl_xor_sync(0xffffffffu, s1b, m, 32);
        s2b += __shfl_xor_sync(0xffffffffu, s2b, m, 32);
    }
    float2* ex = (float2*)(sm + SM_BB0);   // [64 rows][2 halves]
    const int half = nbase >> 6;
    if (q == 0) {
        ex[r0 * 2 + half] = make_float2(s1a, s2a);
        ex[r1 * 2 + half] = make_float2(s1b, s2b);
    }
    __syncthreads();
    float2 a0 = ex[r0 * 2], a1 = ex[r0 * 2 + 1];
    float2 b0 = ex[r1 * 2], b1 = ex[r1 * 2 + 1];
    m0 = (a0.x + a1.x) * (1.0f / 128.0f);
    float v0 = (a0.y + a1.y) * (1.0f / 128.0f) - m0 * m0;
    rs0 = rsqrtf(v0 + 1e-5f);
    m1 = (b0.x + b1.x) * (1.0f / 128.0f);
    float v1 = (b0.y + b1.y) * (1.0f / 128.0f) - m1 * m1;
    rs1 = rsqrtf(v1 + 1e-5f);
}

// ---------------------------------------------------------------------------
// PQ precompute: P = x@W1a, Q = x@W1b (64 rows/block, 256 threads)
// ---------------------------------------------------------------------------
__device__ __forceinline__ void store_pq(float* dst, float acc[8][4],
                                         int n0, int mbase, int nbase, int lane) {
    const int q = lane & 3, r = lane >> 2;
#pragma unroll
    for (int ng = 0; ng < 8; ++ng) {
        const int col = nbase + ng * 8 + q * 2;
        const int r0 = mbase + r, r1 = r0 + 8;
        if (n0 + r0 < NN)
            *(float2*)(dst + (size_t)(n0 + r0) * 128 + col) = make_float2(acc[ng][0], acc[ng][1]);
        if (n0 + r1 < NN)
            *(float2*)(dst + (size_t)(n0 + r1) * 128 + col) = make_float2(acc[ng][2], acc[ng][3]);
        acc[ng][0] = 0.f; acc[ng][1] = 0.f;
        acc[ng][2] = 0.f; acc[ng][3] = 0.f;
    }
}

__global__ __launch_bounds__(NTHREADS, 2)
void pq_kernel(const float* __restrict__ x) {
    extern __shared__ char sm[];
    const u32 smb = smem_u32(sm);
    const int tid = threadIdx.x, wid = tid >> 5, lane = tid & 31;
    const int mbase = (wid >> 1) * 16, nbase = (wid & 1) * 64;
    const int n0 = blockIdx.x * MROWS;
    const int grow = tid >> 2, gqb = (tid & 3) * 8;

    float acc[8][4];
#pragma unroll
    for (int ng = 0; ng < 8; ++ng)
#pragma unroll
        for (int k = 0; k < 4; ++k) acc[ng][k] = 0.f;

    fill_half(smb + SM_BB0, g_we, tid);       CP_COMMIT();
    fill_half(smb + SM_BB1, g_we + HB, tid);  CP_COMMIT();

    float4 pre[8];
    issue_gather_guard(pre, (const float4*)x, n0 + grow, gqb);
    convert_gather(sm, pre, grow, gqb);

    // 2 chunks (W1a, W1b) = 4 half-steps; same A both chunks
#pragma unroll 1
    for (int t = 0; t < 4; ++t) {
        const u32 bbuf = smb + SM_BB0 + (u32)(t & 1) * HB;
        if (t < 3) { CP_WAIT(1); } else { CP_WAIT(0); }
        __syncthreads();
        if (t & 1) mma_odd(smb, bbuf, acc, mbase, nbase, lane);
        else       mma_even(smb, bbuf, acc, mbase, nbase, lane);
        if (t < 3) {
            __syncthreads();
            if (t + 2 < 4) {
                fill_half(bbuf, g_we + (size_t)(t + 2) * HB, tid);
                CP_COMMIT();
            }
            if (t == 1) store_pq(g_P, acc, n0, mbase, nbase, lane);
        }
    }
    store_pq(g_Q, acc, n0, mbase, nbase, lane);
}

// ---------------------------------------------------------------------------
// Edge kernel: 64 edges/block, 256 threads, 3 MMA chunks (W1c, W2, W3).
// Layer-1 acc initialized from P[i]/Q[j] fragment loads (issued first).
// ---------------------------------------------------------------------------
__global__ __launch_bounds__(NTHREADS, 2)
void edge_kernel(const int* __restrict__ eidx,
                 const float* __restrict__ ea,
                 const float* __restrict__ b1, const float* __restrict__ b2,
                 const float* __restrict__ b3,
                 const float* __restrict__ gw, const float* __restrict__ bw,
                 float* __restrict__ out_e) {
    extern __shared__ char sm[];
    const u32 smb = smem_u32(sm);
    const int tid = threadIdx.x, wid = tid >> 5, lane = tid & 31;
    const int mbase = (wid >> 1) * 16, nbase = (wid & 1) * 64;
    const int e0 = blockIdx.x * MROWS;
    const int grow = tid >> 2, gqb = (tid & 3) * 8;
    const int q = lane & 3, r = lane >> 2;
    const int row0 = mbase + r, row1 = row0 + 8;
    const unsigned char* wbase = g_we + 2 * WCHUNK;  // chunks W1c, W2, W3

    skew_delay(blockIdx.x);

    // acc init = P[i] + Q[j] at fragment positions — issued FIRST so the
    // scattered LDG latency hides under fills/convert below.
    float acc[8][4];
    {
        const size_t i0 = (size_t)__ldg(eidx + e0 + row0) * 128;
        const size_t i1 = (size_t)__ldg(eidx + e0 + row1) * 128;
        const size_t j0 = (size_t)__ldg(eidx + NE + e0 + row0) * 128;
        const size_t j1 = (size_t)__ldg(eidx + NE + e0 + row1) * 128;
#pragma unroll
        for (int ng = 0; ng < 8; ++ng) {
            const int col = nbase + ng * 8 + q * 2;
            float2 p0 = __ldg((const float2*)(g_P + i0 + col));
            float2 q0 = __ldg((const float2*)(g_Q + j0 + col));
            float2 p1 = __ldg((const float2*)(g_P + i1 + col));
            float2 q1 = __ldg((const float2*)(g_Q + j1 + col));
            acc[ng][0] = p0.x + q0.x;
            acc[ng][1] = p0.y + q0.y;
            acc[ng][2] = p1.x + q1.x;
            acc[ng][3] = p1.y + q1.y;
        }
    }

    fill_half(smb + SM_BB0, wbase, tid);       CP_COMMIT();
    fill_half(smb + SM_BB1, wbase + HB, tid);  CP_COMMIT();

    float4 preA[8];
    issue_gather(preA, (const float4*)ea, (long long)(e0 + grow), gqb);
    convert_gather(sm, preA, grow, gqb);

    // 3 chunks = 6 half-steps; final step skips post-MMA barrier (B-lo is
    // BB1, ln_reg exchange uses BB0 + its own barrier; A untouched).
#pragma unroll 1
    for (int t = 0; t < 6; ++t) {
        const u32 bbuf = smb + SM_BB0 + (u32)(t & 1) * HB;
        if (t < 5) { CP_WAIT(1); } else { CP_WAIT(0); }
        __syncthreads();
        if (t & 1) mma_odd(smb, bbuf, acc, mbase, nbase, lane);
        else       mma_even(smb, bbuf, acc, mbase, nbase, lane);
        if (t < 5) {
            __syncthreads();
            if (t + 2 < 6) {
                fill_half(bbuf, wbase + (size_t)(t + 2) * HB, tid);
                CP_COMMIT();
            }
            if (t == 1)      mid_epi(sm, acc, b1, mbase, nbase, lane);
            else if (t == 3) mid_epi(sm, acc, b2, mbase, nbase, lane);
        }
    }

    // scatter indices issued before LN so their latency hides under the
    // exchange barrier
    const long long gr0 = e0 + row0, gr1 = e0 + row1;
    const int dj0 = __ldg(eidx + NE + gr0);
    const int dj1 = __ldg(eidx + NE + gr1);

    // ---- final: in-register bias3 + LN, then residual/store/scatter ----
    float m0, rs0, m1, rs1;
    ln_reg(sm, acc, b3, nbase, q, row0, row1, m0, rs0, m1, rs1);

    {
        float* ap0 = g_agg + (size_t)dj0 * 128;
        float* ap1 = g_agg + (size_t)dj1 * 128;
#pragma unroll
        for (int ng = 0; ng < 8; ++ng) {
            const int col = nbase + ng * 8 + q * 2;
            float2 gv = *(const float2*)(gw + col);
            float2 bv = *(const float2*)(bw + col);
            float2 ra0 = __ldg((const float2*)(ea + gr0 * 128 + col));
            float2 ra1 = __ldg((const float2*)(ea + gr1 * 128 + col));
            float o0 = (acc[ng][0] - m0) * rs0 * gv.x + bv.x + ra0.x;
            float o1 = (acc[ng][1] - m0) * rs0 * gv.y + bv.y + ra0.y;
            float o2 = (acc[ng][2] - m1) * rs1 * gv.x + bv.x + ra1.x;
            float o3 = (acc[ng][3] - m1) * rs1 * gv.y + bv.y + ra1.y;
            *(float2*)(out_e + gr0 * 128 + col) = make_float2(o0, o1);
            *(float2*)(out_e + gr1 * 128 + col) = make_float2(o2, o3);
            red2(ap0 + col, o0, o1);
            red2(ap1 + col, o2, o3);
        }
    }
}

// ---------------------------------------------------------------------------
// Node kernel: 64 nodes/block, 256 threads, 2 blocks/SM
// ---------------------------------------------------------------------------
__global__ __launch_bounds__(NTHREADS, 2)
void node_kernel(const float* __restrict__ x,
                 const float* __restrict__ b1, const float* __restrict__ b2,
                 const float* __restrict__ b3,
                 const float* __restrict__ gw, const float* __restrict__ bw,
                 float* __restrict__ out_x) {
    extern __shared__ char sm[];
    const u32 smb = smem_u32(sm);
    const int tid = threadIdx.x, wid = tid >> 5, lane = tid & 31;
    const int mbase = (wid >> 1) * 16, nbase = (wid & 1) * 64;
    const int n0 = blockIdx.x * MROWS;
    const int grow = tid >> 2, gqb = (tid & 3) * 8;
    const int q = lane & 3, r = lane >> 2;
    const int row0 = mbase + r, row1 = row0 + 8;

    skew_delay(blockIdx.x);

    float acc[8][4];
#pragma unroll
    for (int ng = 0; ng < 8; ++ng)
#pragma unroll
        for (int k = 0; k < 4; ++k) acc[ng][k] = 0.f;

    fill_half(smb + SM_BB0, g_wn, tid);       CP_COMMIT();
    fill_half(smb + SM_BB1, g_wn + HB, tid);  CP_COMMIT();

    float4 pre[8];
    issue_gather_guard(pre, (const float4*)x, n0 + grow, gqb);
    convert_gather(sm, pre, grow, gqb);
    issue_gather_guard(pre, (const float4*)g_agg, n0 + grow, gqb);

    // 4 chunks = 8 half-steps; final step skips post-MMA barrier
#pragma unroll 1
    for (int t = 0; t < 8; ++t) {
        const u32 bbuf = smb + SM_BB0 + (u32)(t & 1) * HB;
        if (t < 7) { CP_WAIT(1); } else { CP_WAIT(0); }
        __syncthreads();
        if (t & 1) mma_odd(smb, bbuf, acc, mbase, nbase, lane);
        else       mma_even(smb, bbuf, acc, mbase, nbase, lane);
        if (t < 7) {
            __syncthreads();
            if (t + 2 < 8) {
                fill_half(bbuf, g_wn + (size_t)(t + 2) * HB, tid);
                CP_COMMIT();
            }
            if (t & 1) {
                const int s = t >> 1;
                if (s == 0) {
                    convert_gather(sm, pre, grow, gqb);
                } else if (s == 1) {
                    mid_epi(sm, acc, b1, mbase, nbase, lane);
                } else if (s == 2) {
                    mid_epi(sm, acc, b2, mbase, nbase, lane);
                }
            }
        }
    }

    // ---- final: in-register bias3 + LN, residual + store ----
    float m0, rs0, m1, rs1;
    ln_reg(sm, acc, b3, nbase, q, row0, row1, m0, rs0, m1, rs1);

    {
        const long long gr0 = n0 + row0, gr1 = n0 + row1;
        const bool ok0 = gr0 < NN, ok1 = gr1 < NN;
#pragma unroll
        for (int ng = 0; ng < 8; ++ng) {
            const int col = nbase + ng * 8 + q * 2;
            float2 gv = *(const float2*)(gw + col);
            float2 bv = *(const float2*)(bw + col);
            if (ok0) {
                float2 ra = __ldg((const float2*)(x + gr0 * 128 + col));
                float o0 = (acc[ng][0] - m0) * rs0 * gv.x + bv.x + ra.x;
                float o1 = (acc[ng][1] - m0) * rs0 * gv.y + bv.y + ra.y;
                *(float2*)(out_x + gr0 * 128 + col) = make_float2(o0, o1);
            }
            if (ok1) {
                float2 ra = __ldg((const float2*)(x + gr1 * 128 + col));
                float o2 = (acc[ng][2] - m1) * rs1 * gv.x + bv.x + ra.x;
                float o3 = (acc[ng][3] - m1) * rs1 * gv.y + bv.y + ra.y;
                *(float2*)(out_x + gr1 * 128 + col) = make_float2(o2, o3);
            }
        }
    }
}

// ---------------------------------------------------------------------------
// Weight prep (split bf16 hi/lo, [n][k], stride 272B) fused with g_agg zeroing.
// ---------------------------------------------------------------------------
#define PREP_N (9 * 16384)
#define ZERO_N (NN * 32)

__global__ void prep_zero(const float* __restrict__ ew1, const float* __restrict__ ew2,
                          const float* __restrict__ ew3, const float* __restrict__ nw1,
                          const float* __restrict__ nw2, const float* __restrict__ nw3) {
    int i = blockIdx.x * blockDim.x + threadIdx.x;
    if (i < PREP_N) {
        unsigned char* dst;
        float val;
        int cs = i >> 14, rr = i & 16383;
        int kl = rr >> 7, n = rr & 127;
        if (cs < 5) {
            if (cs < 3)       val = ew1[(cs * 128 + kl) * 128 + n];
            else if (cs == 3) val = ew2[kl * 128 + n];
            else              val = ew3[kl * 128 + n];
            dst = g_we + (size_t)cs * WCHUNK;
        } else {
            int ns = cs - 5;
            if (ns < 2)       val = nw1[(ns * 128 + kl) * 128 + n];
            else if (ns == 2) val = nw2[kl * 128 + n];
            else              val = nw3[kl * 128 + n];
            dst = g_wn + (size_t)ns * WCHUNK;
        }
        u32 h = pack_bf16x2(val, 0.f);
        u32 l = pack_bf16x2(val - bf_lo_f(h), 0.f);
        *(unsigned short*)(dst + n * ROWB + kl * 2)      = (unsigned short)(h & 0xffff);
        *(unsigned short*)(dst + HB + n * ROWB + kl * 2) = (unsigned short)(l & 0xffff);
    } else {
        int z = i - PREP_N;
        if (z < ZERO_N)
            ((float4*)g_agg)[z] = make_float4(0.f, 0.f, 0.f, 0.f);
    }
}

// ---------------------------------------------------------------------------
extern "C" void kernel_launch(void* const* d_in, const int* in_sizes, int n_in,
                              void* d_out, int out_size) {
    const float* x    = (const float*)d_in[0];
    const int*   eidx = (const int*)d_in[1];
    const float* ea   = (const float*)d_in[2];
    const float* ew1  = (const float*)d_in[3];
    const float* eb1  = (const float*)d_in[4];
    const float* ew2  = (const float*)d_in[5];
    const float* eb2  = (const float*)d_in[6];
    const float* ew3  = (const float*)d_in[7];
    const float* eb3  = (const float*)d_in[8];
    const float* eg   = (const float*)d_in[9];
    const float* ebt  = (const float*)d_in[10];
    const float* nw1  = (const float*)d_in[11];
    const float* nb1  = (const float*)d_in[12];
    const float* nw2  = (const float*)d_in[13];
    const float* nb2  = (const float*)d_in[14];
    const float* nw3  = (const float*)d_in[15];
    const float* nb3  = (const float*)d_in[16];
    const float* ng   = (const float*)d_in[17];
    const float* nbt  = (const float*)d_in[18];

    float* out_x = (float*)d_out;                       // [50000, 128]
    float* out_e = (float*)d_out + (size_t)NN * 128;    // [800000, 128]

    cudaFuncSetAttribute(pq_kernel,   cudaFuncAttributeMaxDynamicSharedMemorySize, SM_BYTES);
    cudaFuncSetAttribute(edge_kernel, cudaFuncAttributeMaxDynamicSharedMemorySize, SM_BYTES);
    cudaFuncSetAttribute(node_kernel, cudaFuncAttributeMaxDynamicSharedMemorySize, SM_BYTES);

    prep_zero<<<(PREP_N + ZERO_N + 255) / 256, 256>>>(ew1, ew2, ew3, nw1, nw2, nw3);
    pq_kernel<<<(NN + MROWS - 1) / MROWS, NTHREADS, SM_BYTES>>>(x);
    edge_kernel<<<NE / MROWS, NTHREADS, SM_BYTES>>>(eidx, ea, eb1, eb2, eb3, eg, ebt, out_e);
    node_kernel<<<(NN + MROWS - 1) / MROWS, NTHREADS, SM_BYTES>>>(x, nb1, nb2, nb3, ng, nbt, out_x);
}

// round 17
// speedup vs baseline: 1.8113x; 1.0695x over previous
#include <cuda_runtime.h>

#define NN 50000
#define NE 800000

typedef unsigned int u32;
typedef unsigned long long u64;

// ---------------------------------------------------------------------------
// Device scratch (no cudaMalloc allowed)
// ---------------------------------------------------------------------------
__device__ float g_agg[(size_t)NN * 128];
__device__ float g_P[(size_t)NN * 128];   // x @ W1a (edge layer-1, x_i part)
__device__ float g_Q[(size_t)NN * 128];   // x @ W1b (edge layer-1, x_j part)
// Weights pre-split bf16 hi/lo, transposed to [n][k], K-SPLIT halves:
// chunk = [half0: k0-63 (hi 18432B | lo 18432B)][half1: k64-127 (hi|lo)]
#define BROWB 144                // B sub-tile row stride (64 k * 2B + pad)
#define HSUB  18432              // one hi or lo sub-tile: 128 * 144
#define HBK   36864              // one K-half (hi+lo)
#define WCH2  73728              // full chunk (2 K-halves)
__device__ __align__(16) unsigned char g_we[5 * WCH2]; // W1a,W1b,W1c,W2,W3
__device__ __align__(16) unsigned char g_wn[4 * WCH2]; // node: L1 x2, L2, L3

// ---------------------------------------------------------------------------
// SMEM: A_hi, A_lo (64 rows, ROWB), two B K-half buffers. 108544 -> 2 blk/SM.
// ---------------------------------------------------------------------------
#define ROWB 272
#define SM_AHI 0
#define SM_ALO 17408             // 64*272
#define SM_BB0 34816
#define SM_BB1 (34816 + HBK)     // 71680
#define SM_BYTES (34816 + 2 * HBK) // 108544

#define MROWS 64
#define NTHREADS 256

// ---------------------------------------------------------------------------
// Helpers
// ---------------------------------------------------------------------------
__device__ __forceinline__ u32 smem_u32(const void* p) {
    u32 a;
    asm("{ .reg .u64 t; cvta.to.shared.u64 t, %1; cvt.u32.u64 %0, t; }"
        : "=r"(a) : "l"(p));
    return a;
}
__device__ __forceinline__ u32 pack_bf16x2(float e0, float e1) {
    u32 r;
    asm("cvt.rn.bf16x2.f32 %0, %1, %2;" : "=r"(r) : "f"(e1), "f"(e0));
    return r;
}
__device__ __forceinline__ float bf_lo_f(u32 p) { return __uint_as_float(p << 16); }
__device__ __forceinline__ float bf_hi_f(u32 p) { return __uint_as_float(p & 0xffff0000u); }
// silu via tanh.approx: silu(x) = 0.5*x*(1 + tanh(0.5*x)) — 1 MUFU op
__device__ __forceinline__ float silu_f(float v) {
    float t;
    asm("tanh.approx.f32 %0, %1;" : "=f"(t) : "f"(v * 0.5f));
    return 0.5f * v + 0.5f * v * t;
}
// de-phase-lock the two co-resident blocks (half-phase offset)
__device__ __forceinline__ void skew_delay(int bid) {
    if (bid >= 148 && bid < 296) {
        long long t0 = clock64();
        while (clock64() - t0 < 8192) {}
    }
}

__device__ __forceinline__ void ldsm4(u32& r0, u32& r1, u32& r2, u32& r3, u32 addr) {
    asm volatile("ldmatrix.sync.aligned.m8n8.x4.shared.b16 {%0,%1,%2,%3}, [%4];"
                 : "=r"(r0), "=r"(r1), "=r"(r2), "=r"(r3) : "r"(addr));
}
__device__ __forceinline__ void mma16816(float* c, const u32* a, u32 b0, u32 b1) {
    asm volatile(
        "mma.sync.aligned.m16n8k16.row.col.f32.bf16.bf16.f32 "
        "{%0,%1,%2,%3}, {%4,%5,%6,%7}, {%8,%9}, {%0,%1,%2,%3};"
        : "+f"(c[0]), "+f"(c[1]), "+f"(c[2]), "+f"(c[3])
        : "r"(a[0]), "r"(a[1]), "r"(a[2]), "r"(a[3]), "r"(b0), "r"(b1));
}
__device__ __forceinline__ void split4(float v0, float v1, float v2, float v3,
                                       u64& hi, u64& lo) {
    u32 h0 = pack_bf16x2(v0, v1), h1 = pack_bf16x2(v2, v3);
    u32 l0 = pack_bf16x2(v0 - bf_lo_f(h0), v1 - bf_hi_f(h0));
    u32 l1 = pack_bf16x2(v2 - bf_lo_f(h1), v3 - bf_hi_f(h1));
    hi = (u64)h0 | ((u64)h1 << 32);
    lo = (u64)l0 | ((u64)l1 << 32);
}
__device__ __forceinline__ void red2(float* p, float a, float b) {
    asm volatile("red.global.add.v2.f32 [%0], {%1,%2};"
                 :: "l"(p), "f"(a), "f"(b) : "memory");
}

// ---- register gather prefetch (8 float4 per thread) ----
__device__ __forceinline__ void issue_gather(float4* pre, const float4* src,
                                             long long g, int qb) {
#pragma unroll
    for (int i = 0; i < 8; ++i)
        pre[i] = __ldg(src + g * 32 + qb + i);
}
__device__ __forceinline__ void issue_gather_guard(float4* pre, const float4* src,
                                                   int g, int qb) {
#pragma unroll
    for (int i = 0; i < 8; ++i) {
        float4 v = make_float4(0.f, 0.f, 0.f, 0.f);
        if (g < NN) v = __ldg(src + (size_t)g * 32 + qb + i);
        pre[i] = v;
    }
}
__device__ __forceinline__ void convert_gather(char* sm, const float4* pre,
                                               int row, int qb) {
#pragma unroll
    for (int i = 0; i < 8; ++i) {
        u64 hi, lo;
        split4(pre[i].x, pre[i].y, pre[i].z, pre[i].w, hi, lo);
        *(u64*)(sm + SM_AHI + row * ROWB + (qb + i) * 8) = hi;
        *(u64*)(sm + SM_ALO + row * ROWB + (qb + i) * 8) = lo;
    }
}

// ---- cp.async ----
__device__ __forceinline__ void cp16(u32 dst, const void* src) {
    asm volatile("cp.async.cg.shared.global [%0], [%1], 16;" :: "r"(dst), "l"(src));
}
#define CP_COMMIT() asm volatile("cp.async.commit_group;" ::: "memory")
#define CP_WAIT(n)  asm volatile("cp.async.wait_group %0;" :: "n"(n) : "memory")

// One K-half = 36864 B = 2304 x 16B = 9 iters x 256 threads exactly.
__device__ __forceinline__ void fill_half(u32 dst, const unsigned char* w, int tid) {
#pragma unroll
    for (int i = 0; i < 9; ++i) {
        int t = tid + i * NTHREADS;
        cp16(dst + t * 16, w + t * 16);
    }
}

// ---------------------------------------------------------------------------
// One K-half step: all 3 split terms (hh, lh, hl) for k-range of this half.
// A-hi/A-lo loaded once per ks; B register block reused hi->lo.
// Warp tile 16x64. acc[8][4].
// ---------------------------------------------------------------------------
__device__ __forceinline__ void mma_khalf(u32 smb, u32 bbuf, float acc[8][4],
                                          int mbase, int nbase, int lane, u32 khb) {
    const u32 a_off = (u32)(mbase + (lane & 15)) * ROWB + (u32)(lane >> 4) * 16 + khb;
    const u32 b_off = (u32)(nbase + (lane & 7) + ((lane >> 4) & 1) * 8) * BROWB
                    + (u32)((lane >> 3) & 1) * 16;
#pragma unroll
    for (int ks = 0; ks < 4; ++ks) {
        const u32 kb = (u32)ks * 32;
        u32 ah[4], al[4], b[4][4];
        ldsm4(ah[0], ah[1], ah[2], ah[3], smb + SM_AHI + a_off + kb);
        ldsm4(al[0], al[1], al[2], al[3], smb + SM_ALO + a_off + kb);
#pragma unroll
        for (int g = 0; g < 4; ++g)
            ldsm4(b[g][0], b[g][1], b[g][2], b[g][3],
                  bbuf + b_off + (u32)g * (16 * BROWB) + kb);
        // hh
#pragma unroll
        for (int ng = 0; ng < 8; ++ng)
            mma16816(acc[ng], ah, b[ng >> 1][(ng & 1) * 2], b[ng >> 1][(ng & 1) * 2 + 1]);
        // lh
#pragma unroll
        for (int ng = 0; ng < 8; ++ng)
            mma16816(acc[ng], al, b[ng >> 1][(ng & 1) * 2], b[ng >> 1][(ng & 1) * 2 + 1]);
        // hl: reload B regs from lo sub-tile
#pragma unroll
        for (int g = 0; g < 4; ++g)
            ldsm4(b[g][0], b[g][1], b[g][2], b[g][3],
                  bbuf + HSUB + b_off + (u32)g * (16 * BROWB) + kb);
#pragma unroll
        for (int ng = 0; ng < 8; ++ng)
            mma16816(acc[ng], ah, b[ng >> 1][(ng & 1) * 2], b[ng >> 1][(ng & 1) * 2 + 1]);
    }
}

// bias + SiLU from acc -> A smem (hi/lo), zero acc
__device__ __forceinline__ void mid_epi(char* sm, float acc[8][4],
                                        const float* __restrict__ bias,
                                        int mbase, int nbase, int lane) {
    const int q = lane & 3, r = lane >> 2;
#pragma unroll
    for (int ng = 0; ng < 8; ++ng) {
        const int col = nbase + ng * 8 + q * 2;
        const float bx = __ldg(bias + col), by = __ldg(bias + col + 1);
        const int r0 = mbase + r, r1 = r0 + 8;
        float v0 = silu_f(acc[ng][0] + bx);
        float v1 = silu_f(acc[ng][1] + by);
        float v2 = silu_f(acc[ng][2] + bx);
        float v3 = silu_f(acc[ng][3] + by);
        u32 h0 = pack_bf16x2(v0, v1);
        u32 l0 = pack_bf16x2(v0 - bf_lo_f(h0), v1 - bf_hi_f(h0));
        u32 h1 = pack_bf16x2(v2, v3);
        u32 l1 = pack_bf16x2(v2 - bf_lo_f(h1), v3 - bf_hi_f(h1));
        *(u32*)(sm + SM_AHI + r0 * ROWB + col * 2) = h0;
        *(u32*)(sm + SM_ALO + r0 * ROWB + col * 2) = l0;
        *(u32*)(sm + SM_AHI + r1 * ROWB + col * 2) = h1;
        *(u32*)(sm + SM_ALO + r1 * ROWB + col * 2) = l1;
        acc[ng][0] = 0.f; acc[ng][1] = 0.f;
        acc[ng][2] = 0.f; acc[ng][3] = 0.f;
    }
}

// In-register LN: bias + per-row stats via 4-lane butterfly + cross-warp
// exchange in SM_BB0 (free after last MMA which reads SM_BB1).
__device__ __forceinline__ void ln_reg(char* sm, float acc[8][4],
                                       const float* __restrict__ b3,
                                       int nbase, int q, int r0, int r1,
                                       float& m0, float& rs0, float& m1, float& rs1) {
    float s1a = 0.f, s2a = 0.f, s1b = 0.f, s2b = 0.f;
#pragma unroll
    for (int ng = 0; ng < 8; ++ng) {
        const int col = nbase + ng * 8 + q * 2;
        const float bx = __ldg(b3 + col), by = __ldg(b3 + col + 1);
        float v0 = acc[ng][0] + bx, v1 = acc[ng][1] + by;
        float v2 = acc[ng][2] + bx, v3 = acc[ng][3] + by;
        acc[ng][0] = v0; acc[ng][1] = v1; acc[ng][2] = v2; acc[ng][3] = v3;
        s1a += v0 + v1; s2a += v0 * v0 + v1 * v1;
        s1b += v2 + v3; s2b += v2 * v2 + v3 * v3;
    }
#pragma unroll
    for (int m = 1; m <= 2; m <<= 1) {
        s1a += __shfl_xor_sync(0xffffffffu, s1a, m, 32);
        s2a += __shfl_xor_sync(0xffffffffu, s2a, m, 32);
        s1b += __shfl_xor_sync(0xffffffffu, s1b, m, 32);
        s2b += __shfl_xor_sync(0xffffffffu, s2b, m, 32);
    }
    float2* ex = (float2*)(sm + SM_BB0);   // [64 rows][2 halves]
    const int half = nbase >> 6;
    if (q == 0) {
        ex[r0 * 2 + half] = make_float2(s1a, s2a);
        ex[r1 * 2 + half] = make_float2(s1b, s2b);
    }
    __syncthreads();
    float2 a0 = ex[r0 * 2], a1 = ex[r0 * 2 + 1];
    float2 b0 = ex[r1 * 2], b1 = ex[r1 * 2 + 1];
    m0 = (a0.x + a1.x) * (1.0f / 128.0f);
    float v0 = (a0.y + a1.y) * (1.0f / 128.0f) - m0 * m0;
    rs0 = rsqrtf(v0 + 1e-5f);
    m1 = (b0.x + b1.x) * (1.0f / 128.0f);
    float v1 = (b0.y + b1.y) * (1.0f / 128.0f) - m1 * m1;
    rs1 = rsqrtf(v1 + 1e-5f);
}

// ---------------------------------------------------------------------------
// PQ precompute: P = x@W1a, Q = x@W1b (64 rows/block, 256 threads)
// ---------------------------------------------------------------------------
__device__ __forceinline__ void store_pq(float* dst, float acc[8][4],
                                         int n0, int mbase, int nbase, int lane) {
    const int q = lane & 3, r = lane >> 2;
#pragma unroll
    for (int ng = 0; ng < 8; ++ng) {
        const int col = nbase + ng * 8 + q * 2;
        const int r0 = mbase + r, r1 = r0 + 8;
        if (n0 + r0 < NN)
            *(float2*)(dst + (size_t)(n0 + r0) * 128 + col) = make_float2(acc[ng][0], acc[ng][1]);
        if (n0 + r1 < NN)
            *(float2*)(dst + (size_t)(n0 + r1) * 128 + col) = make_float2(acc[ng][2], acc[ng][3]);
        acc[ng][0] = 0.f; acc[ng][1] = 0.f;
        acc[ng][2] = 0.f; acc[ng][3] = 0.f;
    }
}

__global__ __launch_bounds__(NTHREADS, 2)
void pq_kernel(const float* __restrict__ x) {
    extern __shared__ char sm[];
    const u32 smb = smem_u32(sm);
    const int tid = threadIdx.x, wid = tid >> 5, lane = tid & 31;
    const int mbase = (wid >> 1) * 16, nbase = (wid & 1) * 64;
    const int n0 = blockIdx.x * MROWS;
    const int grow = tid >> 2, gqb = (tid & 3) * 8;

    float acc[8][4];
#pragma unroll
    for (int ng = 0; ng < 8; ++ng)
#pragma unroll
        for (int k = 0; k < 4; ++k) acc[ng][k] = 0.f;

    fill_half(smb + SM_BB0, g_we, tid);        CP_COMMIT();
    fill_half(smb + SM_BB1, g_we + HBK, tid);  CP_COMMIT();

    float4 pre[8];
    issue_gather_guard(pre, (const float4*)x, n0 + grow, gqb);
    convert_gather(sm, pre, grow, gqb);

    // 2 chunks (W1a, W1b) = 4 K-half steps; same A both chunks
#pragma unroll 1
    for (int t = 0; t < 4; ++t) {
        const u32 bbuf = smb + SM_BB0 + (u32)(t & 1) * HBK;
        if (t < 3) { CP_WAIT(1); } else { CP_WAIT(0); }
        __syncthreads();
        mma_khalf(smb, bbuf, acc, mbase, nbase, lane, (u32)(t & 1) * 128);
        if (t < 3) {
            __syncthreads();
            if (t + 2 < 4) {
                fill_half(bbuf, g_we + (size_t)((t + 2) >> 1) * WCH2
                                     + (size_t)((t + 2) & 1) * HBK, tid);
                CP_COMMIT();
            }
            if (t == 1) store_pq(g_P, acc, n0, mbase, nbase, lane);
        }
    }
    store_pq(g_Q, acc, n0, mbase, nbase, lane);
}

// ---------------------------------------------------------------------------
// Edge kernel: 64 edges/block, 256 threads, 3 MMA chunks (W1c, W2, W3).
// ---------------------------------------------------------------------------
__global__ __launch_bounds__(NTHREADS, 2)
void edge_kernel(const int* __restrict__ eidx,
                 const float* __restrict__ ea,
                 const float* __restrict__ b1, const float* __restrict__ b2,
                 const float* __restrict__ b3,
                 const float* __restrict__ gw, const float* __restrict__ bw,
                 float* __restrict__ out_e) {
    extern __shared__ char sm[];
    const u32 smb = smem_u32(sm);
    const int tid = threadIdx.x, wid = tid >> 5, lane = tid & 31;
    const int mbase = (wid >> 1) * 16, nbase = (wid & 1) * 64;
    const int e0 = blockIdx.x * MROWS;
    const int grow = tid >> 2, gqb = (tid & 3) * 8;
    const int q = lane & 3, r = lane >> 2;
    const int row0 = mbase + r, row1 = row0 + 8;
    const unsigned char* wbase = g_we + 2 * WCH2;  // chunks W1c, W2, W3

    skew_delay(blockIdx.x);

    // acc init = P[i] + Q[j] at fragment positions — issued first.
    float acc[8][4];
    {
        const size_t i0 = (size_t)__ldg(eidx + e0 + row0) * 128;
        const size_t i1 = (size_t)__ldg(eidx + e0 + row1) * 128;
        const size_t j0 = (size_t)__ldg(eidx + NE + e0 + row0) * 128;
        const size_t j1 = (size_t)__ldg(eidx + NE + e0 + row1) * 128;
#pragma unroll
        for (int ng = 0; ng < 8; ++ng) {
            const int col = nbase + ng * 8 + q * 2;
            float2 p0 = __ldg((const float2*)(g_P + i0 + col));
            float2 q0 = __ldg((const float2*)(g_Q + j0 + col));
            float2 p1 = __ldg((const float2*)(g_P + i1 + col));
            float2 q1 = __ldg((const float2*)(g_Q + j1 + col));
            acc[ng][0] = p0.x + q0.x;
            acc[ng][1] = p0.y + q0.y;
            acc[ng][2] = p1.x + q1.x;
            acc[ng][3] = p1.y + q1.y;
        }
    }

    fill_half(smb + SM_BB0, wbase, tid);        CP_COMMIT();
    fill_half(smb + SM_BB1, wbase + HBK, tid);  CP_COMMIT();

    float4 preA[8];
    issue_gather(preA, (const float4*)ea, (long long)(e0 + grow), gqb);
    convert_gather(sm, preA, grow, gqb);

    // 3 chunks = 6 K-half steps; final step skips post-MMA barrier
#pragma unroll 1
    for (int t = 0; t < 6; ++t) {
        const u32 bbuf = smb + SM_BB0 + (u32)(t & 1) * HBK;
        if (t < 5) { CP_WAIT(1); } else { CP_WAIT(0); }
        __syncthreads();
        mma_khalf(smb, bbuf, acc, mbase, nbase, lane, (u32)(t & 1) * 128);
        if (t < 5) {
            __syncthreads();
            if (t + 2 < 6) {
                fill_half(bbuf, wbase + (size_t)((t + 2) >> 1) * WCH2
                                      + (size_t)((t + 2) & 1) * HBK, tid);
                CP_COMMIT();
            }
            if (t == 1)      mid_epi(sm, acc, b1, mbase, nbase, lane);
            else if (t == 3) mid_epi(sm, acc, b2, mbase, nbase, lane);
        }
    }

    // scatter indices issued before LN to hide latency under exchange barrier
    const long long gr0 = e0 + row0, gr1 = e0 + row1;
    const int dj0 = __ldg(eidx + NE + gr0);
    const int dj1 = __ldg(eidx + NE + gr1);

    float m0, rs0, m1, rs1;
    ln_reg(sm, acc, b3, nbase, q, row0, row1, m0, rs0, m1, rs1);

    {
        float* ap0 = g_agg + (size_t)dj0 * 128;
        float* ap1 = g_agg + (size_t)dj1 * 128;
#pragma unroll
        for (int ng = 0; ng < 8; ++ng) {
            const int col = nbase + ng * 8 + q * 2;
            float2 gv = *(const float2*)(gw + col);
            float2 bv = *(const float2*)(bw + col);
            float2 ra0 = __ldg((const float2*)(ea + gr0 * 128 + col));
            float2 ra1 = __ldg((const float2*)(ea + gr1 * 128 + col));
            float o0 = (acc[ng][0] - m0) * rs0 * gv.x + bv.x + ra0.x;
            float o1 = (acc[ng][1] - m0) * rs0 * gv.y + bv.y + ra0.y;
            float o2 = (acc[ng][2] - m1) * rs1 * gv.x + bv.x + ra1.x;
            float o3 = (acc[ng][3] - m1) * rs1 * gv.y + bv.y + ra1.y;
            __stcs((float2*)(out_e + gr0 * 128 + col), make_float2(o0, o1));
            __stcs((float2*)(out_e + gr1 * 128 + col), make_float2(o2, o3));
            red2(ap0 + col, o0, o1);
            red2(ap1 + col, o2, o3);
        }
    }
}

// ---------------------------------------------------------------------------
// Node kernel: 64 nodes/block, 256 threads, 2 blocks/SM
// ---------------------------------------------------------------------------
__global__ __launch_bounds__(NTHREADS, 2)
void node_kernel(const float* __restrict__ x,
                 const float* __restrict__ b1, const float* __restrict__ b2,
                 const float* __restrict__ b3,
                 const float* __restrict__ gw, const float* __restrict__ bw,
                 float* __restrict__ out_x) {
    extern __shared__ char sm[];
    const u32 smb = smem_u32(sm);
    const int tid = threadIdx.x, wid = tid >> 5, lane = tid & 31;
    const int mbase = (wid >> 1) * 16, nbase = (wid & 1) * 64;
    const int n0 = blockIdx.x * MROWS;
    const int grow = tid >> 2, gqb = (tid & 3) * 8;
    const int q = lane & 3, r = lane >> 2;
    const int row0 = mbase + r, row1 = row0 + 8;

    skew_delay(blockIdx.x);

    float acc[8][4];
#pragma unroll
    for (int ng = 0; ng < 8; ++ng)
#pragma unroll
        for (int k = 0; k < 4; ++k) acc[ng][k] = 0.f;

    fill_half(smb + SM_BB0, g_wn, tid);        CP_COMMIT();
    fill_half(smb + SM_BB1, g_wn + HBK, tid);  CP_COMMIT();

    float4 pre[8];
    issue_gather_guard(pre, (const float4*)x, n0 + grow, gqb);
    convert_gather(sm, pre, grow, gqb);
    issue_gather_guard(pre, (const float4*)g_agg, n0 + grow, gqb);

    // 4 chunks = 8 K-half steps; final step skips post-MMA barrier
#pragma unroll 1
    for (int t = 0; t < 8; ++t) {
        const u32 bbuf = smb + SM_BB0 + (u32)(t & 1) * HBK;
        if (t < 7) { CP_WAIT(1); } else { CP_WAIT(0); }
        __syncthreads();
        mma_khalf(smb, bbuf, acc, mbase, nbase, lane, (u32)(t & 1) * 128);
        if (t < 7) {
            __syncthreads();
            if (t + 2 < 8) {
                fill_half(bbuf, g_wn + (size_t)((t + 2) >> 1) * WCH2
                                     + (size_t)((t + 2) & 1) * HBK, tid);
                CP_COMMIT();
            }
            if (t & 1) {
                const int s = t >> 1;
                if (s == 0) {
                    convert_gather(sm, pre, grow, gqb);
                } else if (s == 1) {
                    mid_epi(sm, acc, b1, mbase, nbase, lane);
                } else if (s == 2) {
                    mid_epi(sm, acc, b2, mbase, nbase, lane);
                }
            }
        }
    }

    float m0, rs0, m1, rs1;
    ln_reg(sm, acc, b3, nbase, q, row0, row1, m0, rs0, m1, rs1);

    {
        const long long gr0 = n0 + row0, gr1 = n0 + row1;
        const bool ok0 = gr0 < NN, ok1 = gr1 < NN;
#pragma unroll
        for (int ng = 0; ng < 8; ++ng) {
            const int col = nbase + ng * 8 + q * 2;
            float2 gv = *(const float2*)(gw + col);
            float2 bv = *(const float2*)(bw + col);
            if (ok0) {
                float2 ra = __ldg((const float2*)(x + gr0 * 128 + col));
                float o0 = (acc[ng][0] - m0) * rs0 * gv.x + bv.x + ra.x;
                float o1 = (acc[ng][1] - m0) * rs0 * gv.y + bv.y + ra.y;
                __stcs((float2*)(out_x + gr0 * 128 + col), make_float2(o0, o1));
            }
            if (ok1) {
                float2 ra = __ldg((const float2*)(x + gr1 * 128 + col));
                float o2 = (acc[ng][2] - m1) * rs1 * gv.x + bv.x + ra.x;
                float o3 = (acc[ng][3] - m1) * rs1 * gv.y + bv.y + ra.y;
                __stcs((float2*)(out_x + gr1 * 128 + col), make_float2(o2, o3));
            }
        }
    }
}

// ---------------------------------------------------------------------------
// Weight prep (split bf16 hi/lo, [n][k] K-halves, stride 144B) + g_agg zero.
// ---------------------------------------------------------------------------
#define PREP_N (9 * 16384)
#define ZERO_N (NN * 32)

__global__ void prep_zero(const float* __restrict__ ew1, const float* __restrict__ ew2,
                          const float* __restrict__ ew3, const float* __restrict__ nw1,
                          const float* __restrict__ nw2, const float* __restrict__ nw3) {
    int i = blockIdx.x * blockDim.x + threadIdx.x;
    if (i < PREP_N) {
        unsigned char* dst;
        float val;
        int cs = i >> 14, rr = i & 16383;
        int kl = rr >> 7, n = rr & 127;
        if (cs < 5) {
            if (cs < 3)       val = ew1[(cs * 128 + kl) * 128 + n];
            else if (cs == 3) val = ew2[kl * 128 + n];
            else              val = ew3[kl * 128 + n];
            dst = g_we + (size_t)cs * WCH2;
        } else {
            int ns = cs - 5;
            if (ns < 2)       val = nw1[(ns * 128 + kl) * 128 + n];
            else if (ns == 2) val = nw2[kl * 128 + n];
            else              val = nw3[kl * 128 + n];
            dst = g_wn + (size_t)ns * WCH2;
        }
        const int half = kl >> 6, klh = kl & 63;
        u32 h = pack_bf16x2(val, 0.f);
        u32 l = pack_bf16x2(val - bf_lo_f(h), 0.f);
        unsigned char* hbase = dst + (size_t)half * HBK + n * BROWB + klh * 2;
        *(unsigned short*)(hbase)        = (unsigned short)(h & 0xffff);
        *(unsigned short*)(hbase + HSUB) = (unsigned short)(l & 0xffff);
    } else {
        int z = i - PREP_N;
        if (z < ZERO_N)
            ((float4*)g_agg)[z] = make_float4(0.f, 0.f, 0.f, 0.f);
    }
}

// ---------------------------------------------------------------------------
extern "C" void kernel_launch(void* const* d_in, const int* in_sizes, int n_in,
                              void* d_out, int out_size) {
    const float* x    = (const float*)d_in[0];
    const int*   eidx = (const int*)d_in[1];
    const float* ea   = (const float*)d_in[2];
    const float* ew1  = (const float*)d_in[3];
    const float* eb1  = (const float*)d_in[4];
    const float* ew2  = (const float*)d_in[5];
    const float* eb2  = (const float*)d_in[6];
    const float* ew3  = (const float*)d_in[7];
    const float* eb3  = (const float*)d_in[8];
    const float* eg   = (const float*)d_in[9];
    const float* ebt  = (const float*)d_in[10];
    const float* nw1  = (const float*)d_in[11];
    const float* nb1  = (const float*)d_in[12];
    const float* nw2  = (const float*)d_in[13];
    const float* nb2  = (const float*)d_in[14];
    const float* nw3  = (const float*)d_in[15];
    const float* nb3  = (const float*)d_in[16];
    const float* ng   = (const float*)d_in[17];
    const float* nbt  = (const float*)d_in[18];

    float* out_x = (float*)d_out;                       // [50000, 128]
    float* out_e = (float*)d_out + (size_t)NN * 128;    // [800000, 128]

    cudaFuncSetAttribute(pq_kernel,   cudaFuncAttributeMaxDynamicSharedMemorySize, SM_BYTES);
    cudaFuncSetAttribute(edge_kernel, cudaFuncAttributeMaxDynamicSharedMemorySize, SM_BYTES);
    cudaFuncSetAttribute(node_kernel, cudaFuncAttributeMaxDynamicSharedMemorySize, SM_BYTES);

    prep_zero<<<(PREP_N + ZERO_N + 255) / 256, 256>>>(ew1, ew2, ew3, nw1, nw2, nw3);
    pq_kernel<<<(NN + MROWS - 1) / MROWS, NTHREADS, SM_BYTES>>>(x);
    edge_kernel<<<NE / MROWS, NTHREADS, SM_BYTES>>>(eidx, ea, eb1, eb2, eb3, eg, ebt, out_e);
    node_kernel<<<(NN + MROWS - 1) / MROWS, NTHREADS, SM_BYTES>>>(x, nb1, nb2, nb3, ng, nbt, out_x);
}